// round 10
// baseline (speedup 1.0000x reference)
#include <cuda_runtime.h>
#include <cuda_bf16.h>
#include <math.h>
#include <stdint.h>

// ---------------------------------------------------------------------------
// PCTransformer block, GB300 (sm_103a, compute_103 baseline PTX)
// B=16, N=1024, C=384, H=6, HD=64, K=8, HID=768, M=B*N=16384
// Dense GEMMs: merged-K bf16 HMMA; 2-term split for all residual-accuracy
// GEMMs (kNN/proj/merge/fc1/fc2); plain bf16 only for qkv (output is
// bf16-rounded anyway). Attention: HMMA flash. kNN branch on side stream.
// ---------------------------------------------------------------------------

#define MROWS 16384

// ---------------- scratch (static device globals; no allocation) -----------
__device__ float g_AbCc[MROWS * 768];    // [Ab | Cc] for kNN branch
__device__ float g_xres[MROWS * 384];

// per-(b,h) contiguous bf16 Q/K/V  [96][1024][64]
__device__ __align__(16) __nv_bfloat16 g_qb[96*1024*64];
__device__ __align__(16) __nv_bfloat16 g_kb[96*1024*64];
__device__ __align__(16) __nv_bfloat16 g_vb[96*1024*64];

// bf16 split activations
__device__ __align__(16) __nv_bfloat16 g_nxh[MROWS*384],  g_nxl[MROWS*384];
__device__ __align__(16) __nv_bfloat16 g_aoh[MROWS*384],  g_aol[MROWS*384];
__device__ __align__(16) __nv_bfloat16 g_cath[MROWS*768], g_catl[MROWS*768];
__device__ __align__(16) __nv_bfloat16 g_l2h[MROWS*384],  g_l2l[MROWS*384];
__device__ __align__(16) __nv_bfloat16 g_hh[MROWS*768],   g_hl[MROWS*768];

// bf16 split transposed weights
__device__ __align__(16) __nv_bfloat16 g_wqkvh[1152*384], g_wqkvl[1152*384];
__device__ __align__(16) __nv_bfloat16 g_wprojh[384*384], g_wprojl[384*384];
__device__ __align__(16) __nv_bfloat16 g_wkh[768*384],    g_wkl[768*384];   // [W1 | W2-W1]
__device__ __align__(16) __nv_bfloat16 g_wmh[384*768],    g_wml[384*768];
__device__ __align__(16) __nv_bfloat16 g_f1h[768*384],    g_f1l[768*384];
__device__ __align__(16) __nv_bfloat16 g_f2h[384*768],    g_f2l[384*768];

// ---------------- PTX helpers ----------------------------------------------
__device__ __forceinline__ uint32_t smem_u32(const void* p) {
    uint32_t a;
    asm("{ .reg .u64 t; cvta.to.shared.u64 t, %1; cvt.u32.u64 %0, t; }"
        : "=r"(a) : "l"(p));
    return a;
}
__device__ __forceinline__ void ldsm_x4(uint32_t addr, uint32_t* r) {
    asm volatile("ldmatrix.sync.aligned.m8n8.x4.shared.b16 {%0,%1,%2,%3}, [%4];"
                 : "=r"(r[0]), "=r"(r[1]), "=r"(r[2]), "=r"(r[3]) : "r"(addr));
}
__device__ __forceinline__ void ldsm_x4t(uint32_t addr, uint32_t* r) {
    asm volatile("ldmatrix.sync.aligned.m8n8.x4.trans.shared.b16 {%0,%1,%2,%3}, [%4];"
                 : "=r"(r[0]), "=r"(r[1]), "=r"(r[2]), "=r"(r[3]) : "r"(addr));
}
__device__ __forceinline__ void mma_bf16(float* c, const uint32_t* a,
                                         uint32_t b0, uint32_t b1) {
    asm volatile(
        "mma.sync.aligned.m16n8k16.row.col.f32.bf16.bf16.f32 "
        "{%0,%1,%2,%3},{%4,%5,%6,%7},{%8,%9},{%0,%1,%2,%3};"
        : "+f"(c[0]), "+f"(c[1]), "+f"(c[2]), "+f"(c[3])
        : "r"(a[0]), "r"(a[1]), "r"(a[2]), "r"(a[3]), "r"(b0), "r"(b1));
}
__device__ __forceinline__ void cp16(uint32_t dst, const void* src) {
    asm volatile("cp.async.cg.shared.global [%0], [%1], 16;"
                 :: "r"(dst), "l"(src) : "memory");
}
#define CP_COMMIT() asm volatile("cp.async.commit_group;" ::: "memory")
#define CP_WAIT(n)  asm volatile("cp.async.wait_group %0;" :: "n"(n) : "memory")

__device__ __forceinline__ uint32_t bf2pk(float lo, float hi) {
    uint32_t r;
    asm("cvt.rn.bf16x2.f32 %0, %1, %2;" : "=r"(r) : "f"(hi), "f"(lo));
    return r;
}

__device__ __forceinline__ void split_store(__nv_bfloat16* H, __nv_bfloat16* L,
                                            size_t idx, float x, float y) {
    __nv_bfloat16 hx = __float2bfloat16_rn(x);
    __nv_bfloat16 hy = __float2bfloat16_rn(y);
    *(__nv_bfloat162*)&H[idx] = __nv_bfloat162(hx, hy);
    *(__nv_bfloat162*)&L[idx] =
        __nv_bfloat162(__float2bfloat16_rn(x - __bfloat162float(hx)),
                       __float2bfloat16_rn(y - __bfloat162float(hy)));
}

// qkv GEMM epilogue: write directly into per-(b,h) bf16 Q(scaled)/K/V
__device__ __forceinline__ void qkv_store(__nv_bfloat16* qp, __nv_bfloat16* kp,
                                          __nv_bfloat16* vp, int token, int col,
                                          float x, float y) {
    int bb = token >> 10, n = token & 1023;
    int which = col / 384;
    int rem = col - which * 384;
    int h = rem >> 6, d = rem & 63;
    size_t di = ((size_t)(bb * 6 + h) * 1024 + n) * 64 + d;
    float sc = (which == 0) ? 0.125f : 1.0f;
    __nv_bfloat16* dst = (which == 0) ? qp : ((which == 1) ? kp : vp);
    *(__nv_bfloat162*)&dst[di] =
        __nv_bfloat162(__float2bfloat16_rn(x * sc), __float2bfloat16_rn(y * sc));
}

// ---------------- LayerNorm (writes bf16 split) ----------------------------
__global__ void ln_kernel(const float* __restrict__ x,
                          const float* __restrict__ w,
                          const float* __restrict__ b,
                          __nv_bfloat16* __restrict__ H,
                          __nv_bfloat16* __restrict__ L) {
    int row = blockIdx.x, tid = threadIdx.x;
    const float* xr = x + (size_t)row * 384;
    float v0 = xr[tid], v1 = xr[tid + 128], v2 = xr[tid + 256];
    float s  = v0 + v1 + v2;
    float sq = v0 * v0 + v1 * v1 + v2 * v2;
    #pragma unroll
    for (int o = 16; o; o >>= 1) {
        s  += __shfl_xor_sync(0xffffffffu, s,  o);
        sq += __shfl_xor_sync(0xffffffffu, sq, o);
    }
    __shared__ float ss[4], sqs[4];
    int wid = tid >> 5, lid = tid & 31;
    if (lid == 0) { ss[wid] = s; sqs[wid] = sq; }
    __syncthreads();
    s  = ss[0] + ss[1] + ss[2] + ss[3];
    sq = sqs[0] + sqs[1] + sqs[2] + sqs[3];
    float mean = s * (1.0f / 384.0f);
    float var  = sq * (1.0f / 384.0f) - mean * mean;
    float inv  = rsqrtf(var + 1e-5f);
    size_t base = (size_t)row * 384;
    #pragma unroll
    for (int cc = 0; cc < 3; cc++) {
        int c = tid + cc * 128;
        float v = (cc == 0 ? v0 : (cc == 1 ? v1 : v2));
        float y = (v - mean) * inv * w[c] + b[c];
        __nv_bfloat16 h = __float2bfloat16_rn(y);
        H[base + c] = h;
        L[base + c] = __float2bfloat16_rn(y - __bfloat162float(h));
    }
}

__device__ __forceinline__ float gelu_exact(float v) {
    return 0.5f * v * (1.0f + erff(v * 0.70710678118654752f));
}

// ---------------- weight transpose+split -----------------------------------
__global__ void tsplit(const float* __restrict__ W,
                       __nv_bfloat16* __restrict__ Th,
                       __nv_bfloat16* __restrict__ Tl, int K, int N) {
    int idx = blockIdx.x * 256 + threadIdx.x;
    if (idx >= K * N) return;
    int n = idx / K, k = idx - n * K;
    float v = W[(size_t)k * N + n];
    __nv_bfloat16 h = __float2bfloat16_rn(v);
    Th[idx] = h;
    Tl[idx] = __float2bfloat16_rn(v - __bfloat162float(h));
}

// combined kNN weights: rows 0..383 = W1^T, rows 384..767 = (W2-W1)^T
__global__ void tsplit_knn2(const float* __restrict__ W,
                            __nv_bfloat16* __restrict__ Th,
                            __nv_bfloat16* __restrict__ Tl) {
    int idx = blockIdx.x * 256 + threadIdx.x;
    if (idx >= 768 * 384) return;
    int np = idx / 384, k = idx - np * 384;
    float v;
    if (np < 384) {
        v = W[(size_t)k * 384 + np];
    } else {
        int n = np - 384;
        v = W[(size_t)(384 + k) * 384 + n] - W[(size_t)k * 384 + n];
    }
    __nv_bfloat16 h = __float2bfloat16_rn(v);
    Th[idx] = h;
    Tl[idx] = __float2bfloat16_rn(v - __bfloat162float(h));
}

// ---------------- HMMA GEMM, merged split loop -----------------------------
// SPLITIN=1: tiles Ah,Al,Bh,Bl resident per K-chunk; acc += AhBh+AhBl+AlBh.
// SPLITIN=0: tiles Ah,Bh only; acc += AhBh (plain bf16).
// 128x128 CTA tile, 256 threads, warp tile 64x32, 2-stage cp.async.
// OMODE: 0 = fp32 C, 1 = split bf16 Ho/Lo, 2 = qkv direct (qp/kp/vp)
#define ROWB    80
#define TILE_B  (128 * ROWB)     // 10240
#define SMEM_MM4 (2 * 4 * TILE_B)   // 81920 (split)
#define SMEM_MM2 (2 * 2 * TILE_B)   // 40960 (nosplit)

template <int GELU, int OMODE, int SPLITIN>
__global__ void __launch_bounds__(256, 2) tgemm(
    const __nv_bfloat16* __restrict__ Ah, const __nv_bfloat16* __restrict__ Al,
    const __nv_bfloat16* __restrict__ Bh, const __nv_bfloat16* __restrict__ Bl,
    const float* __restrict__ bias, const float* __restrict__ res,
    float* __restrict__ C, __nv_bfloat16* __restrict__ Ho,
    __nv_bfloat16* __restrict__ Lo,
    __nv_bfloat16* __restrict__ qp, __nv_bfloat16* __restrict__ kp,
    __nv_bfloat16* __restrict__ vp,
    int K, int ldc, int ldres) {
    extern __shared__ char smem[];
    uint32_t sb = smem_u32(smem);
    int tid = threadIdx.x, lid = tid & 31, w = tid >> 5;
    int wm = w & 1, wn = w >> 1;
    int m0 = blockIdx.y * 128, n0 = blockIdx.x * 128;
    const int NIT = K >> 5;
    constexpr int NT = SPLITIN ? 4 : 2;          // tiles per stage
    constexpr uint32_t STG_B = NT * TILE_B;
    constexpr uint32_t BOFF  = (SPLITIN ? 2 : 1) * TILE_B;   // Bh tile offset

    float acc[4][4][4];
    #pragma unroll
    for (int i = 0; i < 4; i++)
        #pragma unroll
        for (int j = 0; j < 4; j++)
            #pragma unroll
            for (int q = 0; q < 4; q++) acc[i][j][q] = 0.0f;

    int c0 = tid * 2;
    int lr0 = c0 >> 2,       lq0 = c0 & 3;
    int lr1 = (c0 + 1) >> 2, lq1 = (c0 + 1) & 3;

    auto load_stage = [&](int kc, int s) {
        size_t aoff = (size_t)m0 * K + kc * 32;
        size_t boff = (size_t)n0 * K + kc * 32;
        uint32_t st = sb + s * STG_B;
        uint32_t d0 = lr0 * ROWB + lq0 * 16, d1 = lr1 * ROWB + lq1 * 16;
        size_t s0a = (size_t)lr0 * K + lq0 * 8, s1a = (size_t)lr1 * K + lq1 * 8;
        cp16(st + d0,          Ah + aoff + s0a);
        cp16(st + d1,          Ah + aoff + s1a);
        cp16(st + BOFF + d0,   Bh + boff + s0a);
        cp16(st + BOFF + d1,   Bh + boff + s1a);
        if (SPLITIN) {
            cp16(st + TILE_B + d0,     Al + aoff + s0a);
            cp16(st + TILE_B + d1,     Al + aoff + s1a);
            cp16(st + 3 * TILE_B + d0, Bl + boff + s0a);
            cp16(st + 3 * TILE_B + d1, Bl + boff + s1a);
        }
    };

    int rA = lid & 15, hA = lid >> 4;
    int rB = (lid & 7) + ((lid >> 4) << 3), hB = (lid >> 3) & 1;

    auto compute_stage = [&](int s) {
        uint32_t sAh = sb + s * STG_B + (wm * 64) * ROWB;
        uint32_t sBh = sb + s * STG_B + BOFF + (wn * 32) * ROWB;
        #pragma unroll
        for (int ks = 0; ks < 2; ks++) {
            int kk = ks * 16;
            uint32_t a[4][4];
            #pragma unroll
            for (int i = 0; i < 4; i++)
                ldsm_x4(sAh + (i * 16 + rA) * ROWB + (kk + hA * 8) * 2, a[i]);
            uint32_t bh[2][4];
            #pragma unroll
            for (int jj = 0; jj < 2; jj++)
                ldsm_x4(sBh + (jj * 16 + rB) * ROWB + (kk + hB * 8) * 2, bh[jj]);
            // Ah * Bh
            #pragma unroll
            for (int i = 0; i < 4; i++)
                #pragma unroll
                for (int j = 0; j < 4; j++)
                    mma_bf16(acc[i][j], a[i], bh[j >> 1][(j & 1) * 2],
                             bh[j >> 1][(j & 1) * 2 + 1]);
            if (SPLITIN) {
                uint32_t sAl = sAh + TILE_B;
                uint32_t sBl = sBh + TILE_B;
                uint32_t bl[2][4];
                #pragma unroll
                for (int jj = 0; jj < 2; jj++)
                    ldsm_x4(sBl + (jj * 16 + rB) * ROWB + (kk + hB * 8) * 2, bl[jj]);
                // Ah * Bl
                #pragma unroll
                for (int i = 0; i < 4; i++)
                    #pragma unroll
                    for (int j = 0; j < 4; j++)
                        mma_bf16(acc[i][j], a[i], bl[j >> 1][(j & 1) * 2],
                                 bl[j >> 1][(j & 1) * 2 + 1]);
                // Al * Bh
                uint32_t al[4][4];
                #pragma unroll
                for (int i = 0; i < 4; i++)
                    ldsm_x4(sAl + (i * 16 + rA) * ROWB + (kk + hA * 8) * 2, al[i]);
                #pragma unroll
                for (int i = 0; i < 4; i++)
                    #pragma unroll
                    for (int j = 0; j < 4; j++)
                        mma_bf16(acc[i][j], al[i], bh[j >> 1][(j & 1) * 2],
                                 bh[j >> 1][(j & 1) * 2 + 1]);
            }
        }
    };

    load_stage(0, 0); CP_COMMIT();
    for (int it = 0; it < NIT; ++it) {
        if (it + 1 < NIT) { load_stage(it + 1, (it + 1) & 1); CP_COMMIT(); }
        if (it + 1 < NIT) CP_WAIT(1); else CP_WAIT(0);
        __syncthreads();
        compute_stage(it & 1);
        __syncthreads();
    }

    #pragma unroll
    for (int i = 0; i < 4; i++) {
        int r0 = m0 + wm * 64 + i * 16 + (lid >> 2);
        int r1 = r0 + 8;
        #pragma unroll
        for (int j = 0; j < 4; j++) {
            int col = n0 + wn * 32 + j * 8 + (lid & 3) * 2;
            float2 v0 = make_float2(acc[i][j][0], acc[i][j][1]);
            float2 v1 = make_float2(acc[i][j][2], acc[i][j][3]);
            if (bias) {
                float2 bb = *(const float2*)&bias[col];
                v0.x += bb.x; v0.y += bb.y; v1.x += bb.x; v1.y += bb.y;
            }
            if (GELU) {
                v0.x = gelu_exact(v0.x); v0.y = gelu_exact(v0.y);
                v1.x = gelu_exact(v1.x); v1.y = gelu_exact(v1.y);
            }
            if (res) {
                float2 q0 = *(const float2*)&res[(size_t)r0 * ldres + col];
                float2 q1 = *(const float2*)&res[(size_t)r1 * ldres + col];
                v0.x += q0.x; v0.y += q0.y; v1.x += q1.x; v1.y += q1.y;
            }
            if (OMODE == 2) {
                qkv_store(qp, kp, vp, r0, col, v0.x, v0.y);
                qkv_store(qp, kp, vp, r1, col, v1.x, v1.y);
            } else if (OMODE == 1) {
                split_store(Ho, Lo, (size_t)r0 * ldc + col, v0.x, v0.y);
                split_store(Ho, Lo, (size_t)r1 * ldc + col, v1.x, v1.y);
            } else {
                *(float2*)&C[(size_t)r0 * ldc + col] = v0;
                *(float2*)&C[(size_t)r1 * ldc + col] = v1;
            }
        }
    }
}

// ---------------- HMMA flash attention -------------------------------------
#define AT_STB  144
#define SQ_OFF  0
#define SK0_OFF (128 * AT_STB)
#define SV0_OFF (SK0_OFF + 64 * AT_STB)
#define SK1_OFF (SV0_OFF + 64 * AT_STB)
#define SV1_OFF (SK1_OFF + 64 * AT_STB)
#define SMEM_AT (SV1_OFF + 64 * AT_STB)

__global__ void __launch_bounds__(128) attn_mma(
    const __nv_bfloat16* __restrict__ qb,
    const __nv_bfloat16* __restrict__ kb,
    const __nv_bfloat16* __restrict__ vb,
    __nv_bfloat16* __restrict__ Ho, __nv_bfloat16* __restrict__ Lo) {
    extern __shared__ char smem[];
    uint32_t sb = smem_u32(smem);
    int tid = threadIdx.x, lid = tid & 31, wid = tid >> 5;
    int p = blockIdx.y, q0 = blockIdx.x * 128;
    int b = p / 6, h = p - b * 6;
    const __nv_bfloat16* Qg = qb + ((size_t)p * 1024 + q0) * 64;
    const __nv_bfloat16* Kg = kb + (size_t)p * 1024 * 64;
    const __nv_bfloat16* Vg = vb + (size_t)p * 1024 * 64;

    #pragma unroll
    for (int i = 0; i < 8; i++) {
        int u = i * 128 + tid, r = u >> 3, c = u & 7;
        cp16(sb + SQ_OFF + r * AT_STB + c * 16, Qg + (size_t)r * 64 + c * 8);
    }
    #pragma unroll
    for (int i = 0; i < 4; i++) {
        int u = i * 128 + tid, r = u >> 3, c = u & 7;
        cp16(sb + SK0_OFF + r * AT_STB + c * 16, Kg + (size_t)r * 64 + c * 8);
        cp16(sb + SV0_OFF + r * AT_STB + c * 16, Vg + (size_t)r * 64 + c * 8);
    }
    CP_COMMIT();
    CP_WAIT(0);
    __syncthreads();

    int rA = lid & 15, hA = lid >> 4;
    uint32_t qf[2][4][4];
    #pragma unroll
    for (int mi = 0; mi < 2; mi++)
        #pragma unroll
        for (int kk = 0; kk < 4; kk++)
            ldsm_x4(sb + SQ_OFF + (wid * 32 + mi * 16 + rA) * AT_STB
                       + (kk * 16 + hA * 8) * 2, qf[mi][kk]);

    float o[2][8][4];
    #pragma unroll
    for (int mi = 0; mi < 2; mi++)
        #pragma unroll
        for (int j = 0; j < 8; j++)
            #pragma unroll
            for (int q = 0; q < 4; q++) o[mi][j][q] = 0.0f;
    float lsum[2][2] = {{0.0f, 0.0f}, {0.0f, 0.0f}};

    int rB = (lid & 7) + ((lid >> 4) << 3), hB = (lid >> 3) & 1;
    int tv = lid & 7, v8 = (lid >> 3) & 1, v16 = (lid >> 4) & 1;

    for (int kt = 0; kt < 16; kt++) {
        int buf = kt & 1;
        __syncthreads();
        if (kt + 1 < 16) {
            const __nv_bfloat16* Kn = Kg + (size_t)(kt + 1) * 64 * 64;
            const __nv_bfloat16* Vn = Vg + (size_t)(kt + 1) * 64 * 64;
            uint32_t dK = sb + (buf ? SK0_OFF : SK1_OFF);
            uint32_t dV = sb + (buf ? SV0_OFF : SV1_OFF);
            #pragma unroll
            for (int i = 0; i < 4; i++) {
                int u = i * 128 + tid, r = u >> 3, c = u & 7;
                cp16(dK + r * AT_STB + c * 16, Kn + (size_t)r * 64 + c * 8);
                cp16(dV + r * AT_STB + c * 16, Vn + (size_t)r * 64 + c * 8);
            }
        }
        CP_COMMIT();
        CP_WAIT(1);
        __syncthreads();
        uint32_t sK = sb + (buf ? SK1_OFF : SK0_OFF);
        uint32_t sV = sb + (buf ? SV1_OFF : SV0_OFF);

        float sacc[2][8][4];
        #pragma unroll
        for (int mi = 0; mi < 2; mi++)
            #pragma unroll
            for (int j = 0; j < 8; j++)
                #pragma unroll
                for (int q = 0; q < 4; q++) sacc[mi][j][q] = 0.0f;
        #pragma unroll
        for (int kk = 0; kk < 4; kk++) {
            uint32_t bfm[4][4];
            #pragma unroll
            for (int jj = 0; jj < 4; jj++)
                ldsm_x4(sK + (jj * 16 + rB) * AT_STB + (kk * 16 + hB * 8) * 2,
                        bfm[jj]);
            #pragma unroll
            for (int mi = 0; mi < 2; mi++)
                #pragma unroll
                for (int jj = 0; jj < 4; jj++) {
                    mma_bf16(sacc[mi][2 * jj],     qf[mi][kk], bfm[jj][0], bfm[jj][1]);
                    mma_bf16(sacc[mi][2 * jj + 1], qf[mi][kk], bfm[jj][2], bfm[jj][3]);
                }
        }
        #pragma unroll
        for (int mi = 0; mi < 2; mi++)
            #pragma unroll
            for (int j = 0; j < 8; j++) {
                sacc[mi][j][0] = __expf(sacc[mi][j][0]);
                sacc[mi][j][1] = __expf(sacc[mi][j][1]);
                sacc[mi][j][2] = __expf(sacc[mi][j][2]);
                sacc[mi][j][3] = __expf(sacc[mi][j][3]);
                lsum[mi][0] += sacc[mi][j][0] + sacc[mi][j][1];
                lsum[mi][1] += sacc[mi][j][2] + sacc[mi][j][3];
            }
        #pragma unroll
        for (int kk = 0; kk < 4; kk++) {
            uint32_t vf[4][4];
            #pragma unroll
            for (int jj = 0; jj < 4; jj++)
                ldsm_x4t(sV + (kk * 16 + v8 * 8 + tv) * AT_STB
                            + (jj * 16 + v16 * 8) * 2, vf[jj]);
            #pragma unroll
            for (int mi = 0; mi < 2; mi++) {
                uint32_t pa[4];
                pa[0] = bf2pk(sacc[mi][2 * kk][0],     sacc[mi][2 * kk][1]);
                pa[1] = bf2pk(sacc[mi][2 * kk][2],     sacc[mi][2 * kk][3]);
                pa[2] = bf2pk(sacc[mi][2 * kk + 1][0], sacc[mi][2 * kk + 1][1]);
                pa[3] = bf2pk(sacc[mi][2 * kk + 1][2], sacc[mi][2 * kk + 1][3]);
                #pragma unroll
                for (int jj = 0; jj < 4; jj++) {
                    mma_bf16(o[mi][2 * jj],     pa, vf[jj][0], vf[jj][1]);
                    mma_bf16(o[mi][2 * jj + 1], pa, vf[jj][2], vf[jj][3]);
                }
            }
        }
    }

    #pragma unroll
    for (int mi = 0; mi < 2; mi++)
        #pragma unroll
        for (int rr = 0; rr < 2; rr++) {
            lsum[mi][rr] += __shfl_xor_sync(0xffffffffu, lsum[mi][rr], 1);
            lsum[mi][rr] += __shfl_xor_sync(0xffffffffu, lsum[mi][rr], 2);
        }

    #pragma unroll
    for (int mi = 0; mi < 2; mi++) {
        float inv0 = 1.0f / lsum[mi][0];
        float inv1 = 1.0f / lsum[mi][1];
        int r0 = q0 + wid * 32 + mi * 16 + (lid >> 2);
        size_t row0 = ((size_t)b * 1024 + r0) * 384 + h * 64;
        size_t row1 = row0 + (size_t)8 * 384;
        #pragma unroll
        for (int j = 0; j < 8; j++) {
            int col = j * 8 + (lid & 3) * 2;
            split_store(Ho, Lo, row0 + col, o[mi][j][0] * inv0, o[mi][j][1] * inv0);
            split_store(Ho, Lo, row1 + col, o[mi][j][2] * inv1, o[mi][j][3] * inv1);
        }
    }
}

// ---------------- kNN gather + leaky_relu + max ----------------------------
__global__ void knn_kernel(const float* __restrict__ AbCc,
                           const int* __restrict__ knn,
                           const float* __restrict__ bknn,
                           __nv_bfloat16* __restrict__ Ho,
                           __nv_bfloat16* __restrict__ Lo) {
    int row = blockIdx.x;
    int b = row >> 10, n = row & 1023;
    __shared__ int idxs[8];
    if (threadIdx.x < 8) idxs[threadIdx.x] = knn[((b << 3) + threadIdx.x) * 1024 + n];
    __syncthreads();
    #pragma unroll
    for (int cc = 0; cc < 3; cc++) {
        int c = threadIdx.x + cc * 128;
        float base = AbCc[(size_t)row * 768 + 384 + c] + bknn[c];
        float mx = -3.0e38f;
        #pragma unroll
        for (int k = 0; k < 8; k++) {
            float v = __ldg(&AbCc[(size_t)idxs[k] * 768 + c]) + base;
            v = (v > 0.0f) ? v : 0.2f * v;
            mx = fmaxf(mx, v);
        }
        size_t oi = (size_t)row * 768 + 384 + c;
        __nv_bfloat16 hb = __float2bfloat16_rn(mx);
        Ho[oi] = hb;
        Lo[oi] = __float2bfloat16_rn(mx - __bfloat162float(hb));
    }
}

// ---------------------------------------------------------------------------
extern "C" void kernel_launch(void* const* d_in, const int* in_sizes, int n_in,
                              void* d_out, int out_size) {
    (void)in_sizes; (void)n_in; (void)out_size;
    const float* x       = (const float*)d_in[0];
    const int*   knn     = (const int*)  d_in[1];
    const float* ln1_w   = (const float*)d_in[2];
    const float* ln1_b   = (const float*)d_in[3];
    const float* w_qkv   = (const float*)d_in[4];
    const float* w_proj  = (const float*)d_in[5];
    const float* b_proj  = (const float*)d_in[6];
    const float* w_knn   = (const float*)d_in[7];
    const float* b_knn   = (const float*)d_in[8];
    const float* w_merge = (const float*)d_in[9];
    const float* b_merge = (const float*)d_in[10];
    const float* ln2_w   = (const float*)d_in[11];
    const float* ln2_b   = (const float*)d_in[12];
    const float* w_fc1   = (const float*)d_in[13];
    const float* b_fc1   = (const float*)d_in[14];
    const float* w_fc2   = (const float*)d_in[15];
    const float* b_fc2   = (const float*)d_in[16];
    float* out = (float*)d_out;

    float *AbCc, *xres;
    cudaGetSymbolAddress((void**)&AbCc, g_AbCc);
    cudaGetSymbolAddress((void**)&xres, g_xres);

    __nv_bfloat16 *qb,*kb,*vb;
    cudaGetSymbolAddress((void**)&qb, g_qb);
    cudaGetSymbolAddress((void**)&kb, g_kb);
    cudaGetSymbolAddress((void**)&vb, g_vb);

    __nv_bfloat16 *nxh,*nxl,*aoh,*aol,*cath,*catl,*l2h,*l2l,*hh,*hl;
    __nv_bfloat16 *wqh,*wql,*wph,*wpl,*wkh,*wkl,*wmh,*wml,*f1h,*f1l,*f2h,*f2l;
    cudaGetSymbolAddress((void**)&nxh, g_nxh);   cudaGetSymbolAddress((void**)&nxl, g_nxl);
    cudaGetSymbolAddress((void**)&aoh, g_aoh);   cudaGetSymbolAddress((void**)&aol, g_aol);
    cudaGetSymbolAddress((void**)&cath,g_cath);  cudaGetSymbolAddress((void**)&catl,g_catl);
    cudaGetSymbolAddress((void**)&l2h, g_l2h);   cudaGetSymbolAddress((void**)&l2l, g_l2l);
    cudaGetSymbolAddress((void**)&hh,  g_hh);    cudaGetSymbolAddress((void**)&hl,  g_hl);
    cudaGetSymbolAddress((void**)&wqh, g_wqkvh); cudaGetSymbolAddress((void**)&wql, g_wqkvl);
    cudaGetSymbolAddress((void**)&wph, g_wprojh);cudaGetSymbolAddress((void**)&wpl, g_wprojl);
    cudaGetSymbolAddress((void**)&wkh, g_wkh);   cudaGetSymbolAddress((void**)&wkl, g_wkl);
    cudaGetSymbolAddress((void**)&wmh, g_wmh);   cudaGetSymbolAddress((void**)&wml, g_wml);
    cudaGetSymbolAddress((void**)&f1h, g_f1h);   cudaGetSymbolAddress((void**)&f1l, g_f1l);
    cudaGetSymbolAddress((void**)&f2h, g_f2h);   cudaGetSymbolAddress((void**)&f2l, g_f2l);

    cudaFuncSetAttribute(tgemm<0,0,1>, cudaFuncAttributeMaxDynamicSharedMemorySize, SMEM_MM4);
    cudaFuncSetAttribute(tgemm<0,1,1>, cudaFuncAttributeMaxDynamicSharedMemorySize, SMEM_MM4);
    cudaFuncSetAttribute(tgemm<1,1,1>, cudaFuncAttributeMaxDynamicSharedMemorySize, SMEM_MM4);
    cudaFuncSetAttribute(tgemm<0,2,0>, cudaFuncAttributeMaxDynamicSharedMemorySize, SMEM_MM2);
    cudaFuncSetAttribute(attn_mma,     cudaFuncAttributeMaxDynamicSharedMemorySize, SMEM_AT);

    // fork-join: side stream runs the kNN branch first, then deferred tsplits
    cudaStream_t sB;
    cudaStreamCreateWithFlags(&sB, cudaStreamNonBlocking);
    cudaEvent_t evFork, evLn, evB, evW2;
    cudaEventCreateWithFlags(&evFork, cudaEventDisableTiming);
    cudaEventCreateWithFlags(&evLn,   cudaEventDisableTiming);
    cudaEventCreateWithFlags(&evB,    cudaEventDisableTiming);
    cudaEventCreateWithFlags(&evW2,   cudaEventDisableTiming);

    cudaEventRecord(evFork, 0);
    cudaStreamWaitEvent(sB, evFork, 0);

    // --- main stream: LN1 -> qkv GEMM (plain bf16, direct layout) -> attn ---
    tsplit<<<1728, 256>>>(w_qkv, wqh, wql, 384, 1152);
    ln_kernel<<<MROWS, 128>>>(x, ln1_w, ln1_b, nxh, nxl);
    cudaEventRecord(evLn, 0);
    tgemm<0,2,0><<<dim3(9, 128), 256, SMEM_MM2>>>(nxh, nullptr, wqh, nullptr,
        nullptr, nullptr, nullptr, nullptr, nullptr, qb, kb, vb, 384, 1152, 0);
    tsplit<<<576, 256>>>(w_proj, wph, wpl, 384, 384);
    attn_mma<<<dim3(8, 96), 128, SMEM_AT>>>(qb, kb, vb, aoh, aol);
    tgemm<0,1,1><<<dim3(3, 128), 256, SMEM_MM4>>>(aoh, aol, wph, wpl,
        b_proj, nullptr, nullptr, cath, catl, nullptr, nullptr, nullptr, 384, 768, 0);

    // --- side stream: kNN branch FIRST (full split), then deferred tsplits ---
    tsplit_knn2<<<1152, 256, 0, sB>>>(w_knn, wkh, wkl);
    cudaStreamWaitEvent(sB, evLn, 0);
    tgemm<0,0,1><<<dim3(6, 128), 256, SMEM_MM4, sB>>>(nxh, nxl, wkh, wkl,
        nullptr, nullptr, AbCc, nullptr, nullptr, nullptr, nullptr, nullptr, 384, 768, 0);
    knn_kernel<<<MROWS, 128, 0, sB>>>(AbCc, knn, b_knn, cath, catl);
    tsplit<<<1152, 256, 0, sB>>>(w_merge, wmh, wml, 768, 384);
    cudaEventRecord(evB, sB);
    tsplit<<<2304, 256, 0, sB>>>(w_fc1, f1h, f1l, 384, 768);
    tsplit<<<2304, 256, 0, sB>>>(w_fc2, f2h, f2l, 768, 384);
    cudaEventRecord(evW2, sB);

    // --- join, then merge + MLP (full split) ---
    cudaStreamWaitEvent(0, evB, 0);
    tgemm<0,0,1><<<dim3(3, 128), 256, SMEM_MM4>>>(cath, catl, wmh, wml,
        b_merge, x, xres, nullptr, nullptr, nullptr, nullptr, nullptr, 768, 384, 384);
    ln_kernel<<<MROWS, 128>>>(xres, ln2_w, ln2_b, l2h, l2l);
    cudaStreamWaitEvent(0, evW2, 0);
    tgemm<1,1,1><<<dim3(6, 128), 256, SMEM_MM4>>>(l2h, l2l, f1h, f1l,
        b_fc1, nullptr, nullptr, hh, hl, nullptr, nullptr, nullptr, 384, 768, 0);
    tgemm<0,0,1><<<dim3(3, 128), 256, SMEM_MM4>>>(hh, hl, f2h, f2l,
        b_fc2, xres, out, nullptr, nullptr, nullptr, nullptr, nullptr, 768, 384, 384);
}

// round 12
// speedup vs baseline: 1.0661x; 1.0661x over previous
#include <cuda_runtime.h>
#include <cuda_bf16.h>
#include <math.h>
#include <stdint.h>

// ---------------------------------------------------------------------------
// PCTransformer block, GB300 (sm_103a, compute_103 baseline PTX)
// B=16, N=1024, C=384, H=6, HD=64, K=8, HID=768, M=B*N=16384
// Merge GEMM folded away: x1 = knn_f@Wm2 + bias2 ; x2 = x + ao@(w_proj@Wm1).
// Dense GEMMs: merged-K bf16 HMMA, 2-term split on residual-accuracy paths.
// Attention: HMMA flash. 3 streams (static-once), MLP pipelined by M-halves.
// ---------------------------------------------------------------------------

#define MROWS 16384

// ---------------- scratch (static device globals; no allocation) -----------
__device__ float g_AbCc[MROWS * 768];    // [Ab | Cc] for kNN branch
__device__ float g_x1  [MROWS * 384];    // knn_f@Wm2 + bias2
__device__ float g_x2  [MROWS * 384];    // x + ao@Wpm
__device__ float g_xres[MROWS * 384];    // x1 + x2 (written by ln2sum)
__device__ float g_wpm [384 * 384];      // (w_proj@Wm1)^T-layout fp32
__device__ float g_b2  [384];            // b_proj@Wm1 + b_merge

// per-(b,h) contiguous bf16 Q/K/V  [96][1024][64]
__device__ __align__(16) __nv_bfloat16 g_qb[96*1024*64];
__device__ __align__(16) __nv_bfloat16 g_kb[96*1024*64];
__device__ __align__(16) __nv_bfloat16 g_vb[96*1024*64];

// bf16 split activations
__device__ __align__(16) __nv_bfloat16 g_nxh[MROWS*384],  g_nxl[MROWS*384];
__device__ __align__(16) __nv_bfloat16 g_aoh[MROWS*384],  g_aol[MROWS*384];
__device__ __align__(16) __nv_bfloat16 g_knnh[MROWS*384], g_knnl[MROWS*384];
__device__ __align__(16) __nv_bfloat16 g_l2h[MROWS*384],  g_l2l[MROWS*384];
__device__ __align__(16) __nv_bfloat16 g_hh[MROWS*768],   g_hl[MROWS*768];

// bf16 split weights
__device__ __align__(16) __nv_bfloat16 g_wqkvh[1152*384], g_wqkvl[1152*384];
__device__ __align__(16) __nv_bfloat16 g_wprh[384*384],   g_wprl[384*384];
__device__ __align__(16) __nv_bfloat16 g_wkh[768*384],    g_wkl[768*384];    // [W1 | W2-W1]^T
__device__ __align__(16) __nv_bfloat16 g_wmh[384*768],    g_wml[384*768];    // w_merge^T
__device__ __align__(16) __nv_bfloat16 g_wm2h[384*384],   g_wm2l[384*384];   // Wm2^T
__device__ __align__(16) __nv_bfloat16 g_wpmh[384*384],   g_wpml[384*384];   // Wpm^T split
__device__ __align__(16) __nv_bfloat16 g_f1h[768*384],    g_f1l[768*384];
__device__ __align__(16) __nv_bfloat16 g_f2h[384*768],    g_f2l[384*768];

// ---------------- PTX helpers ----------------------------------------------
__device__ __forceinline__ uint32_t smem_u32(const void* p) {
    uint32_t a;
    asm("{ .reg .u64 t; cvta.to.shared.u64 t, %1; cvt.u32.u64 %0, t; }"
        : "=r"(a) : "l"(p));
    return a;
}
__device__ __forceinline__ void ldsm_x4(uint32_t addr, uint32_t* r) {
    asm volatile("ldmatrix.sync.aligned.m8n8.x4.shared.b16 {%0,%1,%2,%3}, [%4];"
                 : "=r"(r[0]), "=r"(r[1]), "=r"(r[2]), "=r"(r[3]) : "r"(addr));
}
__device__ __forceinline__ void ldsm_x4t(uint32_t addr, uint32_t* r) {
    asm volatile("ldmatrix.sync.aligned.m8n8.x4.trans.shared.b16 {%0,%1,%2,%3}, [%4];"
                 : "=r"(r[0]), "=r"(r[1]), "=r"(r[2]), "=r"(r[3]) : "r"(addr));
}
__device__ __forceinline__ void mma_bf16(float* c, const uint32_t* a,
                                         uint32_t b0, uint32_t b1) {
    asm volatile(
        "mma.sync.aligned.m16n8k16.row.col.f32.bf16.bf16.f32 "
        "{%0,%1,%2,%3},{%4,%5,%6,%7},{%8,%9},{%0,%1,%2,%3};"
        : "+f"(c[0]), "+f"(c[1]), "+f"(c[2]), "+f"(c[3])
        : "r"(a[0]), "r"(a[1]), "r"(a[2]), "r"(a[3]), "r"(b0), "r"(b1));
}
__device__ __forceinline__ void cp16(uint32_t dst, const void* src) {
    asm volatile("cp.async.cg.shared.global [%0], [%1], 16;"
                 :: "r"(dst), "l"(src) : "memory");
}
#define CP_COMMIT() asm volatile("cp.async.commit_group;" ::: "memory")
#define CP_WAIT(n)  asm volatile("cp.async.wait_group %0;" :: "n"(n) : "memory")

__device__ __forceinline__ uint32_t bf2pk(float lo, float hi) {
    uint32_t r;
    asm("cvt.rn.bf16x2.f32 %0, %1, %2;" : "=r"(r) : "f"(hi), "f"(lo));
    return r;
}

__device__ __forceinline__ void split_store(__nv_bfloat16* H, __nv_bfloat16* L,
                                            size_t idx, float x, float y) {
    __nv_bfloat16 hx = __float2bfloat16_rn(x);
    __nv_bfloat16 hy = __float2bfloat16_rn(y);
    *(__nv_bfloat162*)&H[idx] = __nv_bfloat162(hx, hy);
    *(__nv_bfloat162*)&L[idx] =
        __nv_bfloat162(__float2bfloat16_rn(x - __bfloat162float(hx)),
                       __float2bfloat16_rn(y - __bfloat162float(hy)));
}

// qkv GEMM epilogue: write directly into per-(b,h) bf16 Q(scaled)/K/V
__device__ __forceinline__ void qkv_store(__nv_bfloat16* qp, __nv_bfloat16* kp,
                                          __nv_bfloat16* vp, int token, int col,
                                          float x, float y) {
    int bb = token >> 10, n = token & 1023;
    int which = col / 384;
    int rem = col - which * 384;
    int h = rem >> 6, d = rem & 63;
    size_t di = ((size_t)(bb * 6 + h) * 1024 + n) * 64 + d;
    float sc = (which == 0) ? 0.125f : 1.0f;
    __nv_bfloat16* dst = (which == 0) ? qp : ((which == 1) ? kp : vp);
    *(__nv_bfloat162*)&dst[di] =
        __nv_bfloat162(__float2bfloat16_rn(x * sc), __float2bfloat16_rn(y * sc));
}

// ---------------- LayerNorm (writes bf16 split) ----------------------------
__global__ void ln_kernel(const float* __restrict__ x,
                          const float* __restrict__ w,
                          const float* __restrict__ b,
                          __nv_bfloat16* __restrict__ H,
                          __nv_bfloat16* __restrict__ L) {
    int row = blockIdx.x, tid = threadIdx.x;
    const float* xr = x + (size_t)row * 384;
    float v0 = xr[tid], v1 = xr[tid + 128], v2 = xr[tid + 256];
    float s  = v0 + v1 + v2;
    float sq = v0 * v0 + v1 * v1 + v2 * v2;
    #pragma unroll
    for (int o = 16; o; o >>= 1) {
        s  += __shfl_xor_sync(0xffffffffu, s,  o);
        sq += __shfl_xor_sync(0xffffffffu, sq, o);
    }
    __shared__ float ss[4], sqs[4];
    int wid = tid >> 5, lid = tid & 31;
    if (lid == 0) { ss[wid] = s; sqs[wid] = sq; }
    __syncthreads();
    s  = ss[0] + ss[1] + ss[2] + ss[3];
    sq = sqs[0] + sqs[1] + sqs[2] + sqs[3];
    float mean = s * (1.0f / 384.0f);
    float var  = sq * (1.0f / 384.0f) - mean * mean;
    float inv  = rsqrtf(var + 1e-5f);
    size_t base = (size_t)row * 384;
    #pragma unroll
    for (int cc = 0; cc < 3; cc++) {
        int c = tid + cc * 128;
        float v = (cc == 0 ? v0 : (cc == 1 ? v1 : v2));
        float y = (v - mean) * inv * w[c] + b[c];
        __nv_bfloat16 h = __float2bfloat16_rn(y);
        H[base + c] = h;
        L[base + c] = __float2bfloat16_rn(y - __bfloat162float(h));
    }
}

// LN over (x1+x2); also writes the fp32 sum (residual for fc2)
__global__ void ln2sum_kernel(const float* __restrict__ x1,
                              const float* __restrict__ x2,
                              const float* __restrict__ w,
                              const float* __restrict__ b,
                              float* __restrict__ xres,
                              __nv_bfloat16* __restrict__ H,
                              __nv_bfloat16* __restrict__ L) {
    int row = blockIdx.x, tid = threadIdx.x;
    size_t base = (size_t)row * 384;
    float v0 = x1[base + tid]       + x2[base + tid];
    float v1 = x1[base + tid + 128] + x2[base + tid + 128];
    float v2 = x1[base + tid + 256] + x2[base + tid + 256];
    xres[base + tid]       = v0;
    xres[base + tid + 128] = v1;
    xres[base + tid + 256] = v2;
    float s  = v0 + v1 + v2;
    float sq = v0 * v0 + v1 * v1 + v2 * v2;
    #pragma unroll
    for (int o = 16; o; o >>= 1) {
        s  += __shfl_xor_sync(0xffffffffu, s,  o);
        sq += __shfl_xor_sync(0xffffffffu, sq, o);
    }
    __shared__ float ss[4], sqs[4];
    int wid = tid >> 5, lid = tid & 31;
    if (lid == 0) { ss[wid] = s; sqs[wid] = sq; }
    __syncthreads();
    s  = ss[0] + ss[1] + ss[2] + ss[3];
    sq = sqs[0] + sqs[1] + sqs[2] + sqs[3];
    float mean = s * (1.0f / 384.0f);
    float var  = sq * (1.0f / 384.0f) - mean * mean;
    float inv  = rsqrtf(var + 1e-5f);
    #pragma unroll
    for (int cc = 0; cc < 3; cc++) {
        int c = tid + cc * 128;
        float v = (cc == 0 ? v0 : (cc == 1 ? v1 : v2));
        float y = (v - mean) * inv * w[c] + b[c];
        __nv_bfloat16 h = __float2bfloat16_rn(y);
        H[base + c] = h;
        L[base + c] = __float2bfloat16_rn(y - __bfloat162float(h));
    }
}

__device__ __forceinline__ float gelu_exact(float v) {
    return 0.5f * v * (1.0f + erff(v * 0.70710678118654752f));
}

// ---------------- weight prep kernels --------------------------------------
__global__ void tsplit(const float* __restrict__ W,
                       __nv_bfloat16* __restrict__ Th,
                       __nv_bfloat16* __restrict__ Tl, int K, int N) {
    int idx = blockIdx.x * 256 + threadIdx.x;
    if (idx >= K * N) return;
    int n = idx / K, k = idx - n * K;
    float v = W[(size_t)k * N + n];
    __nv_bfloat16 h = __float2bfloat16_rn(v);
    Th[idx] = h;
    Tl[idx] = __float2bfloat16_rn(v - __bfloat162float(h));
}

__global__ void fsplit(const float* __restrict__ W,
                       __nv_bfloat16* __restrict__ Th,
                       __nv_bfloat16* __restrict__ Tl, int n) {
    int idx = blockIdx.x * 256 + threadIdx.x;
    if (idx >= n) return;
    float v = W[idx];
    __nv_bfloat16 h = __float2bfloat16_rn(v);
    Th[idx] = h;
    Tl[idx] = __float2bfloat16_rn(v - __bfloat162float(h));
}

__global__ void tsplit_knn2(const float* __restrict__ W,
                            __nv_bfloat16* __restrict__ Th,
                            __nv_bfloat16* __restrict__ Tl) {
    int idx = blockIdx.x * 256 + threadIdx.x;
    if (idx >= 768 * 384) return;
    int np = idx / 384, k = idx - np * 384;
    float v;
    if (np < 384) {
        v = W[(size_t)k * 384 + np];
    } else {
        int n = np - 384;
        v = W[(size_t)(384 + k) * 384 + n] - W[(size_t)k * 384 + n];
    }
    __nv_bfloat16 h = __float2bfloat16_rn(v);
    Th[idx] = h;
    Tl[idx] = __float2bfloat16_rn(v - __bfloat162float(h));
}

__global__ void bias2_kernel(const float* __restrict__ bp,
                             const float* __restrict__ wm,
                             const float* __restrict__ bm,
                             float* __restrict__ out) {
    int n = blockIdx.x * 128 + threadIdx.x;
    if (n >= 384) return;
    float s = 0.0f;
    for (int j = 0; j < 384; j++) s += bp[j] * wm[(size_t)j * 384 + n];
    out[n] = s + bm[n];
}

// ---------------- HMMA GEMM, merged split loop -----------------------------
#define ROWB    80
#define TILE_B  (128 * ROWB)
#define SMEM_MM4 (2 * 4 * TILE_B)   // 81920 (split)
#define SMEM_MM2 (2 * 2 * TILE_B)   // 40960 (nosplit)

template <int GELU, int OMODE, int SPLITIN>
__global__ void __launch_bounds__(256, 2) tgemm(
    const __nv_bfloat16* __restrict__ Ah, const __nv_bfloat16* __restrict__ Al,
    const __nv_bfloat16* __restrict__ Bh, const __nv_bfloat16* __restrict__ Bl,
    const float* __restrict__ bias, const float* __restrict__ res,
    float* __restrict__ C, __nv_bfloat16* __restrict__ Ho,
    __nv_bfloat16* __restrict__ Lo,
    __nv_bfloat16* __restrict__ qp, __nv_bfloat16* __restrict__ kp,
    __nv_bfloat16* __restrict__ vp,
    int K, int lda, int ldb, int ldc, int ldres) {
    extern __shared__ char smem[];
    uint32_t sb = smem_u32(smem);
    int tid = threadIdx.x, lid = tid & 31, w = tid >> 5;
    int wm = w & 1, wn = w >> 1;
    int m0 = blockIdx.y * 128, n0 = blockIdx.x * 128;
    const int NIT = K >> 5;
    constexpr int NT = SPLITIN ? 4 : 2;
    constexpr uint32_t STG_B = NT * TILE_B;
    constexpr uint32_t BOFF  = (SPLITIN ? 2 : 1) * TILE_B;

    float acc[4][4][4];
    #pragma unroll
    for (int i = 0; i < 4; i++)
        #pragma unroll
        for (int j = 0; j < 4; j++)
            #pragma unroll
            for (int q = 0; q < 4; q++) acc[i][j][q] = 0.0f;

    int c0 = tid * 2;
    int lr0 = c0 >> 2,       lq0 = c0 & 3;
    int lr1 = (c0 + 1) >> 2, lq1 = (c0 + 1) & 3;

    auto load_stage = [&](int kc, int s) {
        const __nv_bfloat16* Ag = Ah + (size_t)m0 * lda + kc * 32;
        const __nv_bfloat16* Bg = Bh + (size_t)n0 * ldb + kc * 32;
        uint32_t st = sb + s * STG_B;
        uint32_t d0 = lr0 * ROWB + lq0 * 16, d1 = lr1 * ROWB + lq1 * 16;
        size_t a0 = (size_t)lr0 * lda + lq0 * 8, a1 = (size_t)lr1 * lda + lq1 * 8;
        size_t b0 = (size_t)lr0 * ldb + lq0 * 8, b1 = (size_t)lr1 * ldb + lq1 * 8;
        cp16(st + d0,        Ag + a0);
        cp16(st + d1,        Ag + a1);
        cp16(st + BOFF + d0, Bg + b0);
        cp16(st + BOFF + d1, Bg + b1);
        if (SPLITIN) {
            const __nv_bfloat16* Ag2 = Al + (size_t)m0 * lda + kc * 32;
            const __nv_bfloat16* Bg2 = Bl + (size_t)n0 * ldb + kc * 32;
            cp16(st + TILE_B + d0,     Ag2 + a0);
            cp16(st + TILE_B + d1,     Ag2 + a1);
            cp16(st + 3 * TILE_B + d0, Bg2 + b0);
            cp16(st + 3 * TILE_B + d1, Bg2 + b1);
        }
    };

    int rA = lid & 15, hA = lid >> 4;
    int rB = (lid & 7) + ((lid >> 4) << 3), hB = (lid >> 3) & 1;

    auto compute_stage = [&](int s) {
        uint32_t sAh = sb + s * STG_B + (wm * 64) * ROWB;
        uint32_t sBh = sb + s * STG_B + BOFF + (wn * 32) * ROWB;
        #pragma unroll
        for (int ks = 0; ks < 2; ks++) {
            int kk = ks * 16;
            uint32_t a[4][4];
            #pragma unroll
            for (int i = 0; i < 4; i++)
                ldsm_x4(sAh + (i * 16 + rA) * ROWB + (kk + hA * 8) * 2, a[i]);
            uint32_t bh[2][4];
            #pragma unroll
            for (int jj = 0; jj < 2; jj++)
                ldsm_x4(sBh + (jj * 16 + rB) * ROWB + (kk + hB * 8) * 2, bh[jj]);
            #pragma unroll
            for (int i = 0; i < 4; i++)
                #pragma unroll
                for (int j = 0; j < 4; j++)
                    mma_bf16(acc[i][j], a[i], bh[j >> 1][(j & 1) * 2],
                             bh[j >> 1][(j & 1) * 2 + 1]);
            if (SPLITIN) {
                uint32_t sAl = sAh + TILE_B;
                uint32_t sBl = sBh + TILE_B;
                uint32_t bl[2][4];
                #pragma unroll
                for (int jj = 0; jj < 2; jj++)
                    ldsm_x4(sBl + (jj * 16 + rB) * ROWB + (kk + hB * 8) * 2, bl[jj]);
                #pragma unroll
                for (int i = 0; i < 4; i++)
                    #pragma unroll
                    for (int j = 0; j < 4; j++)
                        mma_bf16(acc[i][j], a[i], bl[j >> 1][(j & 1) * 2],
                                 bl[j >> 1][(j & 1) * 2 + 1]);
                uint32_t al[4][4];
                #pragma unroll
                for (int i = 0; i < 4; i++)
                    ldsm_x4(sAl + (i * 16 + rA) * ROWB + (kk + hA * 8) * 2, al[i]);
                #pragma unroll
                for (int i = 0; i < 4; i++)
                    #pragma unroll
                    for (int j = 0; j < 4; j++)
                        mma_bf16(acc[i][j], al[i], bh[j >> 1][(j & 1) * 2],
                                 bh[j >> 1][(j & 1) * 2 + 1]);
            }
        }
    };

    load_stage(0, 0); CP_COMMIT();
    for (int it = 0; it < NIT; ++it) {
        if (it + 1 < NIT) { load_stage(it + 1, (it + 1) & 1); CP_COMMIT(); }
        if (it + 1 < NIT) CP_WAIT(1); else CP_WAIT(0);
        __syncthreads();
        compute_stage(it & 1);
        __syncthreads();
    }

    #pragma unroll
    for (int i = 0; i < 4; i++) {
        int r0 = m0 + wm * 64 + i * 16 + (lid >> 2);
        int r1 = r0 + 8;
        #pragma unroll
        for (int j = 0; j < 4; j++) {
            int col = n0 + wn * 32 + j * 8 + (lid & 3) * 2;
            float2 v0 = make_float2(acc[i][j][0], acc[i][j][1]);
            float2 v1 = make_float2(acc[i][j][2], acc[i][j][3]);
            if (bias) {
                float2 bb = *(const float2*)&bias[col];
                v0.x += bb.x; v0.y += bb.y; v1.x += bb.x; v1.y += bb.y;
            }
            if (GELU) {
                v0.x = gelu_exact(v0.x); v0.y = gelu_exact(v0.y);
                v1.x = gelu_exact(v1.x); v1.y = gelu_exact(v1.y);
            }
            if (res) {
                float2 q0 = *(const float2*)&res[(size_t)r0 * ldres + col];
                float2 q1 = *(const float2*)&res[(size_t)r1 * ldres + col];
                v0.x += q0.x; v0.y += q0.y; v1.x += q1.x; v1.y += q1.y;
            }
            if (OMODE == 2) {
                qkv_store(qp, kp, vp, r0, col, v0.x, v0.y);
                qkv_store(qp, kp, vp, r1, col, v1.x, v1.y);
            } else if (OMODE == 1) {
                split_store(Ho, Lo, (size_t)r0 * ldc + col, v0.x, v0.y);
                split_store(Ho, Lo, (size_t)r1 * ldc + col, v1.x, v1.y);
            } else {
                *(float2*)&C[(size_t)r0 * ldc + col] = v0;
                *(float2*)&C[(size_t)r1 * ldc + col] = v1;
            }
        }
    }
}

// ---------------- HMMA flash attention -------------------------------------
#define AT_STB  144
#define SQ_OFF  0
#define SK0_OFF (128 * AT_STB)
#define SV0_OFF (SK0_OFF + 64 * AT_STB)
#define SK1_OFF (SV0_OFF + 64 * AT_STB)
#define SV1_OFF (SK1_OFF + 64 * AT_STB)
#define SMEM_AT (SV1_OFF + 64 * AT_STB)

__global__ void __launch_bounds__(128) attn_mma(
    const __nv_bfloat16* __restrict__ qb,
    const __nv_bfloat16* __restrict__ kb,
    const __nv_bfloat16* __restrict__ vb,
    __nv_bfloat16* __restrict__ Ho, __nv_bfloat16* __restrict__ Lo) {
    extern __shared__ char smem[];
    uint32_t sb = smem_u32(smem);
    int tid = threadIdx.x, lid = tid & 31, wid = tid >> 5;
    int p = blockIdx.y, q0 = blockIdx.x * 128;
    int b = p / 6, h = p - b * 6;
    const __nv_bfloat16* Qg = qb + ((size_t)p * 1024 + q0) * 64;
    const __nv_bfloat16* Kg = kb + (size_t)p * 1024 * 64;
    const __nv_bfloat16* Vg = vb + (size_t)p * 1024 * 64;

    #pragma unroll
    for (int i = 0; i < 8; i++) {
        int u = i * 128 + tid, r = u >> 3, c = u & 7;
        cp16(sb + SQ_OFF + r * AT_STB + c * 16, Qg + (size_t)r * 64 + c * 8);
    }
    #pragma unroll
    for (int i = 0; i < 4; i++) {
        int u = i * 128 + tid, r = u >> 3, c = u & 7;
        cp16(sb + SK0_OFF + r * AT_STB + c * 16, Kg + (size_t)r * 64 + c * 8);
        cp16(sb + SV0_OFF + r * AT_STB + c * 16, Vg + (size_t)r * 64 + c * 8);
    }
    CP_COMMIT();
    CP_WAIT(0);
    __syncthreads();

    int rA = lid & 15, hA = lid >> 4;
    uint32_t qf[2][4][4];
    #pragma unroll
    for (int mi = 0; mi < 2; mi++)
        #pragma unroll
        for (int kk = 0; kk < 4; kk++)
            ldsm_x4(sb + SQ_OFF + (wid * 32 + mi * 16 + rA) * AT_STB
                       + (kk * 16 + hA * 8) * 2, qf[mi][kk]);

    float o[2][8][4];
    #pragma unroll
    for (int mi = 0; mi < 2; mi++)
        #pragma unroll
        for (int j = 0; j < 8; j++)
            #pragma unroll
            for (int q = 0; q < 4; q++) o[mi][j][q] = 0.0f;
    float lsum[2][2] = {{0.0f, 0.0f}, {0.0f, 0.0f}};

    int rB = (lid & 7) + ((lid >> 4) << 3), hB = (lid >> 3) & 1;
    int tv = lid & 7, v8 = (lid >> 3) & 1, v16 = (lid >> 4) & 1;

    for (int kt = 0; kt < 16; kt++) {
        int buf = kt & 1;
        __syncthreads();
        if (kt + 1 < 16) {
            const __nv_bfloat16* Kn = Kg + (size_t)(kt + 1) * 64 * 64;
            const __nv_bfloat16* Vn = Vg + (size_t)(kt + 1) * 64 * 64;
            uint32_t dK = sb + (buf ? SK0_OFF : SK1_OFF);
            uint32_t dV = sb + (buf ? SV0_OFF : SV1_OFF);
            #pragma unroll
            for (int i = 0; i < 4; i++) {
                int u = i * 128 + tid, r = u >> 3, c = u & 7;
                cp16(dK + r * AT_STB + c * 16, Kn + (size_t)r * 64 + c * 8);
                cp16(dV + r * AT_STB + c * 16, Vn + (size_t)r * 64 + c * 8);
            }
        }
        CP_COMMIT();
        CP_WAIT(1);
        __syncthreads();
        uint32_t sK = sb + (buf ? SK1_OFF : SK0_OFF);
        uint32_t sV = sb + (buf ? SV1_OFF : SV0_OFF);

        float sacc[2][8][4];
        #pragma unroll
        for (int mi = 0; mi < 2; mi++)
            #pragma unroll
            for (int j = 0; j < 8; j++)
                #pragma unroll
                for (int q = 0; q < 4; q++) sacc[mi][j][q] = 0.0f;
        #pragma unroll
        for (int kk = 0; kk < 4; kk++) {
            uint32_t bfm[4][4];
            #pragma unroll
            for (int jj = 0; jj < 4; jj++)
                ldsm_x4(sK + (jj * 16 + rB) * AT_STB + (kk * 16 + hB * 8) * 2,
                        bfm[jj]);
            #pragma unroll
            for (int mi = 0; mi < 2; mi++)
                #pragma unroll
                for (int jj = 0; jj < 4; jj++) {
                    mma_bf16(sacc[mi][2 * jj],     qf[mi][kk], bfm[jj][0], bfm[jj][1]);
                    mma_bf16(sacc[mi][2 * jj + 1], qf[mi][kk], bfm[jj][2], bfm[jj][3]);
                }
        }
        #pragma unroll
        for (int mi = 0; mi < 2; mi++)
            #pragma unroll
            for (int j = 0; j < 8; j++) {
                sacc[mi][j][0] = __expf(sacc[mi][j][0]);
                sacc[mi][j][1] = __expf(sacc[mi][j][1]);
                sacc[mi][j][2] = __expf(sacc[mi][j][2]);
                sacc[mi][j][3] = __expf(sacc[mi][j][3]);
                lsum[mi][0] += sacc[mi][j][0] + sacc[mi][j][1];
                lsum[mi][1] += sacc[mi][j][2] + sacc[mi][j][3];
            }
        #pragma unroll
        for (int kk = 0; kk < 4; kk++) {
            uint32_t vf[4][4];
            #pragma unroll
            for (int jj = 0; jj < 4; jj++)
                ldsm_x4t(sV + (kk * 16 + v8 * 8 + tv) * AT_STB
                            + (jj * 16 + v16 * 8) * 2, vf[jj]);
            #pragma unroll
            for (int mi = 0; mi < 2; mi++) {
                uint32_t pa[4];
                pa[0] = bf2pk(sacc[mi][2 * kk][0],     sacc[mi][2 * kk][1]);
                pa[1] = bf2pk(sacc[mi][2 * kk][2],     sacc[mi][2 * kk][3]);
                pa[2] = bf2pk(sacc[mi][2 * kk + 1][0], sacc[mi][2 * kk + 1][1]);
                pa[3] = bf2pk(sacc[mi][2 * kk + 1][2], sacc[mi][2 * kk + 1][3]);
                #pragma unroll
                for (int jj = 0; jj < 4; jj++) {
                    mma_bf16(o[mi][2 * jj],     pa, vf[jj][0], vf[jj][1]);
                    mma_bf16(o[mi][2 * jj + 1], pa, vf[jj][2], vf[jj][3]);
                }
            }
        }
    }

    #pragma unroll
    for (int mi = 0; mi < 2; mi++)
        #pragma unroll
        for (int rr = 0; rr < 2; rr++) {
            lsum[mi][rr] += __shfl_xor_sync(0xffffffffu, lsum[mi][rr], 1);
            lsum[mi][rr] += __shfl_xor_sync(0xffffffffu, lsum[mi][rr], 2);
        }

    #pragma unroll
    for (int mi = 0; mi < 2; mi++) {
        float inv0 = 1.0f / lsum[mi][0];
        float inv1 = 1.0f / lsum[mi][1];
        int r0 = q0 + wid * 32 + mi * 16 + (lid >> 2);
        size_t row0 = ((size_t)b * 1024 + r0) * 384 + h * 64;
        size_t row1 = row0 + (size_t)8 * 384;
        #pragma unroll
        for (int j = 0; j < 8; j++) {
            int col = j * 8 + (lid & 3) * 2;
            split_store(Ho, Lo, row0 + col, o[mi][j][0] * inv0, o[mi][j][1] * inv0);
            split_store(Ho, Lo, row1 + col, o[mi][j][2] * inv1, o[mi][j][3] * inv1);
        }
    }
}

// ---------------- kNN gather + leaky_relu + max -> split [M,384] -----------
__global__ void knn_kernel(const float* __restrict__ AbCc,
                           const int* __restrict__ knn,
                           const float* __restrict__ bknn,
                           __nv_bfloat16* __restrict__ Ho,
                           __nv_bfloat16* __restrict__ Lo) {
    int row = blockIdx.x;
    int b = row >> 10, n = row & 1023;
    __shared__ int idxs[8];
    if (threadIdx.x < 8) idxs[threadIdx.x] = knn[((b << 3) + threadIdx.x) * 1024 + n];
    __syncthreads();
    #pragma unroll
    for (int cc = 0; cc < 3; cc++) {
        int c = threadIdx.x + cc * 128;
        float base = AbCc[(size_t)row * 768 + 384 + c] + bknn[c];
        float mx = -3.0e38f;
        #pragma unroll
        for (int k = 0; k < 8; k++) {
            float v = __ldg(&AbCc[(size_t)idxs[k] * 768 + c]) + base;
            v = (v > 0.0f) ? v : 0.2f * v;
            mx = fmaxf(mx, v);
        }
        size_t oi = (size_t)row * 384 + c;
        __nv_bfloat16 hb = __float2bfloat16_rn(mx);
        Ho[oi] = hb;
        Lo[oi] = __float2bfloat16_rn(mx - __bfloat162float(hb));
    }
}

// ---------------------------------------------------------------------------
extern "C" void kernel_launch(void* const* d_in, const int* in_sizes, int n_in,
                              void* d_out, int out_size) {
    (void)in_sizes; (void)n_in; (void)out_size;
    const float* x       = (const float*)d_in[0];
    const int*   knn     = (const int*)  d_in[1];
    const float* ln1_w   = (const float*)d_in[2];
    const float* ln1_b   = (const float*)d_in[3];
    const float* w_qkv   = (const float*)d_in[4];
    const float* w_proj  = (const float*)d_in[5];
    const float* b_proj  = (const float*)d_in[6];
    const float* w_knn   = (const float*)d_in[7];
    const float* b_knn   = (const float*)d_in[8];
    const float* w_merge = (const float*)d_in[9];
    const float* b_merge = (const float*)d_in[10];
    const float* ln2_w   = (const float*)d_in[11];
    const float* ln2_b   = (const float*)d_in[12];
    const float* w_fc1   = (const float*)d_in[13];
    const float* b_fc1   = (const float*)d_in[14];
    const float* w_fc2   = (const float*)d_in[15];
    const float* b_fc2   = (const float*)d_in[16];
    float* out = (float*)d_out;

    float *AbCc, *x1, *x2, *xres, *wpm, *b2;
    cudaGetSymbolAddress((void**)&AbCc, g_AbCc);
    cudaGetSymbolAddress((void**)&x1,   g_x1);
    cudaGetSymbolAddress((void**)&x2,   g_x2);
    cudaGetSymbolAddress((void**)&xres, g_xres);
    cudaGetSymbolAddress((void**)&wpm,  g_wpm);
    cudaGetSymbolAddress((void**)&b2,   g_b2);

    __nv_bfloat16 *qb,*kb,*vb;
    cudaGetSymbolAddress((void**)&qb, g_qb);
    cudaGetSymbolAddress((void**)&kb, g_kb);
    cudaGetSymbolAddress((void**)&vb, g_vb);

    __nv_bfloat16 *nxh,*nxl,*aoh,*aol,*knnh,*knnl,*l2h,*l2l,*hh,*hl;
    __nv_bfloat16 *wqh,*wql,*wprh,*wprl,*wkh,*wkl,*wmh,*wml,*wm2h,*wm2l;
    __nv_bfloat16 *wpmh,*wpml,*f1h,*f1l,*f2h,*f2l;
    cudaGetSymbolAddress((void**)&nxh, g_nxh);   cudaGetSymbolAddress((void**)&nxl, g_nxl);
    cudaGetSymbolAddress((void**)&aoh, g_aoh);   cudaGetSymbolAddress((void**)&aol, g_aol);
    cudaGetSymbolAddress((void**)&knnh,g_knnh);  cudaGetSymbolAddress((void**)&knnl,g_knnl);
    cudaGetSymbolAddress((void**)&l2h, g_l2h);   cudaGetSymbolAddress((void**)&l2l, g_l2l);
    cudaGetSymbolAddress((void**)&hh,  g_hh);    cudaGetSymbolAddress((void**)&hl,  g_hl);
    cudaGetSymbolAddress((void**)&wqh, g_wqkvh); cudaGetSymbolAddress((void**)&wql, g_wqkvl);
    cudaGetSymbolAddress((void**)&wprh,g_wprh);  cudaGetSymbolAddress((void**)&wprl,g_wprl);
    cudaGetSymbolAddress((void**)&wkh, g_wkh);   cudaGetSymbolAddress((void**)&wkl, g_wkl);
    cudaGetSymbolAddress((void**)&wmh, g_wmh);   cudaGetSymbolAddress((void**)&wml, g_wml);
    cudaGetSymbolAddress((void**)&wm2h,g_wm2h);  cudaGetSymbolAddress((void**)&wm2l,g_wm2l);
    cudaGetSymbolAddress((void**)&wpmh,g_wpmh);  cudaGetSymbolAddress((void**)&wpml,g_wpml);
    cudaGetSymbolAddress((void**)&f1h, g_f1h);   cudaGetSymbolAddress((void**)&f1l, g_f1l);
    cudaGetSymbolAddress((void**)&f2h, g_f2h);   cudaGetSymbolAddress((void**)&f2l, g_f2l);

    cudaFuncSetAttribute(tgemm<0,0,1>, cudaFuncAttributeMaxDynamicSharedMemorySize, SMEM_MM4);
    cudaFuncSetAttribute(tgemm<1,1,1>, cudaFuncAttributeMaxDynamicSharedMemorySize, SMEM_MM4);
    cudaFuncSetAttribute(tgemm<0,2,0>, cudaFuncAttributeMaxDynamicSharedMemorySize, SMEM_MM2);
    cudaFuncSetAttribute(attn_mma,     cudaFuncAttributeMaxDynamicSharedMemorySize, SMEM_AT);

    // streams/events created ONCE (first call = correctness run, so the
    // harness's pre-capture memory baseline already includes them; capture
    // and replay calls allocate nothing).
    static cudaStream_t sB = nullptr, sC = nullptr;
    static cudaEvent_t evFork, evQW, evLn, evWpm, evX1, evW2, evLn2, evDone;
    if (!sB) {
        cudaStreamCreateWithFlags(&sB, cudaStreamNonBlocking);
        cudaStreamCreateWithFlags(&sC, cudaStreamNonBlocking);
        cudaEventCreateWithFlags(&evFork, cudaEventDisableTiming);
        cudaEventCreateWithFlags(&evQW,   cudaEventDisableTiming);
        cudaEventCreateWithFlags(&evLn,   cudaEventDisableTiming);
        cudaEventCreateWithFlags(&evWpm,  cudaEventDisableTiming);
        cudaEventCreateWithFlags(&evX1,   cudaEventDisableTiming);
        cudaEventCreateWithFlags(&evW2,   cudaEventDisableTiming);
        cudaEventCreateWithFlags(&evLn2,  cudaEventDisableTiming);
        cudaEventCreateWithFlags(&evDone, cudaEventDisableTiming);
    }

    cudaEventRecord(evFork, 0);
    cudaStreamWaitEvent(sB, evFork, 0);
    cudaStreamWaitEvent(sC, evFork, 0);

    // #1: qkv weight split on sC (overlaps LN1)
    tsplit<<<1728, 256, 0, sC>>>(w_qkv, wqh, wql, 384, 1152);
    cudaEventRecord(evQW, sC);
    // #2: LN1 on main
    ln_kernel<<<MROWS, 128>>>(x, ln1_w, ln1_b, nxh, nxl);
    cudaEventRecord(evLn, 0);
    // #3,#4: kNN weight prep on sB
    tsplit_knn2<<<1152, 256, 0, sB>>>(w_knn, wkh, wkl);
    tsplit<<<576, 256, 0, sB>>>(w_merge + 384 * 384, wm2h, wm2l, 384, 384);
    // #5: w_merge transpose-split on sC (needed for Wpm)
    tsplit<<<1152, 256, 0, sC>>>(w_merge, wmh, wml, 768, 384);
    // #6: qkv GEMM on main (plain bf16, direct q/k/v layout) — ncu target
    cudaStreamWaitEvent(0, evQW, 0);
    tgemm<0,2,0><<<dim3(9, 128), 256, SMEM_MM2>>>(nxh, nullptr, wqh, nullptr,
        nullptr, nullptr, nullptr, nullptr, nullptr, qb, kb, vb,
        384, 384, 384, 0, 0);

    // sC: Wpm = w_proj@Wm1, bias2, then fc tsplits
    fsplit<<<576, 256, 0, sC>>>(w_proj, wprh, wprl, 384 * 384);
    tgemm<0,0,1><<<dim3(3, 3), 256, SMEM_MM4, sC>>>(wmh, wml, wprh, wprl,
        nullptr, nullptr, wpm, nullptr, nullptr, nullptr, nullptr, nullptr,
        384, 768, 384, 384, 0);
    fsplit<<<576, 256, 0, sC>>>(wpm, wpmh, wpml, 384 * 384);
    bias2_kernel<<<3, 128, 0, sC>>>(b_proj, w_merge, b_merge, b2);
    cudaEventRecord(evWpm, sC);
    tsplit<<<2304, 256, 0, sC>>>(w_fc1, f1h, f1l, 384, 768);
    tsplit<<<2304, 256, 0, sC>>>(w_fc2, f2h, f2l, 768, 384);
    cudaEventRecord(evW2, sC);

    // main: attention
    attn_mma<<<dim3(8, 96), 128, SMEM_AT>>>(qb, kb, vb, aoh, aol);

    // sB: kNN branch (full split) -> x1 = knn_f@Wm2 + bias2
    cudaStreamWaitEvent(sB, evLn, 0);
    tgemm<0,0,1><<<dim3(6, 128), 256, SMEM_MM4, sB>>>(nxh, nxl, wkh, wkl,
        nullptr, nullptr, AbCc, nullptr, nullptr, nullptr, nullptr, nullptr,
        384, 384, 384, 768, 0);
    knn_kernel<<<MROWS, 128, 0, sB>>>(AbCc, knn, b_knn, knnh, knnl);
    cudaStreamWaitEvent(sB, evWpm, 0);
    tgemm<0,0,1><<<dim3(3, 128), 256, SMEM_MM4, sB>>>(knnh, knnl, wm2h, wm2l,
        b2, nullptr, x1, nullptr, nullptr, nullptr, nullptr, nullptr,
        384, 384, 384, 384, 0);
    cudaEventRecord(evX1, sB);

    // main: x2 = x + ao@Wpm
    cudaStreamWaitEvent(0, evWpm, 0);
    tgemm<0,0,1><<<dim3(3, 128), 256, SMEM_MM4>>>(aoh, aol, wpmh, wpml,
        nullptr, x, x2, nullptr, nullptr, nullptr, nullptr, nullptr,
        384, 384, 384, 384, 384);

    // join: ln2(x1+x2)
    cudaStreamWaitEvent(0, evX1, 0);
    ln2sum_kernel<<<MROWS, 128>>>(x1, x2, ln2_w, ln2_b, xres, l2h, l2l);
    cudaEventRecord(evLn2, 0);

    // MLP pipelined by M-halves: main does rows [0,8192), sB does [8192,16384)
    const size_t HM = 8192;
    cudaStreamWaitEvent(0, evW2, 0);
    tgemm<1,1,1><<<dim3(6, 64), 256, SMEM_MM4>>>(l2h, l2l, f1h, f1l,
        b_fc1, nullptr, nullptr, hh, hl, nullptr, nullptr, nullptr,
        384, 384, 384, 768, 0);
    cudaStreamWaitEvent(sB, evLn2, 0);
    cudaStreamWaitEvent(sB, evW2, 0);
    tgemm<1,1,1><<<dim3(6, 64), 256, SMEM_MM4, sB>>>(l2h + HM * 384, l2l + HM * 384,
        f1h, f1l, b_fc1, nullptr, nullptr, hh + HM * 768, hl + HM * 768,
        nullptr, nullptr, nullptr, 384, 384, 384, 768, 0);
    tgemm<0,0,1><<<dim3(3, 64), 256, SMEM_MM4>>>(hh, hl, f2h, f2l,
        b_fc2, xres, out, nullptr, nullptr, nullptr, nullptr, nullptr,
        768, 768, 768, 384, 384);
    tgemm<0,0,1><<<dim3(3, 64), 256, SMEM_MM4, sB>>>(hh + HM * 768, hl + HM * 768,
        f2h, f2l, b_fc2, xres + HM * 384, out + HM * 384,
        nullptr, nullptr, nullptr, nullptr, nullptr, 768, 768, 768, 384, 384);
    cudaEventRecord(evDone, sB);
    cudaStreamWaitEvent(0, evDone, 0);
}

// round 13
// speedup vs baseline: 1.0972x; 1.0292x over previous
#include <cuda_runtime.h>
#include <cuda_bf16.h>
#include <math.h>
#include <stdint.h>

// ---------------------------------------------------------------------------
// PCTransformer block, GB300 (sm_103a, compute_103 baseline PTX)
// B=16, N=1024, C=384, H=6, HD=64, K=8, HID=768, M=B*N=16384
// Merge GEMM folded away: x1 = knn_f@Wm2 + bias2 ; x2 = x + ao@(w_proj@Wm1).
// qkv GEMM + attention pipelined by batch halves across streams.
// Dense GEMMs: merged-K bf16 HMMA; nosplit path = 3-stage 1-sync pipeline.
// ---------------------------------------------------------------------------

#define MROWS 16384

// ---------------- scratch (static device globals; no allocation) -----------
__device__ float g_AbCc[MROWS * 768];
__device__ float g_x1  [MROWS * 384];
__device__ float g_x2  [MROWS * 384];
__device__ float g_xres[MROWS * 384];
__device__ float g_wpm [384 * 384];
__device__ float g_b2  [384];

__device__ __align__(16) __nv_bfloat16 g_qb[96*1024*64];
__device__ __align__(16) __nv_bfloat16 g_kb[96*1024*64];
__device__ __align__(16) __nv_bfloat16 g_vb[96*1024*64];

__device__ __align__(16) __nv_bfloat16 g_nxh[MROWS*384],  g_nxl[MROWS*384];
__device__ __align__(16) __nv_bfloat16 g_aoh[MROWS*384],  g_aol[MROWS*384];
__device__ __align__(16) __nv_bfloat16 g_knnh[MROWS*384], g_knnl[MROWS*384];
__device__ __align__(16) __nv_bfloat16 g_l2h[MROWS*384],  g_l2l[MROWS*384];
__device__ __align__(16) __nv_bfloat16 g_hh[MROWS*768],   g_hl[MROWS*768];

__device__ __align__(16) __nv_bfloat16 g_wqkvh[1152*384], g_wqkvl[1152*384];
__device__ __align__(16) __nv_bfloat16 g_wprh[384*384],   g_wprl[384*384];
__device__ __align__(16) __nv_bfloat16 g_wkh[768*384],    g_wkl[768*384];
__device__ __align__(16) __nv_bfloat16 g_wmh[384*768],    g_wml[384*768];
__device__ __align__(16) __nv_bfloat16 g_wm2h[384*384],   g_wm2l[384*384];
__device__ __align__(16) __nv_bfloat16 g_wpmh[384*384],   g_wpml[384*384];
__device__ __align__(16) __nv_bfloat16 g_f1h[768*384],    g_f1l[768*384];
__device__ __align__(16) __nv_bfloat16 g_f2h[384*768],    g_f2l[384*768];

// ---------------- PTX helpers ----------------------------------------------
__device__ __forceinline__ uint32_t smem_u32(const void* p) {
    uint32_t a;
    asm("{ .reg .u64 t; cvta.to.shared.u64 t, %1; cvt.u32.u64 %0, t; }"
        : "=r"(a) : "l"(p));
    return a;
}
__device__ __forceinline__ void ldsm_x4(uint32_t addr, uint32_t* r) {
    asm volatile("ldmatrix.sync.aligned.m8n8.x4.shared.b16 {%0,%1,%2,%3}, [%4];"
                 : "=r"(r[0]), "=r"(r[1]), "=r"(r[2]), "=r"(r[3]) : "r"(addr));
}
__device__ __forceinline__ void ldsm_x4t(uint32_t addr, uint32_t* r) {
    asm volatile("ldmatrix.sync.aligned.m8n8.x4.trans.shared.b16 {%0,%1,%2,%3}, [%4];"
                 : "=r"(r[0]), "=r"(r[1]), "=r"(r[2]), "=r"(r[3]) : "r"(addr));
}
__device__ __forceinline__ void mma_bf16(float* c, const uint32_t* a,
                                         uint32_t b0, uint32_t b1) {
    asm volatile(
        "mma.sync.aligned.m16n8k16.row.col.f32.bf16.bf16.f32 "
        "{%0,%1,%2,%3},{%4,%5,%6,%7},{%8,%9},{%0,%1,%2,%3};"
        : "+f"(c[0]), "+f"(c[1]), "+f"(c[2]), "+f"(c[3])
        : "r"(a[0]), "r"(a[1]), "r"(a[2]), "r"(a[3]), "r"(b0), "r"(b1));
}
__device__ __forceinline__ void cp16(uint32_t dst, const void* src) {
    asm volatile("cp.async.cg.shared.global [%0], [%1], 16;"
                 :: "r"(dst), "l"(src) : "memory");
}
#define CP_COMMIT() asm volatile("cp.async.commit_group;" ::: "memory")
#define CP_WAIT(n)  asm volatile("cp.async.wait_group %0;" :: "n"(n) : "memory")

__device__ __forceinline__ uint32_t bf2pk(float lo, float hi) {
    uint32_t r;
    asm("cvt.rn.bf16x2.f32 %0, %1, %2;" : "=r"(r) : "f"(hi), "f"(lo));
    return r;
}

__device__ __forceinline__ void split_store(__nv_bfloat16* H, __nv_bfloat16* L,
                                            size_t idx, float x, float y) {
    __nv_bfloat16 hx = __float2bfloat16_rn(x);
    __nv_bfloat16 hy = __float2bfloat16_rn(y);
    *(__nv_bfloat162*)&H[idx] = __nv_bfloat162(hx, hy);
    *(__nv_bfloat162*)&L[idx] =
        __nv_bfloat162(__float2bfloat16_rn(x - __bfloat162float(hx)),
                       __float2bfloat16_rn(y - __bfloat162float(hy)));
}

__device__ __forceinline__ void qkv_store(__nv_bfloat16* qp, __nv_bfloat16* kp,
                                          __nv_bfloat16* vp, int token, int col,
                                          float x, float y) {
    int bb = token >> 10, n = token & 1023;
    int which = col / 384;
    int rem = col - which * 384;
    int h = rem >> 6, d = rem & 63;
    size_t di = ((size_t)(bb * 6 + h) * 1024 + n) * 64 + d;
    float sc = (which == 0) ? 0.125f : 1.0f;
    __nv_bfloat16* dst = (which == 0) ? qp : ((which == 1) ? kp : vp);
    *(__nv_bfloat162*)&dst[di] =
        __nv_bfloat162(__float2bfloat16_rn(x * sc), __float2bfloat16_rn(y * sc));
}

// ---------------- LayerNorm (writes bf16 split) ----------------------------
__global__ void ln_kernel(const float* __restrict__ x,
                          const float* __restrict__ w,
                          const float* __restrict__ b,
                          __nv_bfloat16* __restrict__ H,
                          __nv_bfloat16* __restrict__ L) {
    int row = blockIdx.x, tid = threadIdx.x;
    const float* xr = x + (size_t)row * 384;
    float v0 = xr[tid], v1 = xr[tid + 128], v2 = xr[tid + 256];
    float s  = v0 + v1 + v2;
    float sq = v0 * v0 + v1 * v1 + v2 * v2;
    #pragma unroll
    for (int o = 16; o; o >>= 1) {
        s  += __shfl_xor_sync(0xffffffffu, s,  o);
        sq += __shfl_xor_sync(0xffffffffu, sq, o);
    }
    __shared__ float ss[4], sqs[4];
    int wid = tid >> 5, lid = tid & 31;
    if (lid == 0) { ss[wid] = s; sqs[wid] = sq; }
    __syncthreads();
    s  = ss[0] + ss[1] + ss[2] + ss[3];
    sq = sqs[0] + sqs[1] + sqs[2] + sqs[3];
    float mean = s * (1.0f / 384.0f);
    float var  = sq * (1.0f / 384.0f) - mean * mean;
    float inv  = rsqrtf(var + 1e-5f);
    size_t base = (size_t)row * 384;
    #pragma unroll
    for (int cc = 0; cc < 3; cc++) {
        int c = tid + cc * 128;
        float v = (cc == 0 ? v0 : (cc == 1 ? v1 : v2));
        float y = (v - mean) * inv * w[c] + b[c];
        __nv_bfloat16 h = __float2bfloat16_rn(y);
        H[base + c] = h;
        L[base + c] = __float2bfloat16_rn(y - __bfloat162float(h));
    }
}

__global__ void ln2sum_kernel(const float* __restrict__ x1,
                              const float* __restrict__ x2,
                              const float* __restrict__ w,
                              const float* __restrict__ b,
                              float* __restrict__ xres,
                              __nv_bfloat16* __restrict__ H,
                              __nv_bfloat16* __restrict__ L) {
    int row = blockIdx.x, tid = threadIdx.x;
    size_t base = (size_t)row * 384;
    float v0 = x1[base + tid]       + x2[base + tid];
    float v1 = x1[base + tid + 128] + x2[base + tid + 128];
    float v2 = x1[base + tid + 256] + x2[base + tid + 256];
    xres[base + tid]       = v0;
    xres[base + tid + 128] = v1;
    xres[base + tid + 256] = v2;
    float s  = v0 + v1 + v2;
    float sq = v0 * v0 + v1 * v1 + v2 * v2;
    #pragma unroll
    for (int o = 16; o; o >>= 1) {
        s  += __shfl_xor_sync(0xffffffffu, s,  o);
        sq += __shfl_xor_sync(0xffffffffu, sq, o);
    }
    __shared__ float ss[4], sqs[4];
    int wid = tid >> 5, lid = tid & 31;
    if (lid == 0) { ss[wid] = s; sqs[wid] = sq; }
    __syncthreads();
    s  = ss[0] + ss[1] + ss[2] + ss[3];
    sq = sqs[0] + sqs[1] + sqs[2] + sqs[3];
    float mean = s * (1.0f / 384.0f);
    float var  = sq * (1.0f / 384.0f) - mean * mean;
    float inv  = rsqrtf(var + 1e-5f);
    #pragma unroll
    for (int cc = 0; cc < 3; cc++) {
        int c = tid + cc * 128;
        float v = (cc == 0 ? v0 : (cc == 1 ? v1 : v2));
        float y = (v - mean) * inv * w[c] + b[c];
        __nv_bfloat16 h = __float2bfloat16_rn(y);
        H[base + c] = h;
        L[base + c] = __float2bfloat16_rn(y - __bfloat162float(h));
    }
}

__device__ __forceinline__ float gelu_exact(float v) {
    return 0.5f * v * (1.0f + erff(v * 0.70710678118654752f));
}

// ---------------- weight prep kernels --------------------------------------
__global__ void tsplit(const float* __restrict__ W,
                       __nv_bfloat16* __restrict__ Th,
                       __nv_bfloat16* __restrict__ Tl, int K, int N) {
    int idx = blockIdx.x * 256 + threadIdx.x;
    if (idx >= K * N) return;
    int n = idx / K, k = idx - n * K;
    float v = W[(size_t)k * N + n];
    __nv_bfloat16 h = __float2bfloat16_rn(v);
    Th[idx] = h;
    Tl[idx] = __float2bfloat16_rn(v - __bfloat162float(h));
}

__global__ void fsplit(const float* __restrict__ W,
                       __nv_bfloat16* __restrict__ Th,
                       __nv_bfloat16* __restrict__ Tl, int n) {
    int idx = blockIdx.x * 256 + threadIdx.x;
    if (idx >= n) return;
    float v = W[idx];
    __nv_bfloat16 h = __float2bfloat16_rn(v);
    Th[idx] = h;
    Tl[idx] = __float2bfloat16_rn(v - __bfloat162float(h));
}

__global__ void tsplit_knn2(const float* __restrict__ W,
                            __nv_bfloat16* __restrict__ Th,
                            __nv_bfloat16* __restrict__ Tl) {
    int idx = blockIdx.x * 256 + threadIdx.x;
    if (idx >= 768 * 384) return;
    int np = idx / 384, k = idx - np * 384;
    float v;
    if (np < 384) {
        v = W[(size_t)k * 384 + np];
    } else {
        int n = np - 384;
        v = W[(size_t)(384 + k) * 384 + n] - W[(size_t)k * 384 + n];
    }
    __nv_bfloat16 h = __float2bfloat16_rn(v);
    Th[idx] = h;
    Tl[idx] = __float2bfloat16_rn(v - __bfloat162float(h));
}

__global__ void bias2_kernel(const float* __restrict__ bp,
                             const float* __restrict__ wm,
                             const float* __restrict__ bm,
                             float* __restrict__ out) {
    int n = blockIdx.x * 128 + threadIdx.x;
    if (n >= 384) return;
    float s = 0.0f;
    for (int j = 0; j < 384; j++) s += bp[j] * wm[(size_t)j * 384 + n];
    out[n] = s + bm[n];
}

// ---------------- HMMA GEMM ------------------------------------------------
// SPLITIN=1: 2-stage/2-sync, 4 tiles/stage, acc += AhBh+AhBl+AlBh.
// SPLITIN=0: 3-stage/1-sync, 2 tiles/stage, acc += AhBh.
// OMODE: 0 = fp32 C, 1 = split bf16 Ho/Lo, 2 = qkv direct (ldc = token offset)
#define ROWB    80
#define TILE_B  (128 * ROWB)
#define SMEM_MM4 (2 * 4 * TILE_B)   // 81920 (split, 2-stage)
#define SMEM_MM2 (3 * 2 * TILE_B)   // 61440 (nosplit, 3-stage)

template <int GELU, int OMODE, int SPLITIN>
__global__ void __launch_bounds__(256, 2) tgemm(
    const __nv_bfloat16* __restrict__ Ah, const __nv_bfloat16* __restrict__ Al,
    const __nv_bfloat16* __restrict__ Bh, const __nv_bfloat16* __restrict__ Bl,
    const float* __restrict__ bias, const float* __restrict__ res,
    float* __restrict__ C, __nv_bfloat16* __restrict__ Ho,
    __nv_bfloat16* __restrict__ Lo,
    __nv_bfloat16* __restrict__ qp, __nv_bfloat16* __restrict__ kp,
    __nv_bfloat16* __restrict__ vp,
    int K, int lda, int ldb, int ldc, int ldres) {
    extern __shared__ char smem[];
    uint32_t sb = smem_u32(smem);
    int tid = threadIdx.x, lid = tid & 31, w = tid >> 5;
    int wm = w & 1, wn = w >> 1;
    int m0 = blockIdx.y * 128, n0 = blockIdx.x * 128;
    const int NIT = K >> 5;
    constexpr int NT = SPLITIN ? 4 : 2;
    constexpr uint32_t STG_B = NT * TILE_B;
    constexpr uint32_t BOFF  = (SPLITIN ? 2 : 1) * TILE_B;

    float acc[4][4][4];
    #pragma unroll
    for (int i = 0; i < 4; i++)
        #pragma unroll
        for (int j = 0; j < 4; j++)
            #pragma unroll
            for (int q = 0; q < 4; q++) acc[i][j][q] = 0.0f;

    int c0 = tid * 2;
    int lr0 = c0 >> 2,       lq0 = c0 & 3;
    int lr1 = (c0 + 1) >> 2, lq1 = (c0 + 1) & 3;

    auto load_stage = [&](int kc, int s) {
        const __nv_bfloat16* Ag = Ah + (size_t)m0 * lda + kc * 32;
        const __nv_bfloat16* Bg = Bh + (size_t)n0 * ldb + kc * 32;
        uint32_t st = sb + s * STG_B;
        uint32_t d0 = lr0 * ROWB + lq0 * 16, d1 = lr1 * ROWB + lq1 * 16;
        size_t a0 = (size_t)lr0 * lda + lq0 * 8, a1 = (size_t)lr1 * lda + lq1 * 8;
        size_t b0 = (size_t)lr0 * ldb + lq0 * 8, b1 = (size_t)lr1 * ldb + lq1 * 8;
        cp16(st + d0,        Ag + a0);
        cp16(st + d1,        Ag + a1);
        cp16(st + BOFF + d0, Bg + b0);
        cp16(st + BOFF + d1, Bg + b1);
        if (SPLITIN) {
            const __nv_bfloat16* Ag2 = Al + (size_t)m0 * lda + kc * 32;
            const __nv_bfloat16* Bg2 = Bl + (size_t)n0 * ldb + kc * 32;
            cp16(st + TILE_B + d0,     Ag2 + a0);
            cp16(st + TILE_B + d1,     Ag2 + a1);
            cp16(st + 3 * TILE_B + d0, Bg2 + b0);
            cp16(st + 3 * TILE_B + d1, Bg2 + b1);
        }
    };

    int rA = lid & 15, hA = lid >> 4;
    int rB = (lid & 7) + ((lid >> 4) << 3), hB = (lid >> 3) & 1;

    auto compute_stage = [&](int s) {
        uint32_t sAh = sb + s * STG_B + (wm * 64) * ROWB;
        uint32_t sBh = sb + s * STG_B + BOFF + (wn * 32) * ROWB;
        #pragma unroll
        for (int ks = 0; ks < 2; ks++) {
            int kk = ks * 16;
            uint32_t a[4][4];
            #pragma unroll
            for (int i = 0; i < 4; i++)
                ldsm_x4(sAh + (i * 16 + rA) * ROWB + (kk + hA * 8) * 2, a[i]);
            uint32_t bh[2][4];
            #pragma unroll
            for (int jj = 0; jj < 2; jj++)
                ldsm_x4(sBh + (jj * 16 + rB) * ROWB + (kk + hB * 8) * 2, bh[jj]);
            #pragma unroll
            for (int i = 0; i < 4; i++)
                #pragma unroll
                for (int j = 0; j < 4; j++)
                    mma_bf16(acc[i][j], a[i], bh[j >> 1][(j & 1) * 2],
                             bh[j >> 1][(j & 1) * 2 + 1]);
            if (SPLITIN) {
                uint32_t sAl = sAh + TILE_B;
                uint32_t sBl = sBh + TILE_B;
                uint32_t bl[2][4];
                #pragma unroll
                for (int jj = 0; jj < 2; jj++)
                    ldsm_x4(sBl + (jj * 16 + rB) * ROWB + (kk + hB * 8) * 2, bl[jj]);
                #pragma unroll
                for (int i = 0; i < 4; i++)
                    #pragma unroll
                    for (int j = 0; j < 4; j++)
                        mma_bf16(acc[i][j], a[i], bl[j >> 1][(j & 1) * 2],
                                 bl[j >> 1][(j & 1) * 2 + 1]);
                uint32_t al[4][4];
                #pragma unroll
                for (int i = 0; i < 4; i++)
                    ldsm_x4(sAl + (i * 16 + rA) * ROWB + (kk + hA * 8) * 2, al[i]);
                #pragma unroll
                for (int i = 0; i < 4; i++)
                    #pragma unroll
                    for (int j = 0; j < 4; j++)
                        mma_bf16(acc[i][j], al[i], bh[j >> 1][(j & 1) * 2],
                                 bh[j >> 1][(j & 1) * 2 + 1]);
            }
        }
    };

    if (SPLITIN) {
        // 2-stage, 2 syncs per iter (validated shape)
        load_stage(0, 0); CP_COMMIT();
        for (int it = 0; it < NIT; ++it) {
            if (it + 1 < NIT) { load_stage(it + 1, (it + 1) & 1); CP_COMMIT(); }
            if (it + 1 < NIT) CP_WAIT(1); else CP_WAIT(0);
            __syncthreads();
            compute_stage(it & 1);
            __syncthreads();
        }
    } else {
        // 3-stage, single sync per iter
        load_stage(0, 0); CP_COMMIT();
        if (NIT > 1) { load_stage(1, 1); CP_COMMIT(); }
        for (int it = 0; it < NIT; ++it) {
            if (it == NIT - 1) { CP_WAIT(0); } else { CP_WAIT(1); }
            __syncthreads();
            compute_stage(it % 3);
            if (it + 2 < NIT) { load_stage(it + 2, (it + 2) % 3); CP_COMMIT(); }
        }
    }

    #pragma unroll
    for (int i = 0; i < 4; i++) {
        int r0 = m0 + wm * 64 + i * 16 + (lid >> 2);
        int r1 = r0 + 8;
        #pragma unroll
        for (int j = 0; j < 4; j++) {
            int col = n0 + wn * 32 + j * 8 + (lid & 3) * 2;
            float2 v0 = make_float2(acc[i][j][0], acc[i][j][1]);
            float2 v1 = make_float2(acc[i][j][2], acc[i][j][3]);
            if (bias) {
                float2 bb = *(const float2*)&bias[col];
                v0.x += bb.x; v0.y += bb.y; v1.x += bb.x; v1.y += bb.y;
            }
            if (GELU) {
                v0.x = gelu_exact(v0.x); v0.y = gelu_exact(v0.y);
                v1.x = gelu_exact(v1.x); v1.y = gelu_exact(v1.y);
            }
            if (res) {
                float2 q0 = *(const float2*)&res[(size_t)r0 * ldres + col];
                float2 q1 = *(const float2*)&res[(size_t)r1 * ldres + col];
                v0.x += q0.x; v0.y += q0.y; v1.x += q1.x; v1.y += q1.y;
            }
            if (OMODE == 2) {   // ldc = global token offset of row 0
                qkv_store(qp, kp, vp, r0 + ldc, col, v0.x, v0.y);
                qkv_store(qp, kp, vp, r1 + ldc, col, v1.x, v1.y);
            } else if (OMODE == 1) {
                split_store(Ho, Lo, (size_t)r0 * ldc + col, v0.x, v0.y);
                split_store(Ho, Lo, (size_t)r1 * ldc + col, v1.x, v1.y);
            } else {
                *(float2*)&C[(size_t)r0 * ldc + col] = v0;
                *(float2*)&C[(size_t)r1 * ldc + col] = v1;
            }
        }
    }
}

// ---------------- HMMA flash attention (poff = plane offset) ---------------
#define AT_STB  144
#define SQ_OFF  0
#define SK0_OFF (128 * AT_STB)
#define SV0_OFF (SK0_OFF + 64 * AT_STB)
#define SK1_OFF (SV0_OFF + 64 * AT_STB)
#define SV1_OFF (SK1_OFF + 64 * AT_STB)
#define SMEM_AT (SV1_OFF + 64 * AT_STB)

__global__ void __launch_bounds__(128) attn_mma(
    const __nv_bfloat16* __restrict__ qb,
    const __nv_bfloat16* __restrict__ kb,
    const __nv_bfloat16* __restrict__ vb,
    __nv_bfloat16* __restrict__ Ho, __nv_bfloat16* __restrict__ Lo,
    int poff) {
    extern __shared__ char smem[];
    uint32_t sb = smem_u32(smem);
    int tid = threadIdx.x, lid = tid & 31, wid = tid >> 5;
    int p = blockIdx.y + poff, q0 = blockIdx.x * 128;
    int b = p / 6, h = p - b * 6;
    const __nv_bfloat16* Qg = qb + ((size_t)p * 1024 + q0) * 64;
    const __nv_bfloat16* Kg = kb + (size_t)p * 1024 * 64;
    const __nv_bfloat16* Vg = vb + (size_t)p * 1024 * 64;

    #pragma unroll
    for (int i = 0; i < 8; i++) {
        int u = i * 128 + tid, r = u >> 3, c = u & 7;
        cp16(sb + SQ_OFF + r * AT_STB + c * 16, Qg + (size_t)r * 64 + c * 8);
    }
    #pragma unroll
    for (int i = 0; i < 4; i++) {
        int u = i * 128 + tid, r = u >> 3, c = u & 7;
        cp16(sb + SK0_OFF + r * AT_STB + c * 16, Kg + (size_t)r * 64 + c * 8);
        cp16(sb + SV0_OFF + r * AT_STB + c * 16, Vg + (size_t)r * 64 + c * 8);
    }
    CP_COMMIT();
    CP_WAIT(0);
    __syncthreads();

    int rA = lid & 15, hA = lid >> 4;
    uint32_t qf[2][4][4];
    #pragma unroll
    for (int mi = 0; mi < 2; mi++)
        #pragma unroll
        for (int kk = 0; kk < 4; kk++)
            ldsm_x4(sb + SQ_OFF + (wid * 32 + mi * 16 + rA) * AT_STB
                       + (kk * 16 + hA * 8) * 2, qf[mi][kk]);

    float o[2][8][4];
    #pragma unroll
    for (int mi = 0; mi < 2; mi++)
        #pragma unroll
        for (int j = 0; j < 8; j++)
            #pragma unroll
            for (int q = 0; q < 4; q++) o[mi][j][q] = 0.0f;
    float lsum[2][2] = {{0.0f, 0.0f}, {0.0f, 0.0f}};

    int rB = (lid & 7) + ((lid >> 4) << 3), hB = (lid >> 3) & 1;
    int tv = lid & 7, v8 = (lid >> 3) & 1, v16 = (lid >> 4) & 1;

    for (int kt = 0; kt < 16; kt++) {
        int buf = kt & 1;
        __syncthreads();
        if (kt + 1 < 16) {
            const __nv_bfloat16* Kn = Kg + (size_t)(kt + 1) * 64 * 64;
            const __nv_bfloat16* Vn = Vg + (size_t)(kt + 1) * 64 * 64;
            uint32_t dK = sb + (buf ? SK0_OFF : SK1_OFF);
            uint32_t dV = sb + (buf ? SV0_OFF : SV1_OFF);
            #pragma unroll
            for (int i = 0; i < 4; i++) {
                int u = i * 128 + tid, r = u >> 3, c = u & 7;
                cp16(dK + r * AT_STB + c * 16, Kn + (size_t)r * 64 + c * 8);
                cp16(dV + r * AT_STB + c * 16, Vn + (size_t)r * 64 + c * 8);
            }
        }
        CP_COMMIT();
        CP_WAIT(1);
        __syncthreads();
        uint32_t sK = sb + (buf ? SK1_OFF : SK0_OFF);
        uint32_t sV = sb + (buf ? SV1_OFF : SV0_OFF);

        float sacc[2][8][4];
        #pragma unroll
        for (int mi = 0; mi < 2; mi++)
            #pragma unroll
            for (int j = 0; j < 8; j++)
                #pragma unroll
                for (int q = 0; q < 4; q++) sacc[mi][j][q] = 0.0f;
        #pragma unroll
        for (int kk = 0; kk < 4; kk++) {
            uint32_t bfm[4][4];
            #pragma unroll
            for (int jj = 0; jj < 4; jj++)
                ldsm_x4(sK + (jj * 16 + rB) * AT_STB + (kk * 16 + hB * 8) * 2,
                        bfm[jj]);
            #pragma unroll
            for (int mi = 0; mi < 2; mi++)
                #pragma unroll
                for (int jj = 0; jj < 4; jj++) {
                    mma_bf16(sacc[mi][2 * jj],     qf[mi][kk], bfm[jj][0], bfm[jj][1]);
                    mma_bf16(sacc[mi][2 * jj + 1], qf[mi][kk], bfm[jj][2], bfm[jj][3]);
                }
        }
        #pragma unroll
        for (int mi = 0; mi < 2; mi++)
            #pragma unroll
            for (int j = 0; j < 8; j++) {
                sacc[mi][j][0] = __expf(sacc[mi][j][0]);
                sacc[mi][j][1] = __expf(sacc[mi][j][1]);
                sacc[mi][j][2] = __expf(sacc[mi][j][2]);
                sacc[mi][j][3] = __expf(sacc[mi][j][3]);
                lsum[mi][0] += sacc[mi][j][0] + sacc[mi][j][1];
                lsum[mi][1] += sacc[mi][j][2] + sacc[mi][j][3];
            }
        #pragma unroll
        for (int kk = 0; kk < 4; kk++) {
            uint32_t vf[4][4];
            #pragma unroll
            for (int jj = 0; jj < 4; jj++)
                ldsm_x4t(sV + (kk * 16 + v8 * 8 + tv) * AT_STB
                            + (jj * 16 + v16 * 8) * 2, vf[jj]);
            #pragma unroll
            for (int mi = 0; mi < 2; mi++) {
                uint32_t pa[4];
                pa[0] = bf2pk(sacc[mi][2 * kk][0],     sacc[mi][2 * kk][1]);
                pa[1] = bf2pk(sacc[mi][2 * kk][2],     sacc[mi][2 * kk][3]);
                pa[2] = bf2pk(sacc[mi][2 * kk + 1][0], sacc[mi][2 * kk + 1][1]);
                pa[3] = bf2pk(sacc[mi][2 * kk + 1][2], sacc[mi][2 * kk + 1][3]);
                #pragma unroll
                for (int jj = 0; jj < 4; jj++) {
                    mma_bf16(o[mi][2 * jj],     pa, vf[jj][0], vf[jj][1]);
                    mma_bf16(o[mi][2 * jj + 1], pa, vf[jj][2], vf[jj][3]);
                }
            }
        }
    }

    #pragma unroll
    for (int mi = 0; mi < 2; mi++)
        #pragma unroll
        for (int rr = 0; rr < 2; rr++) {
            lsum[mi][rr] += __shfl_xor_sync(0xffffffffu, lsum[mi][rr], 1);
            lsum[mi][rr] += __shfl_xor_sync(0xffffffffu, lsum[mi][rr], 2);
        }

    #pragma unroll
    for (int mi = 0; mi < 2; mi++) {
        float inv0 = 1.0f / lsum[mi][0];
        float inv1 = 1.0f / lsum[mi][1];
        int r0 = q0 + wid * 32 + mi * 16 + (lid >> 2);
        size_t row0 = ((size_t)b * 1024 + r0) * 384 + h * 64;
        size_t row1 = row0 + (size_t)8 * 384;
        #pragma unroll
        for (int j = 0; j < 8; j++) {
            int col = j * 8 + (lid & 3) * 2;
            split_store(Ho, Lo, row0 + col, o[mi][j][0] * inv0, o[mi][j][1] * inv0);
            split_store(Ho, Lo, row1 + col, o[mi][j][2] * inv1, o[mi][j][3] * inv1);
        }
    }
}

// ---------------- kNN gather + leaky_relu + max -> split [M,384] -----------
__global__ void knn_kernel(const float* __restrict__ AbCc,
                           const int* __restrict__ knn,
                           const float* __restrict__ bknn,
                           __nv_bfloat16* __restrict__ Ho,
                           __nv_bfloat16* __restrict__ Lo) {
    int row = blockIdx.x;
    int b = row >> 10, n = row & 1023;
    __shared__ int idxs[8];
    if (threadIdx.x < 8) idxs[threadIdx.x] = knn[((b << 3) + threadIdx.x) * 1024 + n];
    __syncthreads();
    #pragma unroll
    for (int cc = 0; cc < 3; cc++) {
        int c = threadIdx.x + cc * 128;
        float base = AbCc[(size_t)row * 768 + 384 + c] + bknn[c];
        float mx = -3.0e38f;
        #pragma unroll
        for (int k = 0; k < 8; k++) {
            float v = __ldg(&AbCc[(size_t)idxs[k] * 768 + c]) + base;
            v = (v > 0.0f) ? v : 0.2f * v;
            mx = fmaxf(mx, v);
        }
        size_t oi = (size_t)row * 384 + c;
        __nv_bfloat16 hb = __float2bfloat16_rn(mx);
        Ho[oi] = hb;
        Lo[oi] = __float2bfloat16_rn(mx - __bfloat162float(hb));
    }
}

// ---------------------------------------------------------------------------
extern "C" void kernel_launch(void* const* d_in, const int* in_sizes, int n_in,
                              void* d_out, int out_size) {
    (void)in_sizes; (void)n_in; (void)out_size;
    const float* x       = (const float*)d_in[0];
    const int*   knn     = (const int*)  d_in[1];
    const float* ln1_w   = (const float*)d_in[2];
    const float* ln1_b   = (const float*)d_in[3];
    const float* w_qkv   = (const float*)d_in[4];
    const float* w_proj  = (const float*)d_in[5];
    const float* b_proj  = (const float*)d_in[6];
    const float* w_knn   = (const float*)d_in[7];
    const float* b_knn   = (const float*)d_in[8];
    const float* w_merge = (const float*)d_in[9];
    const float* b_merge = (const float*)d_in[10];
    const float* ln2_w   = (const float*)d_in[11];
    const float* ln2_b   = (const float*)d_in[12];
    const float* w_fc1   = (const float*)d_in[13];
    const float* b_fc1   = (const float*)d_in[14];
    const float* w_fc2   = (const float*)d_in[15];
    const float* b_fc2   = (const float*)d_in[16];
    float* out = (float*)d_out;

    float *AbCc, *x1, *x2, *xres, *wpm, *b2;
    cudaGetSymbolAddress((void**)&AbCc, g_AbCc);
    cudaGetSymbolAddress((void**)&x1,   g_x1);
    cudaGetSymbolAddress((void**)&x2,   g_x2);
    cudaGetSymbolAddress((void**)&xres, g_xres);
    cudaGetSymbolAddress((void**)&wpm,  g_wpm);
    cudaGetSymbolAddress((void**)&b2,   g_b2);

    __nv_bfloat16 *qb,*kb,*vb;
    cudaGetSymbolAddress((void**)&qb, g_qb);
    cudaGetSymbolAddress((void**)&kb, g_kb);
    cudaGetSymbolAddress((void**)&vb, g_vb);

    __nv_bfloat16 *nxh,*nxl,*aoh,*aol,*knnh,*knnl,*l2h,*l2l,*hh,*hl;
    __nv_bfloat16 *wqh,*wql,*wprh,*wprl,*wkh,*wkl,*wmh,*wml,*wm2h,*wm2l;
    __nv_bfloat16 *wpmh,*wpml,*f1h,*f1l,*f2h,*f2l;
    cudaGetSymbolAddress((void**)&nxh, g_nxh);   cudaGetSymbolAddress((void**)&nxl, g_nxl);
    cudaGetSymbolAddress((void**)&aoh, g_aoh);   cudaGetSymbolAddress((void**)&aol, g_aol);
    cudaGetSymbolAddress((void**)&knnh,g_knnh);  cudaGetSymbolAddress((void**)&knnl,g_knnl);
    cudaGetSymbolAddress((void**)&l2h, g_l2h);   cudaGetSymbolAddress((void**)&l2l, g_l2l);
    cudaGetSymbolAddress((void**)&hh,  g_hh);    cudaGetSymbolAddress((void**)&hl,  g_hl);
    cudaGetSymbolAddress((void**)&wqh, g_wqkvh); cudaGetSymbolAddress((void**)&wql, g_wqkvl);
    cudaGetSymbolAddress((void**)&wprh,g_wprh);  cudaGetSymbolAddress((void**)&wprl,g_wprl);
    cudaGetSymbolAddress((void**)&wkh, g_wkh);   cudaGetSymbolAddress((void**)&wkl, g_wkl);
    cudaGetSymbolAddress((void**)&wmh, g_wmh);   cudaGetSymbolAddress((void**)&wml, g_wml);
    cudaGetSymbolAddress((void**)&wm2h,g_wm2h);  cudaGetSymbolAddress((void**)&wm2l,g_wm2l);
    cudaGetSymbolAddress((void**)&wpmh,g_wpmh);  cudaGetSymbolAddress((void**)&wpml,g_wpml);
    cudaGetSymbolAddress((void**)&f1h, g_f1h);   cudaGetSymbolAddress((void**)&f1l, g_f1l);
    cudaGetSymbolAddress((void**)&f2h, g_f2h);   cudaGetSymbolAddress((void**)&f2l, g_f2l);

    cudaFuncSetAttribute(tgemm<0,0,1>, cudaFuncAttributeMaxDynamicSharedMemorySize, SMEM_MM4);
    cudaFuncSetAttribute(tgemm<1,1,1>, cudaFuncAttributeMaxDynamicSharedMemorySize, SMEM_MM4);
    cudaFuncSetAttribute(tgemm<0,2,0>, cudaFuncAttributeMaxDynamicSharedMemorySize, SMEM_MM2);
    cudaFuncSetAttribute(attn_mma,     cudaFuncAttributeMaxDynamicSharedMemorySize, SMEM_AT);

    // streams/events created ONCE (first call = correctness run; baseline
    // already includes them; capture/replay allocate nothing).
    static cudaStream_t sB = nullptr, sC = nullptr;
    static cudaEvent_t evFork, evQW, evLn, evQA, evAA, evWpm, evX1, evW2, evLn2, evDone;
    if (!sB) {
        cudaStreamCreateWithFlags(&sB, cudaStreamNonBlocking);
        cudaStreamCreateWithFlags(&sC, cudaStreamNonBlocking);
        cudaEventCreateWithFlags(&evFork, cudaEventDisableTiming);
        cudaEventCreateWithFlags(&evQW,   cudaEventDisableTiming);
        cudaEventCreateWithFlags(&evLn,   cudaEventDisableTiming);
        cudaEventCreateWithFlags(&evQA,   cudaEventDisableTiming);
        cudaEventCreateWithFlags(&evAA,   cudaEventDisableTiming);
        cudaEventCreateWithFlags(&evWpm,  cudaEventDisableTiming);
        cudaEventCreateWithFlags(&evX1,   cudaEventDisableTiming);
        cudaEventCreateWithFlags(&evW2,   cudaEventDisableTiming);
        cudaEventCreateWithFlags(&evLn2,  cudaEventDisableTiming);
        cudaEventCreateWithFlags(&evDone, cudaEventDisableTiming);
    }

    cudaEventRecord(evFork, 0);
    cudaStreamWaitEvent(sB, evFork, 0);
    cudaStreamWaitEvent(sC, evFork, 0);

    // sC: qkv weight split first (overlaps LN1)
    tsplit<<<1728, 256, 0, sC>>>(w_qkv, wqh, wql, 384, 1152);
    cudaEventRecord(evQW, sC);
    // main: LN1
    ln_kernel<<<MROWS, 128>>>(x, ln1_w, ln1_b, nxh, nxl);
    cudaEventRecord(evLn, 0);
    // sB: kNN weight prep
    tsplit_knn2<<<1152, 256, 0, sB>>>(w_knn, wkh, wkl);
    tsplit<<<576, 256, 0, sB>>>(w_merge + 384 * 384, wm2h, wm2l, 384, 384);

    // main: qkv GEMM in two M-halves (3-stage nosplit); ldc carries token off
    cudaStreamWaitEvent(0, evQW, 0);
    tgemm<0,2,0><<<dim3(9, 64), 256, SMEM_MM2>>>(nxh, nullptr, wqh, nullptr,
        nullptr, nullptr, nullptr, nullptr, nullptr, qb, kb, vb,
        384, 384, 384, 0, 0);
    cudaEventRecord(evQA, 0);
    tgemm<0,2,0><<<dim3(9, 64), 256, SMEM_MM2>>>(nxh + (size_t)8192 * 384, nullptr,
        wqh, nullptr, nullptr, nullptr, nullptr, nullptr, nullptr, qb, kb, vb,
        384, 384, 384, 8192, 0);
    // main: attention for batches 8..15 (planes 48..95)
    attn_mma<<<dim3(8, 48), 128, SMEM_AT>>>(qb, kb, vb, aoh, aol, 48);

    // sC: Wpm chain, bias2; then attn_A; then fc tsplits
    tsplit<<<1152, 256, 0, sC>>>(w_merge, wmh, wml, 768, 384);
    fsplit<<<576, 256, 0, sC>>>(w_proj, wprh, wprl, 384 * 384);
    tgemm<0,0,1><<<dim3(3, 3), 256, SMEM_MM4, sC>>>(wmh, wml, wprh, wprl,
        nullptr, nullptr, wpm, nullptr, nullptr, nullptr, nullptr, nullptr,
        384, 768, 384, 384, 0);
    fsplit<<<576, 256, 0, sC>>>(wpm, wpmh, wpml, 384 * 384);
    bias2_kernel<<<3, 128, 0, sC>>>(b_proj, w_merge, b_merge, b2);
    cudaEventRecord(evWpm, sC);
    cudaStreamWaitEvent(sC, evQA, 0);
    attn_mma<<<dim3(8, 48), 128, SMEM_AT, sC>>>(qb, kb, vb, aoh, aol, 0);
    cudaEventRecord(evAA, sC);
    tsplit<<<2304, 256, 0, sC>>>(w_fc1, f1h, f1l, 384, 768);
    tsplit<<<2304, 256, 0, sC>>>(w_fc2, f2h, f2l, 768, 384);
    cudaEventRecord(evW2, sC);

    // sB: kNN branch (full split) -> x1 = knn_f@Wm2 + bias2
    cudaStreamWaitEvent(sB, evLn, 0);
    tgemm<0,0,1><<<dim3(6, 128), 256, SMEM_MM4, sB>>>(nxh, nxl, wkh, wkl,
        nullptr, nullptr, AbCc, nullptr, nullptr, nullptr, nullptr, nullptr,
        384, 384, 384, 768, 0);
    knn_kernel<<<MROWS, 128, 0, sB>>>(AbCc, knn, b_knn, knnh, knnl);
    cudaStreamWaitEvent(sB, evWpm, 0);
    tgemm<0,0,1><<<dim3(3, 128), 256, SMEM_MM4, sB>>>(knnh, knnl, wm2h, wm2l,
        b2, nullptr, x1, nullptr, nullptr, nullptr, nullptr, nullptr,
        384, 384, 384, 384, 0);
    cudaEventRecord(evX1, sB);

    // main: x2 = x + ao@Wpm  (needs both attention halves + Wpm)
    cudaStreamWaitEvent(0, evAA, 0);
    cudaStreamWaitEvent(0, evWpm, 0);
    tgemm<0,0,1><<<dim3(3, 128), 256, SMEM_MM4>>>(aoh, aol, wpmh, wpml,
        nullptr, x, x2, nullptr, nullptr, nullptr, nullptr, nullptr,
        384, 384, 384, 384, 384);

    // join: ln2(x1+x2)
    cudaStreamWaitEvent(0, evX1, 0);
    ln2sum_kernel<<<MROWS, 128>>>(x1, x2, ln2_w, ln2_b, xres, l2h, l2l);
    cudaEventRecord(evLn2, 0);

    // MLP pipelined by M-halves
    const size_t HM = 8192;
    cudaStreamWaitEvent(0, evW2, 0);
    tgemm<1,1,1><<<dim3(6, 64), 256, SMEM_MM4>>>(l2h, l2l, f1h, f1l,
        b_fc1, nullptr, nullptr, hh, hl, nullptr, nullptr, nullptr,
        384, 384, 384, 768, 0);
    cudaStreamWaitEvent(sB, evLn2, 0);
    cudaStreamWaitEvent(sB, evW2, 0);
    tgemm<1,1,1><<<dim3(6, 64), 256, SMEM_MM4, sB>>>(l2h + HM * 384, l2l + HM * 384,
        f1h, f1l, b_fc1, nullptr, nullptr, hh + HM * 768, hl + HM * 768,
        nullptr, nullptr, nullptr, 384, 384, 384, 768, 0);
    tgemm<0,0,1><<<dim3(3, 64), 256, SMEM_MM4>>>(hh, hl, f2h, f2l,
        b_fc2, xres, out, nullptr, nullptr, nullptr, nullptr, nullptr,
        768, 768, 768, 384, 384);
    tgemm<0,0,1><<<dim3(3, 64), 256, SMEM_MM4, sB>>>(hh + HM * 768, hl + HM * 768,
        f2h, f2l, b_fc2, xres + HM * 384, out + HM * 384,
        nullptr, nullptr, nullptr, nullptr, nullptr, 768, 768, 768, 384, 384);
    cudaEventRecord(evDone, sB);
    cudaStreamWaitEvent(0, evDone, 0);
}

// round 14
// speedup vs baseline: 1.1031x; 1.0054x over previous
#include <cuda_runtime.h>
#include <cuda_bf16.h>
#include <math.h>
#include <stdint.h>

// ---------------------------------------------------------------------------
// PCTransformer block, GB300 (sm_103a, compute_103 baseline PTX)
// B=16, N=1024, C=384, H=6, HD=64, K=8, HID=768, M=B*N=16384
// Two parallel batch-half pipelines (kNN gather is batch-local):
//   A: qkvA->attnA->x2A ; knnA->x1A ; ln2sumA->fc1A->fc2A
//   B: qkvB->attnB->x2B ; knnB->x1B ; ln2sumB->fc1B->fc2B
// Merge GEMM folded away. Dense GEMMs: merged-K bf16 HMMA (2-term split on
// residual-accuracy paths; nosplit 3-stage for qkv). 4 static streams.
// ---------------------------------------------------------------------------

#define MROWS 16384

// ---------------- scratch (static device globals; no allocation) -----------
__device__ float g_AbCc[MROWS * 768];
__device__ float g_x1  [MROWS * 384];
__device__ float g_x2  [MROWS * 384];
__device__ float g_xres[MROWS * 384];
__device__ float g_wpm [384 * 384];
__device__ float g_b2  [384];

__device__ __align__(16) __nv_bfloat16 g_qb[96*1024*64];
__device__ __align__(16) __nv_bfloat16 g_kb[96*1024*64];
__device__ __align__(16) __nv_bfloat16 g_vb[96*1024*64];

__device__ __align__(16) __nv_bfloat16 g_nxh[MROWS*384],  g_nxl[MROWS*384];
__device__ __align__(16) __nv_bfloat16 g_aoh[MROWS*384],  g_aol[MROWS*384];
__device__ __align__(16) __nv_bfloat16 g_knnh[MROWS*384], g_knnl[MROWS*384];
__device__ __align__(16) __nv_bfloat16 g_l2h[MROWS*384],  g_l2l[MROWS*384];
__device__ __align__(16) __nv_bfloat16 g_hh[MROWS*768],   g_hl[MROWS*768];

__device__ __align__(16) __nv_bfloat16 g_wqkvh[1152*384], g_wqkvl[1152*384];
__device__ __align__(16) __nv_bfloat16 g_wprh[384*384],   g_wprl[384*384];
__device__ __align__(16) __nv_bfloat16 g_wkh[768*384],    g_wkl[768*384];
__device__ __align__(16) __nv_bfloat16 g_wmh[384*768],    g_wml[384*768];
__device__ __align__(16) __nv_bfloat16 g_wm2h[384*384],   g_wm2l[384*384];
__device__ __align__(16) __nv_bfloat16 g_wpmh[384*384],   g_wpml[384*384];
__device__ __align__(16) __nv_bfloat16 g_f1h[768*384],    g_f1l[768*384];
__device__ __align__(16) __nv_bfloat16 g_f2h[384*768],    g_f2l[384*768];

// ---------------- PTX helpers ----------------------------------------------
__device__ __forceinline__ uint32_t smem_u32(const void* p) {
    uint32_t a;
    asm("{ .reg .u64 t; cvta.to.shared.u64 t, %1; cvt.u32.u64 %0, t; }"
        : "=r"(a) : "l"(p));
    return a;
}
__device__ __forceinline__ void ldsm_x4(uint32_t addr, uint32_t* r) {
    asm volatile("ldmatrix.sync.aligned.m8n8.x4.shared.b16 {%0,%1,%2,%3}, [%4];"
                 : "=r"(r[0]), "=r"(r[1]), "=r"(r[2]), "=r"(r[3]) : "r"(addr));
}
__device__ __forceinline__ void ldsm_x4t(uint32_t addr, uint32_t* r) {
    asm volatile("ldmatrix.sync.aligned.m8n8.x4.trans.shared.b16 {%0,%1,%2,%3}, [%4];"
                 : "=r"(r[0]), "=r"(r[1]), "=r"(r[2]), "=r"(r[3]) : "r"(addr));
}
__device__ __forceinline__ void mma_bf16(float* c, const uint32_t* a,
                                         uint32_t b0, uint32_t b1) {
    asm volatile(
        "mma.sync.aligned.m16n8k16.row.col.f32.bf16.bf16.f32 "
        "{%0,%1,%2,%3},{%4,%5,%6,%7},{%8,%9},{%0,%1,%2,%3};"
        : "+f"(c[0]), "+f"(c[1]), "+f"(c[2]), "+f"(c[3])
        : "r"(a[0]), "r"(a[1]), "r"(a[2]), "r"(a[3]), "r"(b0), "r"(b1));
}
__device__ __forceinline__ void cp16(uint32_t dst, const void* src) {
    asm volatile("cp.async.cg.shared.global [%0], [%1], 16;"
                 :: "r"(dst), "l"(src) : "memory");
}
#define CP_COMMIT() asm volatile("cp.async.commit_group;" ::: "memory")
#define CP_WAIT(n)  asm volatile("cp.async.wait_group %0;" :: "n"(n) : "memory")

__device__ __forceinline__ uint32_t bf2pk(float lo, float hi) {
    uint32_t r;
    asm("cvt.rn.bf16x2.f32 %0, %1, %2;" : "=r"(r) : "f"(hi), "f"(lo));
    return r;
}

__device__ __forceinline__ void split_store(__nv_bfloat16* H, __nv_bfloat16* L,
                                            size_t idx, float x, float y) {
    __nv_bfloat16 hx = __float2bfloat16_rn(x);
    __nv_bfloat16 hy = __float2bfloat16_rn(y);
    *(__nv_bfloat162*)&H[idx] = __nv_bfloat162(hx, hy);
    *(__nv_bfloat162*)&L[idx] =
        __nv_bfloat162(__float2bfloat16_rn(x - __bfloat162float(hx)),
                       __float2bfloat16_rn(y - __bfloat162float(hy)));
}

__device__ __forceinline__ void qkv_store(__nv_bfloat16* qp, __nv_bfloat16* kp,
                                          __nv_bfloat16* vp, int token, int col,
                                          float x, float y) {
    int bb = token >> 10, n = token & 1023;
    int which = col / 384;
    int rem = col - which * 384;
    int h = rem >> 6, d = rem & 63;
    size_t di = ((size_t)(bb * 6 + h) * 1024 + n) * 64 + d;
    float sc = (which == 0) ? 0.125f : 1.0f;
    __nv_bfloat16* dst = (which == 0) ? qp : ((which == 1) ? kp : vp);
    *(__nv_bfloat162*)&dst[di] =
        __nv_bfloat162(__float2bfloat16_rn(x * sc), __float2bfloat16_rn(y * sc));
}

// ---------------- LayerNorm (writes bf16 split) ----------------------------
__global__ void ln_kernel(const float* __restrict__ x,
                          const float* __restrict__ w,
                          const float* __restrict__ b,
                          __nv_bfloat16* __restrict__ H,
                          __nv_bfloat16* __restrict__ L) {
    int row = blockIdx.x, tid = threadIdx.x;
    const float* xr = x + (size_t)row * 384;
    float v0 = xr[tid], v1 = xr[tid + 128], v2 = xr[tid + 256];
    float s  = v0 + v1 + v2;
    float sq = v0 * v0 + v1 * v1 + v2 * v2;
    #pragma unroll
    for (int o = 16; o; o >>= 1) {
        s  += __shfl_xor_sync(0xffffffffu, s,  o);
        sq += __shfl_xor_sync(0xffffffffu, sq, o);
    }
    __shared__ float ss[4], sqs[4];
    int wid = tid >> 5, lid = tid & 31;
    if (lid == 0) { ss[wid] = s; sqs[wid] = sq; }
    __syncthreads();
    s  = ss[0] + ss[1] + ss[2] + ss[3];
    sq = sqs[0] + sqs[1] + sqs[2] + sqs[3];
    float mean = s * (1.0f / 384.0f);
    float var  = sq * (1.0f / 384.0f) - mean * mean;
    float inv  = rsqrtf(var + 1e-5f);
    size_t base = (size_t)row * 384;
    #pragma unroll
    for (int cc = 0; cc < 3; cc++) {
        int c = tid + cc * 128;
        float v = (cc == 0 ? v0 : (cc == 1 ? v1 : v2));
        float y = (v - mean) * inv * w[c] + b[c];
        __nv_bfloat16 h = __float2bfloat16_rn(y);
        H[base + c] = h;
        L[base + c] = __float2bfloat16_rn(y - __bfloat162float(h));
    }
}

__global__ void ln2sum_kernel(const float* __restrict__ x1,
                              const float* __restrict__ x2,
                              const float* __restrict__ w,
                              const float* __restrict__ b,
                              float* __restrict__ xres,
                              __nv_bfloat16* __restrict__ H,
                              __nv_bfloat16* __restrict__ L) {
    int row = blockIdx.x, tid = threadIdx.x;
    size_t base = (size_t)row * 384;
    float v0 = x1[base + tid]       + x2[base + tid];
    float v1 = x1[base + tid + 128] + x2[base + tid + 128];
    float v2 = x1[base + tid + 256] + x2[base + tid + 256];
    xres[base + tid]       = v0;
    xres[base + tid + 128] = v1;
    xres[base + tid + 256] = v2;
    float s  = v0 + v1 + v2;
    float sq = v0 * v0 + v1 * v1 + v2 * v2;
    #pragma unroll
    for (int o = 16; o; o >>= 1) {
        s  += __shfl_xor_sync(0xffffffffu, s,  o);
        sq += __shfl_xor_sync(0xffffffffu, sq, o);
    }
    __shared__ float ss[4], sqs[4];
    int wid = tid >> 5, lid = tid & 31;
    if (lid == 0) { ss[wid] = s; sqs[wid] = sq; }
    __syncthreads();
    s  = ss[0] + ss[1] + ss[2] + ss[3];
    sq = sqs[0] + sqs[1] + sqs[2] + sqs[3];
    float mean = s * (1.0f / 384.0f);
    float var  = sq * (1.0f / 384.0f) - mean * mean;
    float inv  = rsqrtf(var + 1e-5f);
    #pragma unroll
    for (int cc = 0; cc < 3; cc++) {
        int c = tid + cc * 128;
        float v = (cc == 0 ? v0 : (cc == 1 ? v1 : v2));
        float y = (v - mean) * inv * w[c] + b[c];
        __nv_bfloat16 h = __float2bfloat16_rn(y);
        H[base + c] = h;
        L[base + c] = __float2bfloat16_rn(y - __bfloat162float(h));
    }
}

__device__ __forceinline__ float gelu_exact(float v) {
    return 0.5f * v * (1.0f + erff(v * 0.70710678118654752f));
}

// ---------------- weight prep kernels --------------------------------------
__global__ void tsplit(const float* __restrict__ W,
                       __nv_bfloat16* __restrict__ Th,
                       __nv_bfloat16* __restrict__ Tl, int K, int N) {
    int idx = blockIdx.x * 256 + threadIdx.x;
    if (idx >= K * N) return;
    int n = idx / K, k = idx - n * K;
    float v = W[(size_t)k * N + n];
    __nv_bfloat16 h = __float2bfloat16_rn(v);
    Th[idx] = h;
    Tl[idx] = __float2bfloat16_rn(v - __bfloat162float(h));
}

__global__ void fsplit(const float* __restrict__ W,
                       __nv_bfloat16* __restrict__ Th,
                       __nv_bfloat16* __restrict__ Tl, int n) {
    int idx = blockIdx.x * 256 + threadIdx.x;
    if (idx >= n) return;
    float v = W[idx];
    __nv_bfloat16 h = __float2bfloat16_rn(v);
    Th[idx] = h;
    Tl[idx] = __float2bfloat16_rn(v - __bfloat162float(h));
}

__global__ void tsplit_knn2(const float* __restrict__ W,
                            __nv_bfloat16* __restrict__ Th,
                            __nv_bfloat16* __restrict__ Tl) {
    int idx = blockIdx.x * 256 + threadIdx.x;
    if (idx >= 768 * 384) return;
    int np = idx / 384, k = idx - np * 384;
    float v;
    if (np < 384) {
        v = W[(size_t)k * 384 + np];
    } else {
        int n = np - 384;
        v = W[(size_t)(384 + k) * 384 + n] - W[(size_t)k * 384 + n];
    }
    __nv_bfloat16 h = __float2bfloat16_rn(v);
    Th[idx] = h;
    Tl[idx] = __float2bfloat16_rn(v - __bfloat162float(h));
}

__global__ void bias2_kernel(const float* __restrict__ bp,
                             const float* __restrict__ wm,
                             const float* __restrict__ bm,
                             float* __restrict__ out) {
    int n = blockIdx.x * 128 + threadIdx.x;
    if (n >= 384) return;
    float s = 0.0f;
    for (int j = 0; j < 384; j++) s += bp[j] * wm[(size_t)j * 384 + n];
    out[n] = s + bm[n];
}

// ---------------- HMMA GEMM ------------------------------------------------
#define ROWB    80
#define TILE_B  (128 * ROWB)
#define SMEM_MM4 (2 * 4 * TILE_B)   // 81920 (split, 2-stage)
#define SMEM_MM2 (3 * 2 * TILE_B)   // 61440 (nosplit, 3-stage)

template <int GELU, int OMODE, int SPLITIN>
__global__ void __launch_bounds__(256, 2) tgemm(
    const __nv_bfloat16* __restrict__ Ah, const __nv_bfloat16* __restrict__ Al,
    const __nv_bfloat16* __restrict__ Bh, const __nv_bfloat16* __restrict__ Bl,
    const float* __restrict__ bias, const float* __restrict__ res,
    float* __restrict__ C, __nv_bfloat16* __restrict__ Ho,
    __nv_bfloat16* __restrict__ Lo,
    __nv_bfloat16* __restrict__ qp, __nv_bfloat16* __restrict__ kp,
    __nv_bfloat16* __restrict__ vp,
    int K, int lda, int ldb, int ldc, int ldres) {
    extern __shared__ char smem[];
    uint32_t sb = smem_u32(smem);
    int tid = threadIdx.x, lid = tid & 31, w = tid >> 5;
    int wm = w & 1, wn = w >> 1;
    int m0 = blockIdx.y * 128, n0 = blockIdx.x * 128;
    const int NIT = K >> 5;
    constexpr int NT = SPLITIN ? 4 : 2;
    constexpr uint32_t STG_B = NT * TILE_B;
    constexpr uint32_t BOFF  = (SPLITIN ? 2 : 1) * TILE_B;

    float acc[4][4][4];
    #pragma unroll
    for (int i = 0; i < 4; i++)
        #pragma unroll
        for (int j = 0; j < 4; j++)
            #pragma unroll
            for (int q = 0; q < 4; q++) acc[i][j][q] = 0.0f;

    int c0 = tid * 2;
    int lr0 = c0 >> 2,       lq0 = c0 & 3;
    int lr1 = (c0 + 1) >> 2, lq1 = (c0 + 1) & 3;

    auto load_stage = [&](int kc, int s) {
        const __nv_bfloat16* Ag = Ah + (size_t)m0 * lda + kc * 32;
        const __nv_bfloat16* Bg = Bh + (size_t)n0 * ldb + kc * 32;
        uint32_t st = sb + s * STG_B;
        uint32_t d0 = lr0 * ROWB + lq0 * 16, d1 = lr1 * ROWB + lq1 * 16;
        size_t a0 = (size_t)lr0 * lda + lq0 * 8, a1 = (size_t)lr1 * lda + lq1 * 8;
        size_t b0 = (size_t)lr0 * ldb + lq0 * 8, b1 = (size_t)lr1 * ldb + lq1 * 8;
        cp16(st + d0,        Ag + a0);
        cp16(st + d1,        Ag + a1);
        cp16(st + BOFF + d0, Bg + b0);
        cp16(st + BOFF + d1, Bg + b1);
        if (SPLITIN) {
            const __nv_bfloat16* Ag2 = Al + (size_t)m0 * lda + kc * 32;
            const __nv_bfloat16* Bg2 = Bl + (size_t)n0 * ldb + kc * 32;
            cp16(st + TILE_B + d0,     Ag2 + a0);
            cp16(st + TILE_B + d1,     Ag2 + a1);
            cp16(st + 3 * TILE_B + d0, Bg2 + b0);
            cp16(st + 3 * TILE_B + d1, Bg2 + b1);
        }
    };

    int rA = lid & 15, hA = lid >> 4;
    int rB = (lid & 7) + ((lid >> 4) << 3), hB = (lid >> 3) & 1;

    auto compute_stage = [&](int s) {
        uint32_t sAh = sb + s * STG_B + (wm * 64) * ROWB;
        uint32_t sBh = sb + s * STG_B + BOFF + (wn * 32) * ROWB;
        #pragma unroll
        for (int ks = 0; ks < 2; ks++) {
            int kk = ks * 16;
            uint32_t a[4][4];
            #pragma unroll
            for (int i = 0; i < 4; i++)
                ldsm_x4(sAh + (i * 16 + rA) * ROWB + (kk + hA * 8) * 2, a[i]);
            uint32_t bh[2][4];
            #pragma unroll
            for (int jj = 0; jj < 2; jj++)
                ldsm_x4(sBh + (jj * 16 + rB) * ROWB + (kk + hB * 8) * 2, bh[jj]);
            #pragma unroll
            for (int i = 0; i < 4; i++)
                #pragma unroll
                for (int j = 0; j < 4; j++)
                    mma_bf16(acc[i][j], a[i], bh[j >> 1][(j & 1) * 2],
                             bh[j >> 1][(j & 1) * 2 + 1]);
            if (SPLITIN) {
                uint32_t sAl = sAh + TILE_B;
                uint32_t sBl = sBh + TILE_B;
                uint32_t bl[2][4];
                #pragma unroll
                for (int jj = 0; jj < 2; jj++)
                    ldsm_x4(sBl + (jj * 16 + rB) * ROWB + (kk + hB * 8) * 2, bl[jj]);
                #pragma unroll
                for (int i = 0; i < 4; i++)
                    #pragma unroll
                    for (int j = 0; j < 4; j++)
                        mma_bf16(acc[i][j], a[i], bl[j >> 1][(j & 1) * 2],
                                 bl[j >> 1][(j & 1) * 2 + 1]);
                uint32_t al[4][4];
                #pragma unroll
                for (int i = 0; i < 4; i++)
                    ldsm_x4(sAl + (i * 16 + rA) * ROWB + (kk + hA * 8) * 2, al[i]);
                #pragma unroll
                for (int i = 0; i < 4; i++)
                    #pragma unroll
                    for (int j = 0; j < 4; j++)
                        mma_bf16(acc[i][j], al[i], bh[j >> 1][(j & 1) * 2],
                                 bh[j >> 1][(j & 1) * 2 + 1]);
            }
        }
    };

    if (SPLITIN) {
        load_stage(0, 0); CP_COMMIT();
        for (int it = 0; it < NIT; ++it) {
            if (it + 1 < NIT) { load_stage(it + 1, (it + 1) & 1); CP_COMMIT(); }
            if (it + 1 < NIT) CP_WAIT(1); else CP_WAIT(0);
            __syncthreads();
            compute_stage(it & 1);
            __syncthreads();
        }
    } else {
        load_stage(0, 0); CP_COMMIT();
        if (NIT > 1) { load_stage(1, 1); CP_COMMIT(); }
        for (int it = 0; it < NIT; ++it) {
            if (it == NIT - 1) { CP_WAIT(0); } else { CP_WAIT(1); }
            __syncthreads();
            compute_stage(it % 3);
            if (it + 2 < NIT) { load_stage(it + 2, (it + 2) % 3); CP_COMMIT(); }
        }
    }

    #pragma unroll
    for (int i = 0; i < 4; i++) {
        int r0 = m0 + wm * 64 + i * 16 + (lid >> 2);
        int r1 = r0 + 8;
        #pragma unroll
        for (int j = 0; j < 4; j++) {
            int col = n0 + wn * 32 + j * 8 + (lid & 3) * 2;
            float2 v0 = make_float2(acc[i][j][0], acc[i][j][1]);
            float2 v1 = make_float2(acc[i][j][2], acc[i][j][3]);
            if (bias) {
                float2 bb = *(const float2*)&bias[col];
                v0.x += bb.x; v0.y += bb.y; v1.x += bb.x; v1.y += bb.y;
            }
            if (GELU) {
                v0.x = gelu_exact(v0.x); v0.y = gelu_exact(v0.y);
                v1.x = gelu_exact(v1.x); v1.y = gelu_exact(v1.y);
            }
            if (res) {
                float2 q0 = *(const float2*)&res[(size_t)r0 * ldres + col];
                float2 q1 = *(const float2*)&res[(size_t)r1 * ldres + col];
                v0.x += q0.x; v0.y += q0.y; v1.x += q1.x; v1.y += q1.y;
            }
            if (OMODE == 2) {   // ldc = global token offset of row 0
                qkv_store(qp, kp, vp, r0 + ldc, col, v0.x, v0.y);
                qkv_store(qp, kp, vp, r1 + ldc, col, v1.x, v1.y);
            } else if (OMODE == 1) {
                split_store(Ho, Lo, (size_t)r0 * ldc + col, v0.x, v0.y);
                split_store(Ho, Lo, (size_t)r1 * ldc + col, v1.x, v1.y);
            } else {
                *(float2*)&C[(size_t)r0 * ldc + col] = v0;
                *(float2*)&C[(size_t)r1 * ldc + col] = v1;
            }
        }
    }
}

// ---------------- HMMA flash attention (poff = plane offset) ---------------
#define AT_STB  144
#define SQ_OFF  0
#define SK0_OFF (128 * AT_STB)
#define SV0_OFF (SK0_OFF + 64 * AT_STB)
#define SK1_OFF (SV0_OFF + 64 * AT_STB)
#define SV1_OFF (SK1_OFF + 64 * AT_STB)
#define SMEM_AT (SV1_OFF + 64 * AT_STB)

__global__ void __launch_bounds__(128) attn_mma(
    const __nv_bfloat16* __restrict__ qb,
    const __nv_bfloat16* __restrict__ kb,
    const __nv_bfloat16* __restrict__ vb,
    __nv_bfloat16* __restrict__ Ho, __nv_bfloat16* __restrict__ Lo,
    int poff) {
    extern __shared__ char smem[];
    uint32_t sb = smem_u32(smem);
    int tid = threadIdx.x, lid = tid & 31, wid = tid >> 5;
    int p = blockIdx.y + poff, q0 = blockIdx.x * 128;
    int b = p / 6, h = p - b * 6;
    const __nv_bfloat16* Qg = qb + ((size_t)p * 1024 + q0) * 64;
    const __nv_bfloat16* Kg = kb + (size_t)p * 1024 * 64;
    const __nv_bfloat16* Vg = vb + (size_t)p * 1024 * 64;

    #pragma unroll
    for (int i = 0; i < 8; i++) {
        int u = i * 128 + tid, r = u >> 3, c = u & 7;
        cp16(sb + SQ_OFF + r * AT_STB + c * 16, Qg + (size_t)r * 64 + c * 8);
    }
    #pragma unroll
    for (int i = 0; i < 4; i++) {
        int u = i * 128 + tid, r = u >> 3, c = u & 7;
        cp16(sb + SK0_OFF + r * AT_STB + c * 16, Kg + (size_t)r * 64 + c * 8);
        cp16(sb + SV0_OFF + r * AT_STB + c * 16, Vg + (size_t)r * 64 + c * 8);
    }
    CP_COMMIT();
    CP_WAIT(0);
    __syncthreads();

    int rA = lid & 15, hA = lid >> 4;
    uint32_t qf[2][4][4];
    #pragma unroll
    for (int mi = 0; mi < 2; mi++)
        #pragma unroll
        for (int kk = 0; kk < 4; kk++)
            ldsm_x4(sb + SQ_OFF + (wid * 32 + mi * 16 + rA) * AT_STB
                       + (kk * 16 + hA * 8) * 2, qf[mi][kk]);

    float o[2][8][4];
    #pragma unroll
    for (int mi = 0; mi < 2; mi++)
        #pragma unroll
        for (int j = 0; j < 8; j++)
            #pragma unroll
            for (int q = 0; q < 4; q++) o[mi][j][q] = 0.0f;
    float lsum[2][2] = {{0.0f, 0.0f}, {0.0f, 0.0f}};

    int rB = (lid & 7) + ((lid >> 4) << 3), hB = (lid >> 3) & 1;
    int tv = lid & 7, v8 = (lid >> 3) & 1, v16 = (lid >> 4) & 1;

    for (int kt = 0; kt < 16; kt++) {
        int buf = kt & 1;
        __syncthreads();
        if (kt + 1 < 16) {
            const __nv_bfloat16* Kn = Kg + (size_t)(kt + 1) * 64 * 64;
            const __nv_bfloat16* Vn = Vg + (size_t)(kt + 1) * 64 * 64;
            uint32_t dK = sb + (buf ? SK0_OFF : SK1_OFF);
            uint32_t dV = sb + (buf ? SV0_OFF : SV1_OFF);
            #pragma unroll
            for (int i = 0; i < 4; i++) {
                int u = i * 128 + tid, r = u >> 3, c = u & 7;
                cp16(dK + r * AT_STB + c * 16, Kn + (size_t)r * 64 + c * 8);
                cp16(dV + r * AT_STB + c * 16, Vn + (size_t)r * 64 + c * 8);
            }
        }
        CP_COMMIT();
        CP_WAIT(1);
        __syncthreads();
        uint32_t sK = sb + (buf ? SK1_OFF : SK0_OFF);
        uint32_t sV = sb + (buf ? SV1_OFF : SV0_OFF);

        float sacc[2][8][4];
        #pragma unroll
        for (int mi = 0; mi < 2; mi++)
            #pragma unroll
            for (int j = 0; j < 8; j++)
                #pragma unroll
                for (int q = 0; q < 4; q++) sacc[mi][j][q] = 0.0f;
        #pragma unroll
        for (int kk = 0; kk < 4; kk++) {
            uint32_t bfm[4][4];
            #pragma unroll
            for (int jj = 0; jj < 4; jj++)
                ldsm_x4(sK + (jj * 16 + rB) * AT_STB + (kk * 16 + hB * 8) * 2,
                        bfm[jj]);
            #pragma unroll
            for (int mi = 0; mi < 2; mi++)
                #pragma unroll
                for (int jj = 0; jj < 4; jj++) {
                    mma_bf16(sacc[mi][2 * jj],     qf[mi][kk], bfm[jj][0], bfm[jj][1]);
                    mma_bf16(sacc[mi][2 * jj + 1], qf[mi][kk], bfm[jj][2], bfm[jj][3]);
                }
        }
        #pragma unroll
        for (int mi = 0; mi < 2; mi++)
            #pragma unroll
            for (int j = 0; j < 8; j++) {
                sacc[mi][j][0] = __expf(sacc[mi][j][0]);
                sacc[mi][j][1] = __expf(sacc[mi][j][1]);
                sacc[mi][j][2] = __expf(sacc[mi][j][2]);
                sacc[mi][j][3] = __expf(sacc[mi][j][3]);
                lsum[mi][0] += sacc[mi][j][0] + sacc[mi][j][1];
                lsum[mi][1] += sacc[mi][j][2] + sacc[mi][j][3];
            }
        #pragma unroll
        for (int kk = 0; kk < 4; kk++) {
            uint32_t vf[4][4];
            #pragma unroll
            for (int jj = 0; jj < 4; jj++)
                ldsm_x4t(sV + (kk * 16 + v8 * 8 + tv) * AT_STB
                            + (jj * 16 + v16 * 8) * 2, vf[jj]);
            #pragma unroll
            for (int mi = 0; mi < 2; mi++) {
                uint32_t pa[4];
                pa[0] = bf2pk(sacc[mi][2 * kk][0],     sacc[mi][2 * kk][1]);
                pa[1] = bf2pk(sacc[mi][2 * kk][2],     sacc[mi][2 * kk][3]);
                pa[2] = bf2pk(sacc[mi][2 * kk + 1][0], sacc[mi][2 * kk + 1][1]);
                pa[3] = bf2pk(sacc[mi][2 * kk + 1][2], sacc[mi][2 * kk + 1][3]);
                #pragma unroll
                for (int jj = 0; jj < 4; jj++) {
                    mma_bf16(o[mi][2 * jj],     pa, vf[jj][0], vf[jj][1]);
                    mma_bf16(o[mi][2 * jj + 1], pa, vf[jj][2], vf[jj][3]);
                }
            }
        }
    }

    #pragma unroll
    for (int mi = 0; mi < 2; mi++)
        #pragma unroll
        for (int rr = 0; rr < 2; rr++) {
            lsum[mi][rr] += __shfl_xor_sync(0xffffffffu, lsum[mi][rr], 1);
            lsum[mi][rr] += __shfl_xor_sync(0xffffffffu, lsum[mi][rr], 2);
        }

    #pragma unroll
    for (int mi = 0; mi < 2; mi++) {
        float inv0 = 1.0f / lsum[mi][0];
        float inv1 = 1.0f / lsum[mi][1];
        int r0 = q0 + wid * 32 + mi * 16 + (lid >> 2);
        size_t row0 = ((size_t)b * 1024 + r0) * 384 + h * 64;
        size_t row1 = row0 + (size_t)8 * 384;
        #pragma unroll
        for (int j = 0; j < 8; j++) {
            int col = j * 8 + (lid & 3) * 2;
            split_store(Ho, Lo, row0 + col, o[mi][j][0] * inv0, o[mi][j][1] * inv0);
            split_store(Ho, Lo, row1 + col, o[mi][j][2] * inv1, o[mi][j][3] * inv1);
        }
    }
}

// ---------------- kNN gather (batch-local) + leaky_relu + max --------------
__global__ void knn_kernel(const float* __restrict__ AbCc,
                           const int* __restrict__ knn,
                           const float* __restrict__ bknn,
                           __nv_bfloat16* __restrict__ Ho,
                           __nv_bfloat16* __restrict__ Lo,
                           int roff) {
    int row = blockIdx.x + roff;
    int b = row >> 10, n = row & 1023;
    __shared__ int idxs[8];
    if (threadIdx.x < 8) idxs[threadIdx.x] = knn[((b << 3) + threadIdx.x) * 1024 + n];
    __syncthreads();
    #pragma unroll
    for (int cc = 0; cc < 3; cc++) {
        int c = threadIdx.x + cc * 128;
        float base = AbCc[(size_t)row * 768 + 384 + c] + bknn[c];
        float mx = -3.0e38f;
        #pragma unroll
        for (int k = 0; k < 8; k++) {
            float v = __ldg(&AbCc[(size_t)idxs[k] * 768 + c]) + base;
            v = (v > 0.0f) ? v : 0.2f * v;
            mx = fmaxf(mx, v);
        }
        size_t oi = (size_t)row * 384 + c;
        __nv_bfloat16 hb = __float2bfloat16_rn(mx);
        Ho[oi] = hb;
        Lo[oi] = __float2bfloat16_rn(mx - __bfloat162float(hb));
    }
}

// ---------------------------------------------------------------------------
extern "C" void kernel_launch(void* const* d_in, const int* in_sizes, int n_in,
                              void* d_out, int out_size) {
    (void)in_sizes; (void)n_in; (void)out_size;
    const float* x       = (const float*)d_in[0];
    const int*   knn     = (const int*)  d_in[1];
    const float* ln1_w   = (const float*)d_in[2];
    const float* ln1_b   = (const float*)d_in[3];
    const float* w_qkv   = (const float*)d_in[4];
    const float* w_proj  = (const float*)d_in[5];
    const float* b_proj  = (const float*)d_in[6];
    const float* w_knn   = (const float*)d_in[7];
    const float* b_knn   = (const float*)d_in[8];
    const float* w_merge = (const float*)d_in[9];
    const float* b_merge = (const float*)d_in[10];
    const float* ln2_w   = (const float*)d_in[11];
    const float* ln2_b   = (const float*)d_in[12];
    const float* w_fc1   = (const float*)d_in[13];
    const float* b_fc1   = (const float*)d_in[14];
    const float* w_fc2   = (const float*)d_in[15];
    const float* b_fc2   = (const float*)d_in[16];
    float* out = (float*)d_out;

    float *AbCc, *x1, *x2, *xres, *wpm, *b2;
    cudaGetSymbolAddress((void**)&AbCc, g_AbCc);
    cudaGetSymbolAddress((void**)&x1,   g_x1);
    cudaGetSymbolAddress((void**)&x2,   g_x2);
    cudaGetSymbolAddress((void**)&xres, g_xres);
    cudaGetSymbolAddress((void**)&wpm,  g_wpm);
    cudaGetSymbolAddress((void**)&b2,   g_b2);

    __nv_bfloat16 *qb,*kb,*vb;
    cudaGetSymbolAddress((void**)&qb, g_qb);
    cudaGetSymbolAddress((void**)&kb, g_kb);
    cudaGetSymbolAddress((void**)&vb, g_vb);

    __nv_bfloat16 *nxh,*nxl,*aoh,*aol,*knnh,*knnl,*l2h,*l2l,*hh,*hl;
    __nv_bfloat16 *wqh,*wql,*wprh,*wprl,*wkh,*wkl,*wmh,*wml,*wm2h,*wm2l;
    __nv_bfloat16 *wpmh,*wpml,*f1h,*f1l,*f2h,*f2l;
    cudaGetSymbolAddress((void**)&nxh, g_nxh);   cudaGetSymbolAddress((void**)&nxl, g_nxl);
    cudaGetSymbolAddress((void**)&aoh, g_aoh);   cudaGetSymbolAddress((void**)&aol, g_aol);
    cudaGetSymbolAddress((void**)&knnh,g_knnh);  cudaGetSymbolAddress((void**)&knnl,g_knnl);
    cudaGetSymbolAddress((void**)&l2h, g_l2h);   cudaGetSymbolAddress((void**)&l2l, g_l2l);
    cudaGetSymbolAddress((void**)&hh,  g_hh);    cudaGetSymbolAddress((void**)&hl,  g_hl);
    cudaGetSymbolAddress((void**)&wqh, g_wqkvh); cudaGetSymbolAddress((void**)&wql, g_wqkvl);
    cudaGetSymbolAddress((void**)&wprh,g_wprh);  cudaGetSymbolAddress((void**)&wprl,g_wprl);
    cudaGetSymbolAddress((void**)&wkh, g_wkh);   cudaGetSymbolAddress((void**)&wkl, g_wkl);
    cudaGetSymbolAddress((void**)&wmh, g_wmh);   cudaGetSymbolAddress((void**)&wml, g_wml);
    cudaGetSymbolAddress((void**)&wm2h,g_wm2h);  cudaGetSymbolAddress((void**)&wm2l,g_wm2l);
    cudaGetSymbolAddress((void**)&wpmh,g_wpmh);  cudaGetSymbolAddress((void**)&wpml,g_wpml);
    cudaGetSymbolAddress((void**)&f1h, g_f1h);   cudaGetSymbolAddress((void**)&f1l, g_f1l);
    cudaGetSymbolAddress((void**)&f2h, g_f2h);   cudaGetSymbolAddress((void**)&f2l, g_f2l);

    cudaFuncSetAttribute(tgemm<0,0,1>, cudaFuncAttributeMaxDynamicSharedMemorySize, SMEM_MM4);
    cudaFuncSetAttribute(tgemm<1,1,1>, cudaFuncAttributeMaxDynamicSharedMemorySize, SMEM_MM4);
    cudaFuncSetAttribute(tgemm<0,2,0>, cudaFuncAttributeMaxDynamicSharedMemorySize, SMEM_MM2);
    cudaFuncSetAttribute(attn_mma,     cudaFuncAttributeMaxDynamicSharedMemorySize, SMEM_AT);

    // streams/events created ONCE (first call = correctness run; baseline
    // already includes them; capture/replay allocate nothing).
    static cudaStream_t sB = nullptr, sC = nullptr, sD = nullptr;
    static cudaEvent_t evFork, evQW, evLn, evKW, evQA, evWpm,
                       evX1A, evX1B, evW2, evOutA;
    if (!sB) {
        cudaStreamCreateWithFlags(&sB, cudaStreamNonBlocking);
        cudaStreamCreateWithFlags(&sC, cudaStreamNonBlocking);
        cudaStreamCreateWithFlags(&sD, cudaStreamNonBlocking);
        cudaEventCreateWithFlags(&evFork, cudaEventDisableTiming);
        cudaEventCreateWithFlags(&evQW,   cudaEventDisableTiming);
        cudaEventCreateWithFlags(&evLn,   cudaEventDisableTiming);
        cudaEventCreateWithFlags(&evKW,   cudaEventDisableTiming);
        cudaEventCreateWithFlags(&evQA,   cudaEventDisableTiming);
        cudaEventCreateWithFlags(&evWpm,  cudaEventDisableTiming);
        cudaEventCreateWithFlags(&evX1A,  cudaEventDisableTiming);
        cudaEventCreateWithFlags(&evX1B,  cudaEventDisableTiming);
        cudaEventCreateWithFlags(&evW2,   cudaEventDisableTiming);
        cudaEventCreateWithFlags(&evOutA, cudaEventDisableTiming);
    }

    const size_t HM = 8192;   // rows per half (batches 0-7 | 8-15)

    cudaEventRecord(evFork, 0);
    cudaStreamWaitEvent(sB, evFork, 0);
    cudaStreamWaitEvent(sC, evFork, 0);
    cudaStreamWaitEvent(sD, evFork, 0);

    // sC: qkv weight split (overlaps LN1)
    tsplit<<<1728, 256, 0, sC>>>(w_qkv, wqh, wql, 384, 1152);
    cudaEventRecord(evQW, sC);
    // main: LN1
    ln_kernel<<<MROWS, 128>>>(x, ln1_w, ln1_b, nxh, nxl);
    cudaEventRecord(evLn, 0);
    // sB: kNN weight prep
    tsplit_knn2<<<1152, 256, 0, sB>>>(w_knn, wkh, wkl);
    tsplit<<<576, 256, 0, sB>>>(w_merge + 384 * 384, wm2h, wm2l, 384, 384);
    cudaEventRecord(evKW, sB);

    // main: qkvA, qkvB (3-stage nosplit; ldc = token offset)
    cudaStreamWaitEvent(0, evQW, 0);
    tgemm<0,2,0><<<dim3(9, 64), 256, SMEM_MM2>>>(nxh, nullptr, wqh, nullptr,
        nullptr, nullptr, nullptr, nullptr, nullptr, qb, kb, vb,
        384, 384, 384, 0, 0);
    cudaEventRecord(evQA, 0);
    tgemm<0,2,0><<<dim3(9, 64), 256, SMEM_MM2>>>(nxh + HM * 384, nullptr,
        wqh, nullptr, nullptr, nullptr, nullptr, nullptr, nullptr, qb, kb, vb,
        384, 384, 384, 8192, 0);
    // main: attnB (planes 48..95)
    attn_mma<<<dim3(8, 48), 128, SMEM_AT>>>(qb, kb, vb, aoh, aol, 48);

    // sC: Wpm chain + bias2; then attnA + x2A; then fc tsplits
    tsplit<<<1152, 256, 0, sC>>>(w_merge, wmh, wml, 768, 384);
    fsplit<<<576, 256, 0, sC>>>(w_proj, wprh, wprl, 384 * 384);
    tgemm<0,0,1><<<dim3(3, 3), 256, SMEM_MM4, sC>>>(wmh, wml, wprh, wprl,
        nullptr, nullptr, wpm, nullptr, nullptr, nullptr, nullptr, nullptr,
        384, 768, 384, 384, 0);
    fsplit<<<576, 256, 0, sC>>>(wpm, wpmh, wpml, 384 * 384);
    bias2_kernel<<<3, 128, 0, sC>>>(b_proj, w_merge, b_merge, b2);
    cudaEventRecord(evWpm, sC);
    cudaStreamWaitEvent(sC, evQA, 0);
    attn_mma<<<dim3(8, 48), 128, SMEM_AT, sC>>>(qb, kb, vb, aoh, aol, 0);
    tgemm<0,0,1><<<dim3(3, 64), 256, SMEM_MM4, sC>>>(aoh, aol, wpmh, wpml,
        nullptr, x, x2, nullptr, nullptr, nullptr, nullptr, nullptr,
        384, 384, 384, 384, 384);
    tsplit<<<2304, 256, 0, sC>>>(w_fc1, f1h, f1l, 384, 768);
    tsplit<<<2304, 256, 0, sC>>>(w_fc2, f2h, f2l, 768, 384);
    cudaEventRecord(evW2, sC);

    // sB: kNN half A
    cudaStreamWaitEvent(sB, evLn, 0);
    tgemm<0,0,1><<<dim3(6, 64), 256, SMEM_MM4, sB>>>(nxh, nxl, wkh, wkl,
        nullptr, nullptr, AbCc, nullptr, nullptr, nullptr, nullptr, nullptr,
        384, 384, 384, 768, 0);
    knn_kernel<<<8192, 128, 0, sB>>>(AbCc, knn, b_knn, knnh, knnl, 0);
    cudaStreamWaitEvent(sB, evWpm, 0);
    tgemm<0,0,1><<<dim3(3, 64), 256, SMEM_MM4, sB>>>(knnh, knnl, wm2h, wm2l,
        b2, nullptr, x1, nullptr, nullptr, nullptr, nullptr, nullptr,
        384, 384, 384, 384, 0);
    cudaEventRecord(evX1A, sB);

    // sD: kNN half B (concurrent with half A)
    cudaStreamWaitEvent(sD, evKW, 0);
    cudaStreamWaitEvent(sD, evLn, 0);
    tgemm<0,0,1><<<dim3(6, 64), 256, SMEM_MM4, sD>>>(nxh + HM * 384, nxl + HM * 384,
        wkh, wkl, nullptr, nullptr, AbCc + HM * 768, nullptr, nullptr,
        nullptr, nullptr, nullptr, 384, 384, 384, 768, 0);
    knn_kernel<<<8192, 128, 0, sD>>>(AbCc, knn, b_knn, knnh, knnl, 8192);
    cudaStreamWaitEvent(sD, evWpm, 0);
    tgemm<0,0,1><<<dim3(3, 64), 256, SMEM_MM4, sD>>>(knnh + HM * 384, knnl + HM * 384,
        wm2h, wm2l, b2, nullptr, x1 + HM * 384, nullptr, nullptr,
        nullptr, nullptr, nullptr, 384, 384, 384, 384, 0);
    cudaEventRecord(evX1B, sD);

    // sC: A-half join + MLP chain A -> out rows [0, 8192)
    cudaStreamWaitEvent(sC, evX1A, 0);
    ln2sum_kernel<<<8192, 128, 0, sC>>>(x1, x2, ln2_w, ln2_b, xres, l2h, l2l);
    tgemm<1,1,1><<<dim3(6, 64), 256, SMEM_MM4, sC>>>(l2h, l2l, f1h, f1l,
        b_fc1, nullptr, nullptr, hh, hl, nullptr, nullptr, nullptr,
        384, 384, 384, 768, 0);
    tgemm<0,0,1><<<dim3(3, 64), 256, SMEM_MM4, sC>>>(hh, hl, f2h, f2l,
        b_fc2, xres, out, nullptr, nullptr, nullptr, nullptr, nullptr,
        768, 768, 768, 384, 384);
    cudaEventRecord(evOutA, sC);

    // main: B-half x2 + join + MLP chain B -> out rows [8192, 16384)
    cudaStreamWaitEvent(0, evWpm, 0);
    tgemm<0,0,1><<<dim3(3, 64), 256, SMEM_MM4>>>(aoh + HM * 384, aol + HM * 384,
        wpmh, wpml, nullptr, x + HM * 384, x2 + HM * 384, nullptr, nullptr,
        nullptr, nullptr, nullptr, 384, 384, 384, 384, 384);
    cudaStreamWaitEvent(0, evX1B, 0);
    ln2sum_kernel<<<8192, 128>>>(x1 + HM * 384, x2 + HM * 384, ln2_w, ln2_b,
                                 xres + HM * 384, l2h + HM * 384, l2l + HM * 384);
    cudaStreamWaitEvent(0, evW2, 0);
    tgemm<1,1,1><<<dim3(6, 64), 256, SMEM_MM4>>>(l2h + HM * 384, l2l + HM * 384,
        f1h, f1l, b_fc1, nullptr, nullptr, hh + HM * 768, hl + HM * 768,
        nullptr, nullptr, nullptr, 384, 384, 384, 768, 0);
    tgemm<0,0,1><<<dim3(3, 64), 256, SMEM_MM4>>>(hh + HM * 768, hl + HM * 768,
        f2h, f2l, b_fc2, xres + HM * 384, out + HM * 384,
        nullptr, nullptr, nullptr, nullptr, nullptr, 768, 768, 768, 384, 384);
    cudaStreamWaitEvent(0, evOutA, 0);
}

// round 15
// speedup vs baseline: 1.1294x; 1.0238x over previous
#include <cuda_runtime.h>
#include <cuda_bf16.h>
#include <math.h>
#include <stdint.h>

// ---------------------------------------------------------------------------
// PCTransformer block, GB300 (sm_103a, compute_103 baseline PTX)
// B=16, N=1024, C=384, H=6, HD=64, K=8, HID=768, M=B*N=16384
// x_new = x + [ao | knn_f] @ [Wpm ; Wm2] + bias2  (merge+proj folded, single
// cat-GEMM). Two batch-half pipelines. Dense GEMMs: merged-K bf16 HMMA
// (2-term split on residual paths; nosplit 3-stage qkv). 4 static streams.
// ---------------------------------------------------------------------------

#define MROWS 16384

// ---------------- scratch (static device globals; no allocation) -----------
__device__ float g_AbCc[MROWS * 768];
__device__ float g_xres[MROWS * 384];
__device__ float g_wpm [384 * 384];
__device__ float g_b2  [384];

__device__ __align__(16) __nv_bfloat16 g_qb[96*1024*64];
__device__ __align__(16) __nv_bfloat16 g_kb[96*1024*64];
__device__ __align__(16) __nv_bfloat16 g_vb[96*1024*64];

__device__ __align__(16) __nv_bfloat16 g_nxh[MROWS*384],  g_nxl[MROWS*384];
__device__ __align__(16) __nv_bfloat16 g_cath[MROWS*768], g_catl[MROWS*768];
__device__ __align__(16) __nv_bfloat16 g_l2h[MROWS*384],  g_l2l[MROWS*384];
__device__ __align__(16) __nv_bfloat16 g_hh[MROWS*768],   g_hl[MROWS*768];

__device__ __align__(16) __nv_bfloat16 g_wqkvh[1152*384], g_wqkvl[1152*384];
__device__ __align__(16) __nv_bfloat16 g_wprh[384*384],   g_wprl[384*384];
__device__ __align__(16) __nv_bfloat16 g_wkh[768*384],    g_wkl[768*384];
__device__ __align__(16) __nv_bfloat16 g_wmh[384*768],    g_wml[384*768];
__device__ __align__(16) __nv_bfloat16 g_wcmbh[384*768],  g_wcmbl[384*768]; // [Wpm ; Wm2]^T
__device__ __align__(16) __nv_bfloat16 g_f1h[768*384],    g_f1l[768*384];
__device__ __align__(16) __nv_bfloat16 g_f2h[384*768],    g_f2l[384*768];

// ---------------- PTX helpers ----------------------------------------------
__device__ __forceinline__ uint32_t smem_u32(const void* p) {
    uint32_t a;
    asm("{ .reg .u64 t; cvta.to.shared.u64 t, %1; cvt.u32.u64 %0, t; }"
        : "=r"(a) : "l"(p));
    return a;
}
__device__ __forceinline__ void ldsm_x4(uint32_t addr, uint32_t* r) {
    asm volatile("ldmatrix.sync.aligned.m8n8.x4.shared.b16 {%0,%1,%2,%3}, [%4];"
                 : "=r"(r[0]), "=r"(r[1]), "=r"(r[2]), "=r"(r[3]) : "r"(addr));
}
__device__ __forceinline__ void ldsm_x4t(uint32_t addr, uint32_t* r) {
    asm volatile("ldmatrix.sync.aligned.m8n8.x4.trans.shared.b16 {%0,%1,%2,%3}, [%4];"
                 : "=r"(r[0]), "=r"(r[1]), "=r"(r[2]), "=r"(r[3]) : "r"(addr));
}
__device__ __forceinline__ void mma_bf16(float* c, const uint32_t* a,
                                         uint32_t b0, uint32_t b1) {
    asm volatile(
        "mma.sync.aligned.m16n8k16.row.col.f32.bf16.bf16.f32 "
        "{%0,%1,%2,%3},{%4,%5,%6,%7},{%8,%9},{%0,%1,%2,%3};"
        : "+f"(c[0]), "+f"(c[1]), "+f"(c[2]), "+f"(c[3])
        : "r"(a[0]), "r"(a[1]), "r"(a[2]), "r"(a[3]), "r"(b0), "r"(b1));
}
__device__ __forceinline__ void cp16(uint32_t dst, const void* src) {
    asm volatile("cp.async.cg.shared.global [%0], [%1], 16;"
                 :: "r"(dst), "l"(src) : "memory");
}
#define CP_COMMIT() asm volatile("cp.async.commit_group;" ::: "memory")
#define CP_WAIT(n)  asm volatile("cp.async.wait_group %0;" :: "n"(n) : "memory")

__device__ __forceinline__ uint32_t bf2pk(float lo, float hi) {
    uint32_t r;
    asm("cvt.rn.bf16x2.f32 %0, %1, %2;" : "=r"(r) : "f"(hi), "f"(lo));
    return r;
}

__device__ __forceinline__ void split_store(__nv_bfloat16* H, __nv_bfloat16* L,
                                            size_t idx, float x, float y) {
    __nv_bfloat16 hx = __float2bfloat16_rn(x);
    __nv_bfloat16 hy = __float2bfloat16_rn(y);
    *(__nv_bfloat162*)&H[idx] = __nv_bfloat162(hx, hy);
    *(__nv_bfloat162*)&L[idx] =
        __nv_bfloat162(__float2bfloat16_rn(x - __bfloat162float(hx)),
                       __float2bfloat16_rn(y - __bfloat162float(hy)));
}

__device__ __forceinline__ void qkv_store(__nv_bfloat16* qp, __nv_bfloat16* kp,
                                          __nv_bfloat16* vp, int token, int col,
                                          float x, float y) {
    int bb = token >> 10, n = token & 1023;
    int which = col / 384;
    int rem = col - which * 384;
    int h = rem >> 6, d = rem & 63;
    size_t di = ((size_t)(bb * 6 + h) * 1024 + n) * 64 + d;
    float sc = (which == 0) ? 0.125f : 1.0f;
    __nv_bfloat16* dst = (which == 0) ? qp : ((which == 1) ? kp : vp);
    *(__nv_bfloat162*)&dst[di] =
        __nv_bfloat162(__float2bfloat16_rn(x * sc), __float2bfloat16_rn(y * sc));
}

// ---------------- LayerNorm (writes bf16 split) ----------------------------
__global__ void ln_kernel(const float* __restrict__ x,
                          const float* __restrict__ w,
                          const float* __restrict__ b,
                          __nv_bfloat16* __restrict__ H,
                          __nv_bfloat16* __restrict__ L) {
    int row = blockIdx.x, tid = threadIdx.x;
    const float* xr = x + (size_t)row * 384;
    float v0 = xr[tid], v1 = xr[tid + 128], v2 = xr[tid + 256];
    float s  = v0 + v1 + v2;
    float sq = v0 * v0 + v1 * v1 + v2 * v2;
    #pragma unroll
    for (int o = 16; o; o >>= 1) {
        s  += __shfl_xor_sync(0xffffffffu, s,  o);
        sq += __shfl_xor_sync(0xffffffffu, sq, o);
    }
    __shared__ float ss[4], sqs[4];
    int wid = tid >> 5, lid = tid & 31;
    if (lid == 0) { ss[wid] = s; sqs[wid] = sq; }
    __syncthreads();
    s  = ss[0] + ss[1] + ss[2] + ss[3];
    sq = sqs[0] + sqs[1] + sqs[2] + sqs[3];
    float mean = s * (1.0f / 384.0f);
    float var  = sq * (1.0f / 384.0f) - mean * mean;
    float inv  = rsqrtf(var + 1e-5f);
    size_t base = (size_t)row * 384;
    #pragma unroll
    for (int cc = 0; cc < 3; cc++) {
        int c = tid + cc * 128;
        float v = (cc == 0 ? v0 : (cc == 1 ? v1 : v2));
        float y = (v - mean) * inv * w[c] + b[c];
        __nv_bfloat16 h = __float2bfloat16_rn(y);
        H[base + c] = h;
        L[base + c] = __float2bfloat16_rn(y - __bfloat162float(h));
    }
}

__device__ __forceinline__ float gelu_exact(float v) {
    return 0.5f * v * (1.0f + erff(v * 0.70710678118654752f));
}

// ---------------- weight prep kernels --------------------------------------
__global__ void tsplit(const float* __restrict__ W,
                       __nv_bfloat16* __restrict__ Th,
                       __nv_bfloat16* __restrict__ Tl, int K, int N) {
    int idx = blockIdx.x * 256 + threadIdx.x;
    if (idx >= K * N) return;
    int n = idx / K, k = idx - n * K;
    float v = W[(size_t)k * N + n];
    __nv_bfloat16 h = __float2bfloat16_rn(v);
    Th[idx] = h;
    Tl[idx] = __float2bfloat16_rn(v - __bfloat162float(h));
}

__global__ void fsplit(const float* __restrict__ W,
                       __nv_bfloat16* __restrict__ Th,
                       __nv_bfloat16* __restrict__ Tl, int n) {
    int idx = blockIdx.x * 256 + threadIdx.x;
    if (idx >= n) return;
    float v = W[idx];
    __nv_bfloat16 h = __float2bfloat16_rn(v);
    Th[idx] = h;
    Tl[idx] = __float2bfloat16_rn(v - __bfloat162float(h));
}

// wpm[384x384] -> wcmb left half (dst stride 768)
__global__ void fsplit_cmb(const float* __restrict__ W,
                           __nv_bfloat16* __restrict__ Th,
                           __nv_bfloat16* __restrict__ Tl) {
    int idx = blockIdx.x * 256 + threadIdx.x;
    if (idx >= 384 * 384) return;
    int n = idx / 384, k = idx - n * 384;
    float v = W[(size_t)n * 384 + k];
    __nv_bfloat16 h = __float2bfloat16_rn(v);
    size_t d = (size_t)n * 768 + k;
    Th[d] = h;
    Tl[d] = __float2bfloat16_rn(v - __bfloat162float(h));
}

// Wm2^T (w_merge rows 384..767) -> wcmb right half (dst stride 768, +384)
__global__ void tsplit_cmb(const float* __restrict__ Wm,
                           __nv_bfloat16* __restrict__ Th,
                           __nv_bfloat16* __restrict__ Tl) {
    int idx = blockIdx.x * 256 + threadIdx.x;
    if (idx >= 384 * 384) return;
    int n = idx / 384, k = idx - n * 384;
    float v = Wm[(size_t)(384 + k) * 384 + n];
    __nv_bfloat16 h = __float2bfloat16_rn(v);
    size_t d = (size_t)n * 768 + 384 + k;
    Th[d] = h;
    Tl[d] = __float2bfloat16_rn(v - __bfloat162float(h));
}

__global__ void tsplit_knn2(const float* __restrict__ W,
                            __nv_bfloat16* __restrict__ Th,
                            __nv_bfloat16* __restrict__ Tl) {
    int idx = blockIdx.x * 256 + threadIdx.x;
    if (idx >= 768 * 384) return;
    int np = idx / 384, k = idx - np * 384;
    float v;
    if (np < 384) {
        v = W[(size_t)k * 384 + np];
    } else {
        int n = np - 384;
        v = W[(size_t)(384 + k) * 384 + n] - W[(size_t)k * 384 + n];
    }
    __nv_bfloat16 h = __float2bfloat16_rn(v);
    Th[idx] = h;
    Tl[idx] = __float2bfloat16_rn(v - __bfloat162float(h));
}

__global__ void bias2_kernel(const float* __restrict__ bp,
                             const float* __restrict__ wm,
                             const float* __restrict__ bm,
                             float* __restrict__ out) {
    int n = blockIdx.x * 128 + threadIdx.x;
    if (n >= 384) return;
    float s = 0.0f;
    for (int j = 0; j < 384; j++) s += bp[j] * wm[(size_t)j * 384 + n];
    out[n] = s + bm[n];
}

// ---------------- HMMA GEMM ------------------------------------------------
#define ROWB    80
#define TILE_B  (128 * ROWB)
#define SMEM_MM4 (2 * 4 * TILE_B)   // 81920 (split, 2-stage)
#define SMEM_MM2 (3 * 2 * TILE_B)   // 61440 (nosplit, 3-stage)

template <int GELU, int OMODE, int SPLITIN>
__global__ void __launch_bounds__(256, 2) tgemm(
    const __nv_bfloat16* __restrict__ Ah, const __nv_bfloat16* __restrict__ Al,
    const __nv_bfloat16* __restrict__ Bh, const __nv_bfloat16* __restrict__ Bl,
    const float* __restrict__ bias, const float* __restrict__ res,
    float* __restrict__ C, __nv_bfloat16* __restrict__ Ho,
    __nv_bfloat16* __restrict__ Lo,
    __nv_bfloat16* __restrict__ qp, __nv_bfloat16* __restrict__ kp,
    __nv_bfloat16* __restrict__ vp,
    int K, int lda, int ldb, int ldc, int ldres) {
    extern __shared__ char smem[];
    uint32_t sb = smem_u32(smem);
    int tid = threadIdx.x, lid = tid & 31, w = tid >> 5;
    int wm = w & 1, wn = w >> 1;
    int m0 = blockIdx.y * 128, n0 = blockIdx.x * 128;
    const int NIT = K >> 5;
    constexpr int NT = SPLITIN ? 4 : 2;
    constexpr uint32_t STG_B = NT * TILE_B;
    constexpr uint32_t BOFF  = (SPLITIN ? 2 : 1) * TILE_B;

    float acc[4][4][4];
    #pragma unroll
    for (int i = 0; i < 4; i++)
        #pragma unroll
        for (int j = 0; j < 4; j++)
            #pragma unroll
            for (int q = 0; q < 4; q++) acc[i][j][q] = 0.0f;

    int c0 = tid * 2;
    int lr0 = c0 >> 2,       lq0 = c0 & 3;
    int lr1 = (c0 + 1) >> 2, lq1 = (c0 + 1) & 3;

    auto load_stage = [&](int kc, int s) {
        const __nv_bfloat16* Ag = Ah + (size_t)m0 * lda + kc * 32;
        const __nv_bfloat16* Bg = Bh + (size_t)n0 * ldb + kc * 32;
        uint32_t st = sb + s * STG_B;
        uint32_t d0 = lr0 * ROWB + lq0 * 16, d1 = lr1 * ROWB + lq1 * 16;
        size_t a0 = (size_t)lr0 * lda + lq0 * 8, a1 = (size_t)lr1 * lda + lq1 * 8;
        size_t b0 = (size_t)lr0 * ldb + lq0 * 8, b1 = (size_t)lr1 * ldb + lq1 * 8;
        cp16(st + d0,        Ag + a0);
        cp16(st + d1,        Ag + a1);
        cp16(st + BOFF + d0, Bg + b0);
        cp16(st + BOFF + d1, Bg + b1);
        if (SPLITIN) {
            const __nv_bfloat16* Ag2 = Al + (size_t)m0 * lda + kc * 32;
            const __nv_bfloat16* Bg2 = Bl + (size_t)n0 * ldb + kc * 32;
            cp16(st + TILE_B + d0,     Ag2 + a0);
            cp16(st + TILE_B + d1,     Ag2 + a1);
            cp16(st + 3 * TILE_B + d0, Bg2 + b0);
            cp16(st + 3 * TILE_B + d1, Bg2 + b1);
        }
    };

    int rA = lid & 15, hA = lid >> 4;
    int rB = (lid & 7) + ((lid >> 4) << 3), hB = (lid >> 3) & 1;

    auto compute_stage = [&](int s) {
        uint32_t sAh = sb + s * STG_B + (wm * 64) * ROWB;
        uint32_t sBh = sb + s * STG_B + BOFF + (wn * 32) * ROWB;
        #pragma unroll
        for (int ks = 0; ks < 2; ks++) {
            int kk = ks * 16;
            uint32_t a[4][4];
            #pragma unroll
            for (int i = 0; i < 4; i++)
                ldsm_x4(sAh + (i * 16 + rA) * ROWB + (kk + hA * 8) * 2, a[i]);
            uint32_t bh[2][4];
            #pragma unroll
            for (int jj = 0; jj < 2; jj++)
                ldsm_x4(sBh + (jj * 16 + rB) * ROWB + (kk + hB * 8) * 2, bh[jj]);
            #pragma unroll
            for (int i = 0; i < 4; i++)
                #pragma unroll
                for (int j = 0; j < 4; j++)
                    mma_bf16(acc[i][j], a[i], bh[j >> 1][(j & 1) * 2],
                             bh[j >> 1][(j & 1) * 2 + 1]);
            if (SPLITIN) {
                uint32_t sAl = sAh + TILE_B;
                uint32_t sBl = sBh + TILE_B;
                uint32_t bl[2][4];
                #pragma unroll
                for (int jj = 0; jj < 2; jj++)
                    ldsm_x4(sBl + (jj * 16 + rB) * ROWB + (kk + hB * 8) * 2, bl[jj]);
                #pragma unroll
                for (int i = 0; i < 4; i++)
                    #pragma unroll
                    for (int j = 0; j < 4; j++)
                        mma_bf16(acc[i][j], a[i], bl[j >> 1][(j & 1) * 2],
                                 bl[j >> 1][(j & 1) * 2 + 1]);
                uint32_t al[4][4];
                #pragma unroll
                for (int i = 0; i < 4; i++)
                    ldsm_x4(sAl + (i * 16 + rA) * ROWB + (kk + hA * 8) * 2, al[i]);
                #pragma unroll
                for (int i = 0; i < 4; i++)
                    #pragma unroll
                    for (int j = 0; j < 4; j++)
                        mma_bf16(acc[i][j], al[i], bh[j >> 1][(j & 1) * 2],
                                 bh[j >> 1][(j & 1) * 2 + 1]);
            }
        }
    };

    if (SPLITIN) {
        load_stage(0, 0); CP_COMMIT();
        for (int it = 0; it < NIT; ++it) {
            if (it + 1 < NIT) { load_stage(it + 1, (it + 1) & 1); CP_COMMIT(); }
            if (it + 1 < NIT) CP_WAIT(1); else CP_WAIT(0);
            __syncthreads();
            compute_stage(it & 1);
            __syncthreads();
        }
    } else {
        load_stage(0, 0); CP_COMMIT();
        if (NIT > 1) { load_stage(1, 1); CP_COMMIT(); }
        for (int it = 0; it < NIT; ++it) {
            if (it == NIT - 1) { CP_WAIT(0); } else { CP_WAIT(1); }
            __syncthreads();
            compute_stage(it % 3);
            if (it + 2 < NIT) { load_stage(it + 2, (it + 2) % 3); CP_COMMIT(); }
        }
    }

    #pragma unroll
    for (int i = 0; i < 4; i++) {
        int r0 = m0 + wm * 64 + i * 16 + (lid >> 2);
        int r1 = r0 + 8;
        #pragma unroll
        for (int j = 0; j < 4; j++) {
            int col = n0 + wn * 32 + j * 8 + (lid & 3) * 2;
            float2 v0 = make_float2(acc[i][j][0], acc[i][j][1]);
            float2 v1 = make_float2(acc[i][j][2], acc[i][j][3]);
            if (bias) {
                float2 bb = *(const float2*)&bias[col];
                v0.x += bb.x; v0.y += bb.y; v1.x += bb.x; v1.y += bb.y;
            }
            if (GELU) {
                v0.x = gelu_exact(v0.x); v0.y = gelu_exact(v0.y);
                v1.x = gelu_exact(v1.x); v1.y = gelu_exact(v1.y);
            }
            if (res) {
                float2 q0 = *(const float2*)&res[(size_t)r0 * ldres + col];
                float2 q1 = *(const float2*)&res[(size_t)r1 * ldres + col];
                v0.x += q0.x; v0.y += q0.y; v1.x += q1.x; v1.y += q1.y;
            }
            if (OMODE == 2) {   // ldc = global token offset of row 0
                qkv_store(qp, kp, vp, r0 + ldc, col, v0.x, v0.y);
                qkv_store(qp, kp, vp, r1 + ldc, col, v1.x, v1.y);
            } else if (OMODE == 1) {
                split_store(Ho, Lo, (size_t)r0 * ldc + col, v0.x, v0.y);
                split_store(Ho, Lo, (size_t)r1 * ldc + col, v1.x, v1.y);
            } else {
                *(float2*)&C[(size_t)r0 * ldc + col] = v0;
                *(float2*)&C[(size_t)r1 * ldc + col] = v1;
            }
        }
    }
}

// ---------------- HMMA flash attention (writes cat[:, :384], stride 768) ---
#define AT_STB  144
#define SQ_OFF  0
#define SK0_OFF (128 * AT_STB)
#define SV0_OFF (SK0_OFF + 64 * AT_STB)
#define SK1_OFF (SV0_OFF + 64 * AT_STB)
#define SV1_OFF (SK1_OFF + 64 * AT_STB)
#define SMEM_AT (SV1_OFF + 64 * AT_STB)

__global__ void __launch_bounds__(128) attn_mma(
    const __nv_bfloat16* __restrict__ qb,
    const __nv_bfloat16* __restrict__ kb,
    const __nv_bfloat16* __restrict__ vb,
    __nv_bfloat16* __restrict__ Ho, __nv_bfloat16* __restrict__ Lo,
    int poff) {
    extern __shared__ char smem[];
    uint32_t sb = smem_u32(smem);
    int tid = threadIdx.x, lid = tid & 31, wid = tid >> 5;
    int p = blockIdx.y + poff, q0 = blockIdx.x * 128;
    int b = p / 6, h = p - b * 6;
    const __nv_bfloat16* Qg = qb + ((size_t)p * 1024 + q0) * 64;
    const __nv_bfloat16* Kg = kb + (size_t)p * 1024 * 64;
    const __nv_bfloat16* Vg = vb + (size_t)p * 1024 * 64;

    #pragma unroll
    for (int i = 0; i < 8; i++) {
        int u = i * 128 + tid, r = u >> 3, c = u & 7;
        cp16(sb + SQ_OFF + r * AT_STB + c * 16, Qg + (size_t)r * 64 + c * 8);
    }
    #pragma unroll
    for (int i = 0; i < 4; i++) {
        int u = i * 128 + tid, r = u >> 3, c = u & 7;
        cp16(sb + SK0_OFF + r * AT_STB + c * 16, Kg + (size_t)r * 64 + c * 8);
        cp16(sb + SV0_OFF + r * AT_STB + c * 16, Vg + (size_t)r * 64 + c * 8);
    }
    CP_COMMIT();
    CP_WAIT(0);
    __syncthreads();

    int rA = lid & 15, hA = lid >> 4;
    uint32_t qf[2][4][4];
    #pragma unroll
    for (int mi = 0; mi < 2; mi++)
        #pragma unroll
        for (int kk = 0; kk < 4; kk++)
            ldsm_x4(sb + SQ_OFF + (wid * 32 + mi * 16 + rA) * AT_STB
                       + (kk * 16 + hA * 8) * 2, qf[mi][kk]);

    float o[2][8][4];
    #pragma unroll
    for (int mi = 0; mi < 2; mi++)
        #pragma unroll
        for (int j = 0; j < 8; j++)
            #pragma unroll
            for (int q = 0; q < 4; q++) o[mi][j][q] = 0.0f;
    float lsum[2][2] = {{0.0f, 0.0f}, {0.0f, 0.0f}};

    int rB = (lid & 7) + ((lid >> 4) << 3), hB = (lid >> 3) & 1;
    int tv = lid & 7, v8 = (lid >> 3) & 1, v16 = (lid >> 4) & 1;

    for (int kt = 0; kt < 16; kt++) {
        int buf = kt & 1;
        __syncthreads();
        if (kt + 1 < 16) {
            const __nv_bfloat16* Kn = Kg + (size_t)(kt + 1) * 64 * 64;
            const __nv_bfloat16* Vn = Vg + (size_t)(kt + 1) * 64 * 64;
            uint32_t dK = sb + (buf ? SK0_OFF : SK1_OFF);
            uint32_t dV = sb + (buf ? SV0_OFF : SV1_OFF);
            #pragma unroll
            for (int i = 0; i < 4; i++) {
                int u = i * 128 + tid, r = u >> 3, c = u & 7;
                cp16(dK + r * AT_STB + c * 16, Kn + (size_t)r * 64 + c * 8);
                cp16(dV + r * AT_STB + c * 16, Vn + (size_t)r * 64 + c * 8);
            }
        }
        CP_COMMIT();
        CP_WAIT(1);
        __syncthreads();
        uint32_t sK = sb + (buf ? SK1_OFF : SK0_OFF);
        uint32_t sV = sb + (buf ? SV1_OFF : SV0_OFF);

        float sacc[2][8][4];
        #pragma unroll
        for (int mi = 0; mi < 2; mi++)
            #pragma unroll
            for (int j = 0; j < 8; j++)
                #pragma unroll
                for (int q = 0; q < 4; q++) sacc[mi][j][q] = 0.0f;
        #pragma unroll
        for (int kk = 0; kk < 4; kk++) {
            uint32_t bfm[4][4];
            #pragma unroll
            for (int jj = 0; jj < 4; jj++)
                ldsm_x4(sK + (jj * 16 + rB) * AT_STB + (kk * 16 + hB * 8) * 2,
                        bfm[jj]);
            #pragma unroll
            for (int mi = 0; mi < 2; mi++)
                #pragma unroll
                for (int jj = 0; jj < 4; jj++) {
                    mma_bf16(sacc[mi][2 * jj],     qf[mi][kk], bfm[jj][0], bfm[jj][1]);
                    mma_bf16(sacc[mi][2 * jj + 1], qf[mi][kk], bfm[jj][2], bfm[jj][3]);
                }
        }
        #pragma unroll
        for (int mi = 0; mi < 2; mi++)
            #pragma unroll
            for (int j = 0; j < 8; j++) {
                sacc[mi][j][0] = __expf(sacc[mi][j][0]);
                sacc[mi][j][1] = __expf(sacc[mi][j][1]);
                sacc[mi][j][2] = __expf(sacc[mi][j][2]);
                sacc[mi][j][3] = __expf(sacc[mi][j][3]);
                lsum[mi][0] += sacc[mi][j][0] + sacc[mi][j][1];
                lsum[mi][1] += sacc[mi][j][2] + sacc[mi][j][3];
            }
        #pragma unroll
        for (int kk = 0; kk < 4; kk++) {
            uint32_t vf[4][4];
            #pragma unroll
            for (int jj = 0; jj < 4; jj++)
                ldsm_x4t(sV + (kk * 16 + v8 * 8 + tv) * AT_STB
                            + (jj * 16 + v16 * 8) * 2, vf[jj]);
            #pragma unroll
            for (int mi = 0; mi < 2; mi++) {
                uint32_t pa[4];
                pa[0] = bf2pk(sacc[mi][2 * kk][0],     sacc[mi][2 * kk][1]);
                pa[1] = bf2pk(sacc[mi][2 * kk][2],     sacc[mi][2 * kk][3]);
                pa[2] = bf2pk(sacc[mi][2 * kk + 1][0], sacc[mi][2 * kk + 1][1]);
                pa[3] = bf2pk(sacc[mi][2 * kk + 1][2], sacc[mi][2 * kk + 1][3]);
                #pragma unroll
                for (int jj = 0; jj < 4; jj++) {
                    mma_bf16(o[mi][2 * jj],     pa, vf[jj][0], vf[jj][1]);
                    mma_bf16(o[mi][2 * jj + 1], pa, vf[jj][2], vf[jj][3]);
                }
            }
        }
    }

    #pragma unroll
    for (int mi = 0; mi < 2; mi++)
        #pragma unroll
        for (int rr = 0; rr < 2; rr++) {
            lsum[mi][rr] += __shfl_xor_sync(0xffffffffu, lsum[mi][rr], 1);
            lsum[mi][rr] += __shfl_xor_sync(0xffffffffu, lsum[mi][rr], 2);
        }

    #pragma unroll
    for (int mi = 0; mi < 2; mi++) {
        float inv0 = 1.0f / lsum[mi][0];
        float inv1 = 1.0f / lsum[mi][1];
        int r0 = q0 + wid * 32 + mi * 16 + (lid >> 2);
        size_t row0 = ((size_t)b * 1024 + r0) * 768 + h * 64;   // cat stride 768
        size_t row1 = row0 + (size_t)8 * 768;
        #pragma unroll
        for (int j = 0; j < 8; j++) {
            int col = j * 8 + (lid & 3) * 2;
            split_store(Ho, Lo, row0 + col, o[mi][j][0] * inv0, o[mi][j][1] * inv0);
            split_store(Ho, Lo, row1 + col, o[mi][j][2] * inv1, o[mi][j][3] * inv1);
        }
    }
}

// ---------------- kNN gather + leaky_relu + max -> cat[:, 384:] ------------
__global__ void knn_kernel(const float* __restrict__ AbCc,
                           const int* __restrict__ knn,
                           const float* __restrict__ bknn,
                           __nv_bfloat16* __restrict__ Ho,
                           __nv_bfloat16* __restrict__ Lo,
                           int roff) {
    int row = blockIdx.x + roff;
    int b = row >> 10, n = row & 1023;
    __shared__ int idxs[8];
    if (threadIdx.x < 8) idxs[threadIdx.x] = knn[((b << 3) + threadIdx.x) * 1024 + n];
    __syncthreads();
    #pragma unroll
    for (int cc = 0; cc < 3; cc++) {
        int c = threadIdx.x + cc * 128;
        float base = AbCc[(size_t)row * 768 + 384 + c] + bknn[c];
        float mx = -3.0e38f;
        #pragma unroll
        for (int k = 0; k < 8; k++) {
            float v = __ldg(&AbCc[(size_t)idxs[k] * 768 + c]) + base;
            v = (v > 0.0f) ? v : 0.2f * v;
            mx = fmaxf(mx, v);
        }
        size_t oi = (size_t)row * 768 + 384 + c;
        __nv_bfloat16 hb = __float2bfloat16_rn(mx);
        Ho[oi] = hb;
        Lo[oi] = __float2bfloat16_rn(mx - __bfloat162float(hb));
    }
}

// ---------------------------------------------------------------------------
extern "C" void kernel_launch(void* const* d_in, const int* in_sizes, int n_in,
                              void* d_out, int out_size) {
    (void)in_sizes; (void)n_in; (void)out_size;
    const float* x       = (const float*)d_in[0];
    const int*   knn     = (const int*)  d_in[1];
    const float* ln1_w   = (const float*)d_in[2];
    const float* ln1_b   = (const float*)d_in[3];
    const float* w_qkv   = (const float*)d_in[4];
    const float* w_proj  = (const float*)d_in[5];
    const float* b_proj  = (const float*)d_in[6];
    const float* w_knn   = (const float*)d_in[7];
    const float* b_knn   = (const float*)d_in[8];
    const float* w_merge = (const float*)d_in[9];
    const float* b_merge = (const float*)d_in[10];
    const float* ln2_w   = (const float*)d_in[11];
    const float* ln2_b   = (const float*)d_in[12];
    const float* w_fc1   = (const float*)d_in[13];
    const float* b_fc1   = (const float*)d_in[14];
    const float* w_fc2   = (const float*)d_in[15];
    const float* b_fc2   = (const float*)d_in[16];
    float* out = (float*)d_out;

    float *AbCc, *xres, *wpm, *b2;
    cudaGetSymbolAddress((void**)&AbCc, g_AbCc);
    cudaGetSymbolAddress((void**)&xres, g_xres);
    cudaGetSymbolAddress((void**)&wpm,  g_wpm);
    cudaGetSymbolAddress((void**)&b2,   g_b2);

    __nv_bfloat16 *qb,*kb,*vb;
    cudaGetSymbolAddress((void**)&qb, g_qb);
    cudaGetSymbolAddress((void**)&kb, g_kb);
    cudaGetSymbolAddress((void**)&vb, g_vb);

    __nv_bfloat16 *nxh,*nxl,*cath,*catl,*l2h,*l2l,*hh,*hl;
    __nv_bfloat16 *wqh,*wql,*wprh,*wprl,*wkh,*wkl,*wmh,*wml,*wcmbh,*wcmbl;
    __nv_bfloat16 *f1h,*f1l,*f2h,*f2l;
    cudaGetSymbolAddress((void**)&nxh, g_nxh);   cudaGetSymbolAddress((void**)&nxl, g_nxl);
    cudaGetSymbolAddress((void**)&cath,g_cath);  cudaGetSymbolAddress((void**)&catl,g_catl);
    cudaGetSymbolAddress((void**)&l2h, g_l2h);   cudaGetSymbolAddress((void**)&l2l, g_l2l);
    cudaGetSymbolAddress((void**)&hh,  g_hh);    cudaGetSymbolAddress((void**)&hl,  g_hl);
    cudaGetSymbolAddress((void**)&wqh, g_wqkvh); cudaGetSymbolAddress((void**)&wql, g_wqkvl);
    cudaGetSymbolAddress((void**)&wprh,g_wprh);  cudaGetSymbolAddress((void**)&wprl,g_wprl);
    cudaGetSymbolAddress((void**)&wkh, g_wkh);   cudaGetSymbolAddress((void**)&wkl, g_wkl);
    cudaGetSymbolAddress((void**)&wmh, g_wmh);   cudaGetSymbolAddress((void**)&wml, g_wml);
    cudaGetSymbolAddress((void**)&wcmbh,g_wcmbh);cudaGetSymbolAddress((void**)&wcmbl,g_wcmbl);
    cudaGetSymbolAddress((void**)&f1h, g_f1h);   cudaGetSymbolAddress((void**)&f1l, g_f1l);
    cudaGetSymbolAddress((void**)&f2h, g_f2h);   cudaGetSymbolAddress((void**)&f2l, g_f2l);

    cudaFuncSetAttribute(tgemm<0,0,1>, cudaFuncAttributeMaxDynamicSharedMemorySize, SMEM_MM4);
    cudaFuncSetAttribute(tgemm<1,1,1>, cudaFuncAttributeMaxDynamicSharedMemorySize, SMEM_MM4);
    cudaFuncSetAttribute(tgemm<0,2,0>, cudaFuncAttributeMaxDynamicSharedMemorySize, SMEM_MM2);
    cudaFuncSetAttribute(attn_mma,     cudaFuncAttributeMaxDynamicSharedMemorySize, SMEM_AT);

    static cudaStream_t sB = nullptr, sC = nullptr, sD = nullptr;
    static cudaEvent_t evFork, evQW, evLn, evKW, evQA, evWpm,
                       evKnnA, evKnnB, evW2, evOutA;
    if (!sB) {
        cudaStreamCreateWithFlags(&sB, cudaStreamNonBlocking);
        cudaStreamCreateWithFlags(&sC, cudaStreamNonBlocking);
        cudaStreamCreateWithFlags(&sD, cudaStreamNonBlocking);
        cudaEventCreateWithFlags(&evFork, cudaEventDisableTiming);
        cudaEventCreateWithFlags(&evQW,   cudaEventDisableTiming);
        cudaEventCreateWithFlags(&evLn,   cudaEventDisableTiming);
        cudaEventCreateWithFlags(&evKW,   cudaEventDisableTiming);
        cudaEventCreateWithFlags(&evQA,   cudaEventDisableTiming);
        cudaEventCreateWithFlags(&evWpm,  cudaEventDisableTiming);
        cudaEventCreateWithFlags(&evKnnA, cudaEventDisableTiming);
        cudaEventCreateWithFlags(&evKnnB, cudaEventDisableTiming);
        cudaEventCreateWithFlags(&evW2,   cudaEventDisableTiming);
        cudaEventCreateWithFlags(&evOutA, cudaEventDisableTiming);
    }

    const size_t HM = 8192;   // rows per half (batches 0-7 | 8-15)

    cudaEventRecord(evFork, 0);
    cudaStreamWaitEvent(sB, evFork, 0);
    cudaStreamWaitEvent(sC, evFork, 0);
    cudaStreamWaitEvent(sD, evFork, 0);

    // sC: qkv weight split (overlaps LN1)
    tsplit<<<1728, 256, 0, sC>>>(w_qkv, wqh, wql, 384, 1152);
    cudaEventRecord(evQW, sC);
    // main: LN1
    ln_kernel<<<MROWS, 128>>>(x, ln1_w, ln1_b, nxh, nxl);
    cudaEventRecord(evLn, 0);
    // sB: kNN weights + wcmb right half (Wm2)
    tsplit_knn2<<<1152, 256, 0, sB>>>(w_knn, wkh, wkl);
    tsplit_cmb<<<576, 256, 0, sB>>>(w_merge, wcmbh, wcmbl);
    cudaEventRecord(evKW, sB);
    // sD: fc weight splits (off the attn critical path)
    tsplit<<<2304, 256, 0, sD>>>(w_fc1, f1h, f1l, 384, 768);
    tsplit<<<2304, 256, 0, sD>>>(w_fc2, f2h, f2l, 768, 384);
    cudaEventRecord(evW2, sD);

    // main: qkvA, qkvB (3-stage nosplit; ldc = token offset), then attnB
    cudaStreamWaitEvent(0, evQW, 0);
    tgemm<0,2,0><<<dim3(9, 64), 256, SMEM_MM2>>>(nxh, nullptr, wqh, nullptr,
        nullptr, nullptr, nullptr, nullptr, nullptr, qb, kb, vb,
        384, 384, 384, 0, 0);
    cudaEventRecord(evQA, 0);
    tgemm<0,2,0><<<dim3(9, 64), 256, SMEM_MM2>>>(nxh + HM * 384, nullptr,
        wqh, nullptr, nullptr, nullptr, nullptr, nullptr, nullptr, qb, kb, vb,
        384, 384, 384, 8192, 0);
    attn_mma<<<dim3(8, 48), 128, SMEM_AT>>>(qb, kb, vb, cath, catl, 48);

    // sC: Wpm chain + bias2 -> wcmb left half; then attnA
    tsplit<<<1152, 256, 0, sC>>>(w_merge, wmh, wml, 768, 384);
    fsplit<<<576, 256, 0, sC>>>(w_proj, wprh, wprl, 384 * 384);
    tgemm<0,0,1><<<dim3(3, 3), 256, SMEM_MM4, sC>>>(wmh, wml, wprh, wprl,
        nullptr, nullptr, wpm, nullptr, nullptr, nullptr, nullptr, nullptr,
        384, 768, 384, 384, 0);
    fsplit_cmb<<<576, 256, 0, sC>>>(wpm, wcmbh, wcmbl);
    bias2_kernel<<<3, 128, 0, sC>>>(b_proj, w_merge, b_merge, b2);
    cudaEventRecord(evWpm, sC);
    cudaStreamWaitEvent(sC, evQA, 0);
    attn_mma<<<dim3(8, 48), 128, SMEM_AT, sC>>>(qb, kb, vb, cath, catl, 0);

    // sB: kNN half A -> cat right rows [0, 8192)
    cudaStreamWaitEvent(sB, evLn, 0);
    tgemm<0,0,1><<<dim3(6, 64), 256, SMEM_MM4, sB>>>(nxh, nxl, wkh, wkl,
        nullptr, nullptr, AbCc, nullptr, nullptr, nullptr, nullptr, nullptr,
        384, 384, 384, 768, 0);
    knn_kernel<<<8192, 128, 0, sB>>>(AbCc, knn, b_knn, cath, catl, 0);
    cudaEventRecord(evKnnA, sB);

    // sD: kNN half B -> cat right rows [8192, 16384)
    cudaStreamWaitEvent(sD, evKW, 0);
    cudaStreamWaitEvent(sD, evLn, 0);
    tgemm<0,0,1><<<dim3(6, 64), 256, SMEM_MM4, sD>>>(nxh + HM * 384, nxl + HM * 384,
        wkh, wkl, nullptr, nullptr, AbCc + HM * 768, nullptr, nullptr,
        nullptr, nullptr, nullptr, 384, 384, 384, 768, 0);
    knn_kernel<<<8192, 128, 0, sD>>>(AbCc, knn, b_knn, cath, catl, 8192);
    cudaEventRecord(evKnnB, sD);

    // sC: A-half cat-GEMM -> xres; ln2; fc1; fc2 -> out rows [0, 8192)
    cudaStreamWaitEvent(sC, evKnnA, 0);
    cudaStreamWaitEvent(sC, evKW, 0);
    tgemm<0,0,1><<<dim3(3, 64), 256, SMEM_MM4, sC>>>(cath, catl, wcmbh, wcmbl,
        b2, x, xres, nullptr, nullptr, nullptr, nullptr, nullptr,
        768, 768, 768, 384, 384);
    ln_kernel<<<8192, 128, 0, sC>>>(xres, ln2_w, ln2_b, l2h, l2l);
    cudaStreamWaitEvent(sC, evW2, 0);
    tgemm<1,1,1><<<dim3(6, 64), 256, SMEM_MM4, sC>>>(l2h, l2l, f1h, f1l,
        b_fc1, nullptr, nullptr, hh, hl, nullptr, nullptr, nullptr,
        384, 384, 384, 768, 0);
    tgemm<0,0,1><<<dim3(3, 64), 256, SMEM_MM4, sC>>>(hh, hl, f2h, f2l,
        b_fc2, xres, out, nullptr, nullptr, nullptr, nullptr, nullptr,
        768, 768, 768, 384, 384);
    cudaEventRecord(evOutA, sC);

    // main: B-half cat-GEMM -> xres; ln2; fc1; fc2 -> out rows [8192, 16384)
    cudaStreamWaitEvent(0, evKnnB, 0);
    cudaStreamWaitEvent(0, evWpm, 0);
    cudaStreamWaitEvent(0, evKW, 0);
    tgemm<0,0,1><<<dim3(3, 64), 256, SMEM_MM4>>>(cath + HM * 768, catl + HM * 768,
        wcmbh, wcmbl, b2, x + HM * 384, xres + HM * 384, nullptr, nullptr,
        nullptr, nullptr, nullptr, 768, 768, 768, 384, 384);
    ln_kernel<<<8192, 128>>>(xres + HM * 384, ln2_w, ln2_b,
                             l2h + HM * 384, l2l + HM * 384);
    cudaStreamWaitEvent(0, evW2, 0);
    tgemm<1,1,1><<<dim3(6, 64), 256, SMEM_MM4>>>(l2h + HM * 384, l2l + HM * 384,
        f1h, f1l, b_fc1, nullptr, nullptr, hh + HM * 768, hl + HM * 768,
        nullptr, nullptr, nullptr, 384, 384, 384, 768, 0);
    tgemm<0,0,1><<<dim3(3, 64), 256, SMEM_MM4>>>(hh + HM * 768, hl + HM * 768,
        f2h, f2l, b_fc2, xres + HM * 384, out + HM * 384,
        nullptr, nullptr, nullptr, nullptr, nullptr, 768, 768, 768, 384, 384);
    cudaStreamWaitEvent(0, evOutA, 0);
}